// round 10
// baseline (speedup 1.0000x reference)
#include <cuda_runtime.h>
#include <cuda_bf16.h>
#include <math.h>
#include <stdint.h>

#define BB  32
#define NSQ 1024
#define NCQ 1024
#define DD  256
#define DP1 257
#define DPAD 272
#define KKW 128
#define KP1 129
#define DH  129   // Hermitian-reduced column count

// ----------------------------- scratch (static device globals; no runtime alloc) ---
static __device__ float2 g_c1 [(size_t)2*BB*NSQ*DH];
static __device__ float2 g_c1T[(size_t)2*BB*DH*NSQ];
static __device__ float  g_sT [(size_t)2*BB*DH*NSQ];
static __device__ float  g_real[(size_t)2*BB*NSQ*DH];
static __device__ float  g_Ls [(size_t)BB*NSQ*DPAD];
static __device__ float  g_Lc [(size_t)BB*NCQ*DPAD];
static __device__ float  g_Llin[(size_t)BB*NCQ*DPAD];
static __device__ float  g_Yt [(size_t)BB*NSQ*KKW];
static __device__ float  g_Wt [(size_t)896*DPAD];     // Wl@0, Ws@384*DPAD, Wc@640*DPAD
static __device__ __align__(16) __nv_bfloat16 g_Lsh [(size_t)BB*NSQ*DPAD];
static __device__ __align__(16) __nv_bfloat16 g_Llh [(size_t)BB*NCQ*DPAD];
static __device__ __align__(16) __nv_bfloat16 g_Lbh [(size_t)BB*NSQ*NCQ];
static __device__ __align__(16) __nv_bfloat16 g_LbTh[(size_t)BB*NCQ*NSQ];
static __device__ __align__(16) __nv_bfloat16 g_HcaTh[(size_t)BB*KKW*NCQ];
static __device__ __align__(16) __nv_bfloat16 g_HsahT[(size_t)BB*KKW*NSQ];
static __device__ float  g_rss[BB*NSQ];
static __device__ float  g_css[BB*NCQ];
static __device__ float  g_amx[BB*NCQ];
static __device__ float  g_ass[BB*NCQ];
static __device__ float  g_xnr[BB*NSQ];
static __device__ float  g_xnc[BB*NCQ];
static __device__ float  g_msc[BB*NCQ];
static __device__ float  g_Hsa[(size_t)BB*NSQ*KKW];
static __device__ float  g_Hca[(size_t)BB*NCQ*KKW];
static __device__ float  g_HcaT[(size_t)BB*KKW*NCQ];
static __device__ float  g_Mxs[(size_t)BB*NSQ*KKW];
static __device__ float  g_MxcT[(size_t)BB*KKW*NCQ];
static __device__ float  g_lgs[BB*NSQ];
static __device__ float  g_lgc[BB*NCQ];
static __device__ float  g_cs [BB*DP1];
static __device__ float  g_cc [BB*DP1];
static __device__ float  g_part[BB*8*DP1];
static __device__ float2 g_tw1024[1024];
static __device__ float2 g_tw256[256];

// ----------------------------- helpers ---------------------------------------------
__device__ __forceinline__ float atanhc(float x){
    x = fminf(fmaxf(x, -1.f + 1e-5f), 1.f - 1e-5f);
    return 0.5f * (log1pf(x) - log1pf(-x));
}
__device__ __forceinline__ float gelu_exact(float v){
    return 0.5f * v * (1.f + erff(v * 0.70710678118654752f));
}
__device__ __forceinline__ float2 cmul(float2 a, float2 b){
    return make_float2(a.x*b.x - a.y*b.y, a.x*b.y + a.y*b.x);
}
__device__ __forceinline__ float2 cadd(float2 a, float2 b){ return make_float2(a.x+b.x, a.y+b.y); }
__device__ __forceinline__ float2 csub(float2 a, float2 b){ return make_float2(a.x-b.x, a.y-b.y); }

__device__ __forceinline__ float wsum(float v){
    #pragma unroll
    for (int o = 16; o; o >>= 1) v += __shfl_xor_sync(0xffffffffu, v, o);
    return v;
}
__device__ __forceinline__ float blockReduceSum(float v){
    __shared__ float sh[32];
    #pragma unroll
    for (int o = 16; o; o >>= 1) v += __shfl_down_sync(0xffffffffu, v, o);
    int lane = threadIdx.x & 31, w = threadIdx.x >> 5;
    if (lane == 0) sh[w] = v;
    __syncthreads();
    int nw = (blockDim.x + 31) >> 5;
    v = (threadIdx.x < (unsigned)nw) ? sh[threadIdx.x] : 0.f;
    if (w == 0){
        #pragma unroll
        for (int o = 16; o; o >>= 1) v += __shfl_down_sync(0xffffffffu, v, o);
        if (lane == 0) sh[0] = v;
    }
    __syncthreads();
    float r = sh[0];
    __syncthreads();
    return r;
}
__device__ __forceinline__ void blockReduceSum3(float& a, float& b, float& c){
    __shared__ float sh3[32][3];
    #pragma unroll
    for (int o = 16; o; o >>= 1){
        a += __shfl_down_sync(0xffffffffu, a, o);
        b += __shfl_down_sync(0xffffffffu, b, o);
        c += __shfl_down_sync(0xffffffffu, c, o);
    }
    int lane = threadIdx.x & 31, w = threadIdx.x >> 5;
    if (lane == 0){ sh3[w][0] = a; sh3[w][1] = b; sh3[w][2] = c; }
    __syncthreads();
    int nw = (blockDim.x + 31) >> 5;
    a = (threadIdx.x < (unsigned)nw) ? sh3[threadIdx.x][0] : 0.f;
    b = (threadIdx.x < (unsigned)nw) ? sh3[threadIdx.x][1] : 0.f;
    c = (threadIdx.x < (unsigned)nw) ? sh3[threadIdx.x][2] : 0.f;
    if (w == 0){
        #pragma unroll
        for (int o = 16; o; o >>= 1){
            a += __shfl_down_sync(0xffffffffu, a, o);
            b += __shfl_down_sync(0xffffffffu, b, o);
            c += __shfl_down_sync(0xffffffffu, c, o);
        }
        if (lane == 0){ sh3[0][0] = a; sh3[0][1] = b; sh3[0][2] = c; }
    }
    __syncthreads();
    a = sh3[0][0]; b = sh3[0][1]; c = sh3[0][2];
    __syncthreads();
}
__device__ __forceinline__ float blockReduceMax(float v){
    __shared__ float sh[32];
    #pragma unroll
    for (int o = 16; o; o >>= 1) v = fmaxf(v, __shfl_down_sync(0xffffffffu, v, o));
    int lane = threadIdx.x & 31, w = threadIdx.x >> 5;
    if (lane == 0) sh[w] = v;
    __syncthreads();
    int nw = (blockDim.x + 31) >> 5;
    v = (threadIdx.x < (unsigned)nw) ? sh[threadIdx.x] : -3.4e38f;
    if (w == 0){
        #pragma unroll
        for (int o = 16; o; o >>= 1) v = fmaxf(v, __shfl_down_sync(0xffffffffu, v, o));
        if (lane == 0) sh[0] = v;
    }
    __syncthreads();
    float r = sh[0];
    __syncthreads();
    return r;
}
__device__ __forceinline__ uint32_t f2tf32(float v){
    uint32_t r;
    asm("cvt.rna.tf32.f32 %0, %1;" : "=r"(r) : "f"(v));
    return r;
}
__device__ __forceinline__ float tf32r(float v){ return __uint_as_float(f2tf32(v)); }
__device__ __forceinline__ void mma_tf32(float* c, const uint32_t* a, const uint32_t* b){
    asm volatile("mma.sync.aligned.m16n8k8.row.col.f32.tf32.tf32.f32 "
        "{%0,%1,%2,%3}, {%4,%5,%6,%7}, {%8,%9}, {%0,%1,%2,%3};"
        : "+f"(c[0]), "+f"(c[1]), "+f"(c[2]), "+f"(c[3])
        : "r"(a[0]), "r"(a[1]), "r"(a[2]), "r"(a[3]), "r"(b[0]), "r"(b[1]));
}
__device__ __forceinline__ void mma_bf16(float* c, const uint32_t* a, const uint32_t* b){
    asm volatile("mma.sync.aligned.m16n8k16.row.col.f32.bf16.bf16.f32 "
        "{%0,%1,%2,%3}, {%4,%5,%6,%7}, {%8,%9}, {%0,%1,%2,%3};"
        : "+f"(c[0]), "+f"(c[1]), "+f"(c[2]), "+f"(c[3])
        : "r"(a[0]), "r"(a[1]), "r"(a[2]), "r"(a[3]), "r"(b[0]), "r"(b[1]));
}
__device__ __forceinline__ void cpa16(uint32_t dsh, const void* src){
    asm volatile("cp.async.ca.shared.global [%0], [%1], 16;" :: "r"(dsh), "l"(src));
}
#define CP_COMMIT() asm volatile("cp.async.commit_group;" ::: "memory")
#define CP_WAIT1()  asm volatile("cp.async.wait_group 1;" ::: "memory")
#define CP_WAIT0()  asm volatile("cp.async.wait_group 0;" ::: "memory")

// ----------------------------- merged setup kernel ---------------------------------
__global__ void k_setup(const float* __restrict__ Wl, const float* __restrict__ Ws,
                        const float* __restrict__ Wc, float* __restrict__ Wt,
                        float* __restrict__ a, float* __restrict__ b,
                        float* __restrict__ c, float* __restrict__ d){
    int blk = blockIdx.x;
    int t = threadIdx.x;                       // 1024
    if (blk < 32){
        int i = blk*1024 + t;
        a[i] = 0.f; b[i] = 0.f; c[i] = 0.f; d[i] = 0.f;
        if (blk == 0){
            double ang = -6.283185307179586476925287 * (double)t / 1024.0;
            g_tw1024[t] = make_float2((float)cos(ang), (float)sin(ang));
            if (t < 256){
                double a2 = -6.283185307179586476925287 * (double)t / 256.0;
                g_tw256[t] = make_float2((float)cos(a2), (float)sin(a2));
            }
        }
        return;
    }
    int r = blk - 32;                          // 0..514
    if (t >= DP1) return;
    const float* src; float* dst;
    if (r < DP1){ src = Wl + (size_t)r*DP1; dst = Wt + (size_t)r*DPAD; }
    else if (r < DP1 + KP1){ int rr = r - DP1; src = Ws + (size_t)rr*DP1; dst = Wt + (size_t)(384+rr)*DPAD; }
    else { int rr = r - DP1 - KP1; src = Wc + (size_t)rr*DP1; dst = Wt + (size_t)(640+rr)*DPAD; }
    dst[t] = tf32r(src[t]);
}

// ----------------------------- radix-4 Stockham FFT kernels ------------------------
__global__ void k_fft256(const float* __restrict__ sent, const float* __restrict__ comm,
                         float2* __restrict__ out){
    __shared__ float2 bufA[4][256];
    __shared__ float2 bufB[4][256];
    __shared__ float2 tws[256];
    __shared__ float  rsum[4][2];
    int tx = threadIdx.x;                      // 64
    int ty = threadIdx.y;                      // 4
    int tid = ty*64 + tx;
    size_t row = (size_t)blockIdx.x*4 + ty;
    bool do_log = row >= (size_t)BB*NSQ;
    const float* x = do_log ? (comm + (row - (size_t)BB*NSQ)*256) : (sent + row*256);
    tws[tid] = g_tw256[tid];

    float v0 = x[tx], v1 = x[tx+64], v2 = x[tx+128], v3 = x[tx+192];
    float ss = v0*v0 + v1*v1 + v2*v2 + v3*v3;
    #pragma unroll
    for (int o = 16; o; o >>= 1) ss += __shfl_down_sync(0xffffffffu, ss, o);
    if ((tx & 31) == 0) rsum[ty][tx >> 5] = ss;
    __syncthreads();
    if (do_log){
        float tot = rsum[ty][0] + rsum[ty][1];
        float yn = sqrtf(fmaxf(tot, 1e-15f));
        float f = atanhc(yn) / yn;
        v0 *= f; v1 *= f; v2 *= f; v3 *= f;
    }
    {
        float pa = v0 + v2, pb = v0 - v2;
        float pc = v1 + v3, pd = v1 - v3;
        bufA[ty][4*tx]     = make_float2(pa + pc, 0.f);
        bufA[ty][4*tx + 1] = make_float2(pb, -pd);
        bufA[ty][4*tx + 2] = make_float2(pa - pc, 0.f);
        bufA[ty][4*tx + 3] = make_float2(pb,  pd);
    }
    __syncthreads();

    float2* X = &bufA[ty][0];
    float2* Y = &bufB[ty][0];
    #pragma unroll
    for (int s = 1; s < 4; s++){
        int Ns = 1 << (2*s);
        int p = tx & (Ns - 1);
        float2 w1 = tws[p * (64/Ns)];
        float2 w2 = cmul(w1, w1);
        float2 w3 = cmul(w2, w1);
        float2 a0 = X[tx];
        float2 a1 = cmul(X[tx + 64],  w1);
        float2 a2 = cmul(X[tx + 128], w2);
        float2 a3 = cmul(X[tx + 192], w3);
        float2 pa = cadd(a0, a2), pb = csub(a0, a2);
        float2 pc = cadd(a1, a3), pd = csub(a1, a3);
        float2 dneg = make_float2(pd.y, -pd.x);
        float2 dpos = make_float2(-pd.y, pd.x);
        int idxD = ((tx >> (2*s)) << (2*s + 2)) + p;
        Y[idxD]          = cadd(pa, pc);
        Y[idxD + Ns]     = cadd(pb, dneg);
        Y[idxD + 2*Ns]   = csub(pa, pc);
        Y[idxD + 3*Ns]   = cadd(pb, dpos);
        __syncthreads();
        float2* tmp = X; X = Y; Y = tmp;
    }
    out[row*DH + tx]      = X[tx];
    out[row*DH + tx + 64] = X[tx + 64];
    if (tx == 0) out[row*DH + 128] = X[128];
}

__global__ void k_fft1024(const float2* __restrict__ in, float* __restrict__ outr){
    __shared__ float2 bufA[1024];
    __shared__ float2 bufB[1024];
    __shared__ float2 tws[1024];
    int t = threadIdx.x;                       // 256
    size_t row = blockIdx.x;
    const float2* src = in + row*1024;
    float2 a0 = src[t], a1 = src[t+256], a2 = src[t+512], a3 = src[t+768];
    #pragma unroll
    for (int i = 0; i < 4; i++)
        tws[t + i*256] = g_tw1024[t + i*256];
    {
        float2 pa = cadd(a0, a2), pb = csub(a0, a2);
        float2 pc = cadd(a1, a3), pd = csub(a1, a3);
        bufA[4*t]     = cadd(pa, pc);
        bufA[4*t + 1] = cadd(pb, make_float2(pd.y, -pd.x));
        bufA[4*t + 2] = csub(pa, pc);
        bufA[4*t + 3] = cadd(pb, make_float2(-pd.y, pd.x));
    }
    __syncthreads();
    float2* X = bufA;
    float2* Y = bufB;
    #pragma unroll
    for (int s = 1; s < 5; s++){
        int Ns = 1 << (2*s);
        int p = t & (Ns - 1);
        float2 w1 = tws[p * (256/Ns)];
        float2 w2 = cmul(w1, w1);
        float2 w3 = cmul(w2, w1);
        float2 b0 = X[t];
        float2 b1 = cmul(X[t + 256], w1);
        float2 b2 = cmul(X[t + 512], w2);
        float2 b3 = cmul(X[t + 768], w3);
        float2 pa = cadd(b0, b2), pb = csub(b0, b2);
        float2 pc = cadd(b1, b3), pd = csub(b1, b3);
        float2 dneg = make_float2(pd.y, -pd.x);
        float2 dpos = make_float2(-pd.y, pd.x);
        int idxD = ((t >> (2*s)) << (2*s + 2)) + p;
        Y[idxD]        = cadd(pa, pc);
        Y[idxD + Ns]   = cadd(pb, dneg);
        Y[idxD + 2*Ns] = csub(pa, pc);
        Y[idxD + 3*Ns] = cadd(pb, dpos);
        __syncthreads();
        float2* tmp = X; X = Y; Y = tmp;
    }
    #pragma unroll
    for (int i = 0; i < 4; i++)
        outr[row*1024 + t + i*256] = X[t + i*256].x;
}

__global__ void k_transpose_ch(const float2* __restrict__ in, float2* __restrict__ out){
    __shared__ float2 tile[32][33];
    int b = blockIdx.z;
    int c0 = blockIdx.x*32, r0 = blockIdx.y*32;
    const float2* src = in + (size_t)b*NSQ*DH;
    for (int i = threadIdx.y; i < 32; i += 8){
        int d = c0 + threadIdx.x;
        tile[i][threadIdx.x] = (d < DH) ? src[(size_t)(r0+i)*DH + d]
                                        : make_float2(0.f, 0.f);
    }
    __syncthreads();
    float2* dst = out + (size_t)b*DH*NSQ;
    for (int i = threadIdx.y; i < 32; i += 8){
        int d = c0 + i;
        if (d < DH) dst[(size_t)d*NSQ + r0 + threadIdx.x] = tile[threadIdx.x][i];
    }
}
__global__ void k_transpose_fh(const float* __restrict__ in, float* __restrict__ out){
    __shared__ float tile[32][33];
    int b = blockIdx.z;
    int d0 = blockIdx.x*32, n0 = blockIdx.y*32;
    const float* src = in + (size_t)b*DH*NSQ;
    for (int i = threadIdx.y; i < 32; i += 8){
        int d = d0 + i;
        tile[i][threadIdx.x] = (d < DH) ? src[(size_t)d*NSQ + n0 + threadIdx.x] : 0.f;
    }
    __syncthreads();
    float* dst = out + (size_t)b*NSQ*DH;
    int d = d0 + threadIdx.x;
    if (d < DH)
        for (int i = threadIdx.y; i < 32; i += 8)
            dst[(size_t)(n0+i)*DH + d] = tile[threadIdx.x][i];
}

// fused Hermitian mirror + euclid_to_lorentz; fp32 tf32-rounded + bf16 (sentence only)
__global__ void k_e2l(const float* __restrict__ rl, float* __restrict__ Ls,
                      float* __restrict__ Lc, __nv_bfloat16* __restrict__ Lsh){
    size_t row = blockIdx.x;                   // 0 .. 2*BB*NSQ-1
    int t = threadIdx.x;                       // 256
    size_t bb = row >> 10;
    int n = (int)(row & 1023);
    float v;
    if (t < DH){
        v = rl[(bb*NSQ + n)*DH + t];
    } else {
        int srcn = (1024 - n) & 1023;
        v = rl[(bb*NSQ + srcn)*DH + (256 - t)];
    }
    float ss = blockReduceSum(v*v);
    float xn = sqrtf(fmaxf(ss, 1e-15f)) + 1e-5f;
    float scl = fminf(1.f, 2.0f / xn);
    v *= scl;
    float vn = sqrtf(fmaxf(ss*scl*scl, 1e-15f));
    float f = sinhf(vn) / vn;
    float* out = (bb < BB) ? Ls : Lc;
    size_t orow = (bb < BB) ? row : row - (size_t)BB*NSQ;
    float tv = coshf(vn), sv = f * v;
    if (t == 0) out[orow*DPAD] = tf32r(tv);
    out[orow*DPAD + 1 + t] = tf32r(sv);
    if (t < DPAD - DP1) out[orow*DPAD + DP1 + t] = 0.f;
    if (bb < BB){
        if (t == 0) Lsh[orow*DPAD] = __float2bfloat16_rn(tv);
        Lsh[orow*DPAD + 1 + t] = __float2bfloat16_rn(sv);
    }
}

// --------- pipelined tensor-core GEMM (pre-rounded TF32; used for linear layers) ---
template<int ATRANS, int BTRANS, int MODE, int ROUND>
__global__ void k_pgemm(const float* __restrict__ A, const float* __restrict__ Bm,
                        const float* __restrict__ bias, float* __restrict__ C,
                        int M, int N, int Klen, int lda, int ldb, int ldc,
                        long sA, long sB, long sC,
                        float* __restrict__ rss, float* __restrict__ css)
{
    constexpr int A_ELE = (ATRANS == 0) ? 128*20 : 16*132;
    constexpr int B_ELE = (BTRANS == 1) ? 128*20 : 16*132;
    __shared__ __align__(16) float As[2][A_ELE];
    __shared__ __align__(16) float Bs[2][B_ELE];

    int bz = blockIdx.z;
    A  += (size_t)bz * sA;
    Bm += (size_t)bz * sB;
    C  += (size_t)bz * sC;
    int bm = blockIdx.y * 128, bn = blockIdx.x * 128;
    int tid = threadIdx.x;
    int wid = tid >> 5, lane = tid & 31;
    int wm = (wid >> 2) * 64;
    int wn = (wid & 3) * 32;
    int g = lane >> 2, tg = lane & 3;

    int KT = (Klen + 15) >> 4;

    uint32_t asBase = (uint32_t)__cvta_generic_to_shared(&As[0][0]);
    uint32_t bsBase = (uint32_t)__cvta_generic_to_shared(&Bs[0][0]);

    auto issueA = [&](int st, int k0){
        uint32_t base = asBase + (uint32_t)(st * A_ELE * 4);
        if (ATRANS == 0){
            #pragma unroll
            for (int i = 0; i < 2; i++){
                int idx = tid + i*256;
                int mm = idx >> 2, k4 = idx & 3;
                cpa16(base + (mm*20 + k4*4)*4, A + (size_t)(bm+mm)*lda + k0 + k4*4);
            }
        } else {
            #pragma unroll
            for (int i = 0; i < 2; i++){
                int idx = tid + i*256;
                int kk = idx >> 5, m4 = idx & 31;
                cpa16(base + (kk*132 + m4*4)*4, A + (size_t)(k0+kk)*lda + bm + m4*4);
            }
        }
    };
    auto issueB = [&](int st, int k0){
        uint32_t base = bsBase + (uint32_t)(st * B_ELE * 4);
        if (BTRANS == 1){
            #pragma unroll
            for (int i = 0; i < 2; i++){
                int idx = tid + i*256;
                int nn = idx >> 2, k4 = idx & 3;
                cpa16(base + (nn*20 + k4*4)*4, Bm + (size_t)(bn+nn)*ldb + k0 + k4*4);
            }
        } else {
            #pragma unroll
            for (int i = 0; i < 2; i++){
                int idx = tid + i*256;
                int kk = idx >> 5, n4 = idx & 31;
                cpa16(base + (kk*132 + n4*4)*4, Bm + (size_t)(k0+kk)*ldb + bn + n4*4);
            }
        }
    };
    auto A_at = [&](int st, int m, int k)->uint32_t{
        const uint32_t* p = reinterpret_cast<const uint32_t*>(&As[st][0]);
        return (ATRANS == 0) ? p[m*20 + k] : p[k*132 + m];
    };
    auto B_at = [&](int st, int n, int k)->uint32_t{
        const uint32_t* p = reinterpret_cast<const uint32_t*>(&Bs[st][0]);
        return (BTRANS == 1) ? p[n*20 + k] : p[k*132 + n];
    };

    float acc[4][4][4];
    #pragma unroll
    for (int mi = 0; mi < 4; mi++)
        #pragma unroll
        for (int ni = 0; ni < 4; ni++)
            #pragma unroll
            for (int r = 0; r < 4; r++) acc[mi][ni][r] = 0.f;

    issueA(0, 0); issueB(0, 0);
    CP_COMMIT();

    for (int kt = 0; kt < KT; kt++){
        int st = kt & 1;
        if (kt + 1 < KT){
            issueA(st ^ 1, (kt+1)*16);
            issueB(st ^ 1, (kt+1)*16);
            CP_COMMIT();
            CP_WAIT1();
        } else {
            CP_WAIT0();
        }
        __syncthreads();

        #pragma unroll
        for (int ks = 0; ks < 2; ks++){
            int kk = ks*8;
            uint32_t bhf[4][2];
            #pragma unroll
            for (int ni = 0; ni < 4; ni++){
                int n = wn + ni*8 + g;
                bhf[ni][0] = B_at(st, n, kk+tg);
                bhf[ni][1] = B_at(st, n, kk+tg+4);
            }
            #pragma unroll
            for (int mi = 0; mi < 4; mi++){
                int m = wm + mi*16;
                uint32_t ahf[4];
                ahf[0] = A_at(st, m+g,   kk+tg);
                ahf[1] = A_at(st, m+g+8, kk+tg);
                ahf[2] = A_at(st, m+g,   kk+tg+4);
                ahf[3] = A_at(st, m+g+8, kk+tg+4);
                #pragma unroll
                for (int ni = 0; ni < 4; ni++)
                    mma_tf32(acc[mi][ni], ahf, bhf[ni]);
            }
        }
        __syncthreads();
    }

    #pragma unroll
    for (int mi = 0; mi < 4; mi++)
        #pragma unroll
        for (int ni = 0; ni < 4; ni++){
            int col = bn + wn + ni*8 + 2*tg;
            #pragma unroll
            for (int r = 0; r < 4; r++){
                int gm = bm + wm + mi*16 + g + (r >= 2 ? 8 : 0);
                int gn = col + (r & 1);
                if (gn >= N) continue;
                float v = acc[mi][ni][r];
                if (MODE == 1) v += bias[gn];
                if (ROUND) v = tf32r(v);
                C[(size_t)gm*ldc + gn] = v;
            }
        }
}

// --------- bf16 GEMM (m16n8k16): A[m][k], B[n][k]; MODE 0 fp32 C, MODE 2 einsum ----
template<int MODE>
__global__ void k_bgemm(const __nv_bfloat16* __restrict__ A,
                        const __nv_bfloat16* __restrict__ Bm,
                        float* __restrict__ C,
                        __nv_bfloat16* __restrict__ Cb, __nv_bfloat16* __restrict__ CbT,
                        int M, int N, int Klen, int lda, int ldb, int ldc, int ldt,
                        long sA, long sB, long sC, long sCb,
                        float* __restrict__ rss, float* __restrict__ css)
{
    __shared__ __align__(16) __nv_bfloat16 As[2][128*24];
    __shared__ __align__(16) __nv_bfloat16 Bs[2][128*24];

    int bz = blockIdx.z;
    A  += (size_t)bz * sA;
    Bm += (size_t)bz * sB;
    if (MODE == 0) C += (size_t)bz * sC;
    else { Cb += (size_t)bz * sCb; CbT += (size_t)bz * sCb; }
    int bm = blockIdx.y * 128, bn = blockIdx.x * 128;
    int tid = threadIdx.x;
    int wid = tid >> 5, lane = tid & 31;
    int wm = (wid >> 2) * 64;
    int wn = (wid & 3) * 32;
    int g = lane >> 2, tg = lane & 3;
    int KT = (Klen + 15) >> 4;

    uint32_t asBase = (uint32_t)__cvta_generic_to_shared(&As[0][0]);
    uint32_t bsBase = (uint32_t)__cvta_generic_to_shared(&Bs[0][0]);

    auto issueA = [&](int st, int k0){
        int mm = tid >> 1, c = tid & 1;
        cpa16(asBase + (uint32_t)(st*6144) + (mm*24 + c*8)*2,
              A + (size_t)(bm+mm)*lda + k0 + c*8);
    };
    auto issueB = [&](int st, int k0){
        int nn = tid >> 1, c = tid & 1;
        cpa16(bsBase + (uint32_t)(st*6144) + (nn*24 + c*8)*2,
              Bm + (size_t)(bn+nn)*ldb + k0 + c*8);
    };

    float acc[4][4][4];
    #pragma unroll
    for (int mi = 0; mi < 4; mi++)
        #pragma unroll
        for (int ni = 0; ni < 4; ni++)
            #pragma unroll
            for (int r = 0; r < 4; r++) acc[mi][ni][r] = 0.f;

    issueA(0, 0); issueB(0, 0);
    CP_COMMIT();

    for (int kt = 0; kt < KT; kt++){
        int st = kt & 1;
        if (kt + 1 < KT){
            issueA(st ^ 1, (kt+1)*16);
            issueB(st ^ 1, (kt+1)*16);
            CP_COMMIT();
            CP_WAIT1();
        } else {
            CP_WAIT0();
        }
        __syncthreads();

        const uint32_t* pA = reinterpret_cast<const uint32_t*>(&As[st][0]);
        const uint32_t* pB = reinterpret_cast<const uint32_t*>(&Bs[st][0]);
        uint32_t bhf[4][2];
        #pragma unroll
        for (int ni = 0; ni < 4; ni++){
            int n = wn + ni*8 + g;
            bhf[ni][0] = pB[n*12 + tg];
            bhf[ni][1] = pB[n*12 + tg + 4];
        }
        #pragma unroll
        for (int mi = 0; mi < 4; mi++){
            int m = wm + mi*16;
            uint32_t ahf[4];
            ahf[0] = pA[(m+g)*12   + tg];
            ahf[1] = pA[(m+g+8)*12 + tg];
            ahf[2] = pA[(m+g)*12   + tg + 4];
            ahf[3] = pA[(m+g+8)*12 + tg + 4];
            #pragma unroll
            for (int ni = 0; ni < 4; ni++)
                mma_bf16(acc[mi][ni], ahf, bhf[ni]);
        }
        __syncthreads();
    }

    if (MODE == 0){
        #pragma unroll
        for (int mi = 0; mi < 4; mi++)
            #pragma unroll
            for (int ni = 0; ni < 4; ni++){
                int col = bn + wn + ni*8 + 2*tg;
                #pragma unroll
                for (int r = 0; r < 4; r++){
                    int gm = bm + wm + mi*16 + g + (r >= 2 ? 8 : 0);
                    int gn = col + (r & 1);
                    if (gn >= N) continue;
                    C[(size_t)gm*ldc + gn] = acc[mi][ni][r];
                }
            }
    } else {
        // gelu (col0 -> 0) + bf16 dual store + fused SSQ atomics
        #pragma unroll
        for (int mi = 0; mi < 4; mi++)
            #pragma unroll
            for (int ni = 0; ni < 4; ni++){
                int col = bn + wn + ni*8 + 2*tg;
                #pragma unroll
                for (int r = 0; r < 4; r++){
                    int gn = col + (r & 1);
                    float v = (gn == 0) ? 0.f : gelu_exact(acc[mi][ni][r]);
                    acc[mi][ni][r] = v;
                    int gm = bm + wm + mi*16 + g + (r >= 2 ? 8 : 0);
                    __nv_bfloat16 hv = __float2bfloat16_rn(v);
                    Cb [(size_t)gm*ldc + gn] = hv;
                    CbT[(size_t)gn*ldt + gm] = hv;
                }
            }
        #pragma unroll
        for (int mi = 0; mi < 4; mi++){
            #pragma unroll
            for (int half = 0; half < 2; half++){
                float rp = 0.f;
                #pragma unroll
                for (int ni = 0; ni < 4; ni++){
                    float a0 = acc[mi][ni][half*2], a1 = acc[mi][ni][half*2+1];
                    rp += a0*a0 + a1*a1;
                }
                rp += __shfl_down_sync(0xffffffffu, rp, 1);
                rp += __shfl_down_sync(0xffffffffu, rp, 2);
                if (tg == 0)
                    atomicAdd(&rss[(size_t)bz*1024 + bm + wm + mi*16 + g + half*8], rp);
            }
        }
        #pragma unroll
        for (int ni = 0; ni < 4; ni++){
            #pragma unroll
            for (int cb = 0; cb < 2; cb++){
                float cp = 0.f;
                #pragma unroll
                for (int mi = 0; mi < 4; mi++){
                    float a0 = acc[mi][ni][cb], a1 = acc[mi][ni][2+cb];
                    cp += a0*a0 + a1*a1;
                }
                cp += __shfl_down_sync(0xffffffffu, cp, 4);
                cp += __shfl_down_sync(0xffffffffu, cp, 8);
                cp += __shfl_down_sync(0xffffffffu, cp, 16);
                if (g == 0)
                    atomicAdd(&css[(size_t)bz*1024 + bn + wn + ni*8 + 2*tg + cb], cp);
            }
        }
    }
}

// ----------------------------- row-wise kernels ------------------------------------
// read Llin fp32, write full bf16 row (space + time) of Llh
__global__ void k_fix_time(const float* __restrict__ Llin, __nv_bfloat16* __restrict__ Llh){
    size_t row = blockIdx.x;
    int t = threadIdx.x;                                  // 256
    float sp = Llin[row*DPAD + 1 + t];
    float S = blockReduceSum(sp*sp);
    Llh[row*DPAD + 1 + t] = __float2bfloat16_rn(sp);
    if (t == 0) Llh[row*DPAD] = __float2bfloat16_rn(sqrtf(S + 1.f));
}
// warp-per-row poincare on 128-wide space rows
__global__ void k_poincare(const float* __restrict__ Y, float* __restrict__ out){
    size_t row = (size_t)blockIdx.x*8 + (threadIdx.x >> 5);
    int lane = threadIdx.x & 31;
    const float* y = Y + row*KKW;
    float v[4], s = 0.f;
    #pragma unroll
    for (int i = 0; i < 4; i++){ v[i] = y[lane + i*32]; s += v[i]*v[i]; }
    s = wsum(s);
    float inv = 1.f / (sqrtf(s + 1.f) + 1.f);
    float* o = out + row*KKW;
    #pragma unroll
    for (int i = 0; i < 4; i++) o[lane + i*32] = v[i] * inv;
}
// finalize norms; write bf16 time entries into Lbh (col0) and LbTh (row0)
__global__ void k_nfin(const float* __restrict__ rss, const float* __restrict__ css,
                       __nv_bfloat16* __restrict__ Lbh, __nv_bfloat16* __restrict__ LbTh,
                       float* __restrict__ xnr, float* __restrict__ xnc){
    int b = blockIdx.x, n = threadIdx.x;                  // 1024
    float S = rss[b*1024 + n];
    float tv = sqrtf(S + 1.f);
    Lbh[((size_t)b*1024 + n)*1024] = __float2bfloat16_rn(tv);
    LbTh[(size_t)b*1024*1024 + n]  = __float2bfloat16_rn(tv);
    xnr[b*1024 + n] = sqrtf(fmaxf(2.f*S + 1.f, 1e-15f));
    float ts = blockReduceSum(S + 1.f);
    float c = css[b*1024 + n];
    xnc[b*1024 + n] = (n == 0) ? sqrtf(ts) : sqrtf(fmaxf(c, 1e-15f));
}
// mobius_matvec scale from MxcT
__global__ void k_mscale(const float* __restrict__ MxT, const float* __restrict__ xna,
                         float* __restrict__ sc){
    int b = blockIdx.y;
    int m = blockIdx.x*256 + threadIdx.x;
    const float* base = MxT + (size_t)b*KKW*NCQ + m;
    float ss = 0.f;
    #pragma unroll 4
    for (int j = 0; j < KKW; j++){
        float v = base[(size_t)j*NCQ];
        ss += v*v;
    }
    float mxn = sqrtf(fmaxf(ss, 1e-15f));
    float xn = xna[b*NCQ + m];
    sc[b*NCQ + m] = tanhf(mxn / xn * atanhc(xn)) / mxn;
}
// warp-per-row fused Hs pipeline
__global__ void k_hs(const float* __restrict__ Hsa, const float* __restrict__ MxRaw,
                     const float* __restrict__ xnr,
                     const float* __restrict__ whs, float* __restrict__ lg){
    size_t row = (size_t)blockIdx.x*8 + (threadIdx.x >> 5);
    int lane = threadIdx.x & 31;
    const float* my = MxRaw + row*KKW;
    const float* hx = Hsa + row*KKW;
    float yr[4], x[4];
    float mm = 0.f;
    #pragma unroll
    for (int i = 0; i < 4; i++){
        yr[i] = my[lane + i*32];
        x[i]  = hx[lane + i*32];
        mm += yr[i]*yr[i];
    }
    mm = wsum(mm);
    float mxn = sqrtf(fmaxf(mm, 1e-15f));
    float xnb = xnr[row];
    float fac = tanhf(mxn / xnb * atanhc(xnb)) / mxn;

    float xy = 0.f, x2 = 0.f, y2 = 0.f;
    float y[4];
    #pragma unroll
    for (int i = 0; i < 4; i++){
        y[i] = yr[i] * fac;
        xy += x[i]*y[i]; x2 += x[i]*x[i]; y2 += y[i]*y[i];
    }
    xy = wsum(xy); x2 = wsum(x2); y2 = wsum(y2);
    float den = fmaxf(1.f + 2.f*xy + x2*y2, 1e-15f);
    float c1 = (1.f + 2.f*xy + y2) / den, c2 = (1.f - x2) / den;
    float h[4], hh = 0.f;
    #pragma unroll
    for (int i = 0; i < 4; i++){ h[i] = c1*x[i] + c2*y[i]; hh += h[i]*h[i]; }
    hh = wsum(hh);
    float hn = sqrtf(fmaxf(hh, 1e-15f));
    float fa = atanhc(hn) / hn;
    float gv[4], gg = 0.f;
    #pragma unroll
    for (int i = 0; i < 4; i++){ gv[i] = gelu_exact(fa*h[i]); gg += gv[i]*gv[i]; }
    gg = wsum(gg);
    float gn = sqrtf(fmaxf(gg, 1e-15f));
    float fb = tanhf(gn) / gn;
    float mx = 0.f, xn2 = 0.f;
    #pragma unroll
    for (int i = 0; i < 4; i++){
        float hs = fb * gv[i];
        mx += hs * __ldg(&whs[lane + i*32]);
        xn2 += hs*hs;
    }
    mx = wsum(mx); xn2 = wsum(xn2);
    if (lane == 0){
        float xn = sqrtf(fmaxf(xn2, 1e-15f));
        float mxn2 = sqrtf(fmaxf(mx*mx, 1e-15f));
        lg[row] = tanhf(mxn2 / xn * atanhc(xn)) * mx / mxn2;
    }
}
// dual transpose: z<BB: Hca -> HcaT fp32 + HcaTh bf16 ; z>=BB: Hsa -> HsahT bf16
__global__ void k_tbk2(const float* __restrict__ Hca, const float* __restrict__ Hsa,
                       float* __restrict__ HcaT, __nv_bfloat16* __restrict__ HcaTh,
                       __nv_bfloat16* __restrict__ HsahT){
    __shared__ float tile[32][33];
    int z = blockIdx.z;
    bool isHc = z < BB;
    int b = isHc ? z : z - BB;
    int j0 = blockIdx.x*32, m0 = blockIdx.y*32;
    const float* src = (isHc ? Hca : Hsa) + (size_t)b*NCQ*KKW;
    for (int i = threadIdx.y; i < 32; i += 8)
        tile[i][threadIdx.x] = src[(size_t)(m0+i)*KKW + j0 + threadIdx.x];
    __syncthreads();
    size_t base = (size_t)b*KKW*NCQ;
    for (int i = threadIdx.y; i < 32; i += 8){
        float v = tile[threadIdx.x][i];
        size_t idx = base + (size_t)(j0+i)*NCQ + m0 + threadIdx.x;
        if (isHc){ HcaT[idx] = v; HcaTh[idx] = __float2bfloat16_rn(v); }
        else     { HsahT[idx] = __float2bfloat16_rn(v); }
    }
}
// Hc pipeline on transposed inputs, fused Ac-logit accumulation (atomics)
__global__ void k_hc(const float* __restrict__ HcaT, const float* __restrict__ MxcT,
                     const float* __restrict__ sc, const float* __restrict__ whc,
                     float* __restrict__ amx, float* __restrict__ ass){
    int bj = blockIdx.x;
    int b = bj >> 7, j = bj & 127;
    int t = threadIdx.x;                                  // 256
    float wj = __ldg(&whc[j]);
    const float* xrow = HcaT + ((size_t)(b*KKW + j))*NCQ;
    const float* yrow = MxcT + ((size_t)(b*KKW + j))*NCQ;
    const float* srow = sc + (size_t)b*NCQ;
    float x[4], y[4];
    #pragma unroll
    for (int i = 0; i < 4; i++){
        int m = t + i*256;
        x[i] = xrow[m]; y[i] = yrow[m] * srow[m];
    }
    float sxy = 0.f, sx2 = 0.f, sy2 = 0.f;
    #pragma unroll
    for (int i = 0; i < 4; i++){ sxy += x[i]*y[i]; sx2 += x[i]*x[i]; sy2 += y[i]*y[i]; }
    blockReduceSum3(sxy, sx2, sy2);
    float xy = sxy, x2 = sx2, y2 = sy2;
    float den = fmaxf(1.f + 2.f*xy + x2*y2, 1e-15f);
    float c1 = 1.f + 2.f*xy + y2, c2 = 1.f - x2;
    float h[4], hh = 0.f;
    #pragma unroll
    for (int i = 0; i < 4; i++){ h[i] = (c1*x[i] + c2*y[i]) / den; hh += h[i]*h[i]; }
    float hn = sqrtf(fmaxf(blockReduceSum(hh), 1e-15f));
    float fa = atanhc(hn) / hn;
    float g[4], gg = 0.f;
    #pragma unroll
    for (int i = 0; i < 4; i++){ g[i] = gelu_exact(fa*h[i]); gg += g[i]*g[i]; }
    float gn = sqrtf(fmaxf(blockReduceSum(gg), 1e-15f));
    float fb = tanhf(gn) / gn;
    #pragma unroll
    for (int i = 0; i < 4; i++){
        int m = t + i*256;
        float hc = fb * g[i];
        atomicAdd(&amx[b*NCQ + m], hc * wj);
        atomicAdd(&ass[b*NCQ + m], hc * hc);
    }
}
__global__ void k_acfin(const float* __restrict__ amx, const float* __restrict__ ass,
                        float* __restrict__ lg){
    int b = blockIdx.x, m = threadIdx.x;                  // 1024
    float mx = amx[b*NCQ + m];
    float ss = ass[b*NCQ + m];
    float xn = sqrtf(fmaxf(ss, 1e-15f));
    float mxn = sqrtf(fmaxf(mx*mx, 1e-15f));
    lg[b*NCQ + m] = tanhf(mxn / xn * atanhc(xn)) * mx / mxn;
}
__global__ void k_softmax(const float* __restrict__ lg, float* __restrict__ out){
    int b = blockIdx.x, t = threadIdx.x;                  // 256
    float l[4];
    float lm = -3.4e38f;
    #pragma unroll
    for (int i = 0; i < 4; i++){ l[i] = lg[b*1024 + t + i*256]; lm = fmaxf(lm, l[i]); }
    float M = blockReduceMax(lm);
    float es = 0.f, e[4];
    #pragma unroll
    for (int i = 0; i < 4; i++){ e[i] = expf(l[i] - M); es += e[i]; }
    float S = blockReduceSum(es);
    #pragma unroll
    for (int i = 0; i < 4; i++) out[b*1024 + t + i*256] = e[i] / S;
}
__global__ void k_centroid_part(const float* __restrict__ Lx, const float* __restrict__ w,
                                float* __restrict__ part){
    __shared__ float wsh[128];
    int ch = blockIdx.x, b = blockIdx.y;
    int t = threadIdx.x;                                  // 288, t<257 active
    for (int i = t; i < 128; i += blockDim.x) wsh[i] = w[(size_t)b*NSQ + ch*128 + i];
    __syncthreads();
    if (t < DP1){
        const float* base = Lx + ((size_t)b*NSQ + (size_t)ch*128)*DPAD + t;
        float acc = 0.f;
        for (int n = 0; n < 128; n++) acc += wsh[n] * base[(size_t)n*DPAD];
        part[(b*8 + ch)*DP1 + t] = acc;
    }
}
__global__ void k_centroid_fin(const float* __restrict__ part, float* __restrict__ co){
    __shared__ float t0sh;
    int b = blockIdx.x, t = threadIdx.x;                  // 288
    float acc = 0.f;
    if (t < DP1){
        #pragma unroll
        for (int c = 0; c < 8; c++) acc += part[(b*8 + c)*DP1 + t];
    }
    float sp = (t >= 1 && t < DP1) ? acc*acc : 0.f;
    float ssp = blockReduceSum(sp);
    if (t == 0) t0sh = acc;
    __syncthreads();
    float inner = -t0sh*t0sh + ssp;
    float den = sqrtf(fmaxf(fabsf(inner), 1e-8f));
    if (t < DP1) co[(size_t)b*DP1 + t] = acc / den;
}
__global__ void k_concat(const float* __restrict__ cs, const float* __restrict__ cc,
                         float* __restrict__ out){
    int b = blockIdx.x, t = threadIdx.x;                  // 256
    float t0s = cs[(size_t)b*DP1];
    float t0c = cc[(size_t)b*DP1];
    float sps = cs[(size_t)b*DP1 + 1 + t];
    float spc = cc[(size_t)b*DP1 + 1 + t];
    float ns  = sqrtf(fmaxf(blockReduceSum(sps*sps), 1e-15f));
    float ncv = sqrtf(fmaxf(blockReduceSum(spc*spc), 1e-15f));
    float zs = acoshf(fmaxf(t0s, 1.f + 1e-7f)) * sps / ns;
    float zc = acoshf(fmaxf(t0c, 1.f + 1e-7f)) * spc / ncv;
    float vn = sqrtf(fmaxf(blockReduceSum(zs*zs + zc*zc), 1e-15f));
    float f = sinhf(vn) / vn;
    float* o = out + (size_t)b*513;
    if (t == 0) o[0] = coshf(vn);
    o[1 + t]       = f * zs;
    o[1 + DD + t]  = f * zc;
}

// ----------------------------- launch ----------------------------------------------
extern "C" void kernel_launch(void* const* d_in, const int* in_sizes, int n_in,
                              void* d_out, int out_size)
{
    const float* sent = (const float*)d_in[0];
    const float* comm = (const float*)d_in[1];
    const float* WlW  = (const float*)d_in[2];
    const float* Wlb  = (const float*)d_in[3];
    const float* WcW  = (const float*)d_in[4];
    const float* Wcb  = (const float*)d_in[5];
    const float* WsW  = (const float*)d_in[6];
    const float* Wsb  = (const float*)d_in[7];
    const float* whs  = (const float*)d_in[8];
    const float* whc  = (const float*)d_in[9];
    float* out = (float*)d_out;
    (void)in_sizes; (void)n_in; (void)out_size;

    float2 *c1, *c1T;
    float *sT, *rl, *Ls, *Lc, *Llin, *Yt, *Wt, *rss, *css, *amx, *ass, *xnr, *xnc,
          *msc, *Hsa, *Hca, *HcaT, *Mxs, *MxcT, *lgs, *lgc, *cs, *cc, *part;
    __nv_bfloat16 *Lsh, *Llh, *Lbh, *LbTh, *HcaTh, *HsahT;
    cudaGetSymbolAddress((void**)&c1,  g_c1);
    cudaGetSymbolAddress((void**)&c1T, g_c1T);
    cudaGetSymbolAddress((void**)&sT,  g_sT);
    cudaGetSymbolAddress((void**)&rl,  g_real);
    cudaGetSymbolAddress((void**)&Ls,  g_Ls);
    cudaGetSymbolAddress((void**)&Lc,  g_Lc);
    cudaGetSymbolAddress((void**)&Llin,g_Llin);
    cudaGetSymbolAddress((void**)&Yt,  g_Yt);
    cudaGetSymbolAddress((void**)&Wt,  g_Wt);
    cudaGetSymbolAddress((void**)&Lsh, g_Lsh);
    cudaGetSymbolAddress((void**)&Llh, g_Llh);
    cudaGetSymbolAddress((void**)&Lbh, g_Lbh);
    cudaGetSymbolAddress((void**)&LbTh,g_LbTh);
    cudaGetSymbolAddress((void**)&HcaTh,g_HcaTh);
    cudaGetSymbolAddress((void**)&HsahT,g_HsahT);
    cudaGetSymbolAddress((void**)&rss, g_rss);
    cudaGetSymbolAddress((void**)&css, g_css);
    cudaGetSymbolAddress((void**)&amx, g_amx);
    cudaGetSymbolAddress((void**)&ass, g_ass);
    cudaGetSymbolAddress((void**)&xnr, g_xnr);
    cudaGetSymbolAddress((void**)&xnc, g_xnc);
    cudaGetSymbolAddress((void**)&msc, g_msc);
    cudaGetSymbolAddress((void**)&Hsa, g_Hsa);
    cudaGetSymbolAddress((void**)&Hca, g_Hca);
    cudaGetSymbolAddress((void**)&HcaT,g_HcaT);
    cudaGetSymbolAddress((void**)&Mxs, g_Mxs);
    cudaGetSymbolAddress((void**)&MxcT,g_MxcT);
    cudaGetSymbolAddress((void**)&lgs, g_lgs);
    cudaGetSymbolAddress((void**)&lgc, g_lgc);
    cudaGetSymbolAddress((void**)&cs,  g_cs);
    cudaGetSymbolAddress((void**)&cc,  g_cc);
    cudaGetSymbolAddress((void**)&part,g_part);

    const int AS_OFF = BB*513;             // 16416
    const int AC_OFF = AS_OFF + BB*NSQ;    // 49184

    k_setup<<<32 + DP1 + 2*KP1, 1024>>>(WlW, WsW, WcW, Wt, rss, css, amx, ass);

    // ---- dual-branch FFT2 (stage-0 fused, Hermitian-compact) + euclid_to_lorentz ----
    k_fft256<<<2*BB*NSQ/4, dim3(64,4)>>>(sent, comm, c1);
    k_transpose_ch<<<dim3(5, NSQ/32, 2*BB), dim3(32,8)>>>(c1, c1T);
    k_fft1024<<<2*BB*DH, 256>>>(c1T, sT);
    k_transpose_fh<<<dim3(5, NSQ/32, 2*BB), dim3(32,8)>>>(sT, rl);
    k_e2l<<<2*BB*NSQ, 256>>>(rl, Ls, Lc, Lsh);

    // ---- linear layers (tf32; dead time-column skipped) ----
    k_pgemm<0,1,1,0><<<dim3(2,256,1),256>>>(Lc, Wt + (size_t)1*DPAD, Wlb + 1, Llin + 1,
        BB*NCQ, 256, DP1, DPAD, DPAD, DPAD, 0, 0, 0, nullptr, nullptr);
    k_fix_time<<<BB*NCQ, 256>>>(Llin, Llh);

    k_pgemm<0,1,1,0><<<dim3(1,256,1),256>>>(Ls, Wt + (size_t)385*DPAD, Wsb + 1, Yt,
        BB*NSQ, KKW, DP1, DPAD, DPAD, KKW, 0, 0, 0, nullptr, nullptr);
    k_poincare<<<BB*NSQ/8, 256>>>(Yt, Hsa);

    k_pgemm<0,1,1,0><<<dim3(1,256,1),256>>>(Lc, Wt + (size_t)641*DPAD, Wcb + 1, Yt,
        BB*NCQ, KKW, DP1, DPAD, DPAD, KKW, 0, 0, 0, nullptr, nullptr);
    k_poincare<<<BB*NCQ/8, 256>>>(Yt, Hca);

    // ---- big einsum (bf16) + lorentz_act + fused norms, dual bf16 outputs ----
    k_bgemm<2><<<dim3(8,8,BB),256>>>(Lsh, Llh, nullptr, Lbh, LbTh,
        NSQ, NCQ, DP1, DPAD, DPAD, NCQ, NSQ,
        (long)NSQ*DPAD, (long)NCQ*DPAD, 0, (long)NSQ*NCQ, rss, css);
    k_nfin<<<BB, 1024>>>(rss, css, Lbh, LbTh, xnr, xnc);

    // ---- transposes for mobius operands ----
    k_tbk2<<<dim3(4, 32, 2*BB), dim3(32,8)>>>(Hca, Hsa, HcaT, HcaTh, HsahT);

    // ---- mobius_matvec GEMMs (bf16) ----
    k_bgemm<0><<<dim3(1,8,BB),256>>>(Lbh, HcaTh, Mxs, nullptr, nullptr,
        NSQ, KKW, NCQ, NCQ, NCQ, KKW, 0,
        (long)NSQ*NCQ, (long)KKW*NCQ, (long)NSQ*KKW, 0, nullptr, nullptr);
    k_bgemm<0><<<dim3(8,1,BB),256>>>(HsahT, LbTh, MxcT, nullptr, nullptr,
        KKW, NCQ, NSQ, NSQ, NSQ, NCQ, 0,
        (long)KKW*NSQ, (long)NCQ*NSQ, (long)KKW*NCQ, 0, nullptr, nullptr);
    k_mscale<<<dim3(NCQ/256, BB), 256>>>(MxcT, xnc, msc);

    // ---- mobius_add + gelu pipelines + attention logits ----
    k_hs<<<BB*NSQ/8, 256>>>(Hsa, Mxs, xnr, whs, lgs);
    k_hc<<<BB*KKW, 256>>>(HcaT, MxcT, msc, whc, amx, ass);
    k_acfin<<<BB, 1024>>>(amx, ass, lgc);

    // ---- softmaxes straight into output ----
    k_softmax<<<BB, 256>>>(lgs, out + AS_OFF);
    k_softmax<<<BB, 256>>>(lgc, out + AC_OFF);

    // ---- centroids + concat ----
    k_centroid_part<<<dim3(8,BB), 288>>>(Ls, out + AS_OFF, part);
    k_centroid_fin<<<BB, 288>>>(part, cs);
    k_centroid_part<<<dim3(8,BB), 288>>>(Lc, out + AC_OFF, part);
    k_centroid_fin<<<BB, 288>>>(part, cc);
    k_concat<<<BB, 256>>>(cs, cc, out);
}

// round 12
// speedup vs baseline: 1.1372x; 1.1372x over previous
#include <cuda_runtime.h>
#include <cuda_bf16.h>
#include <math.h>
#include <stdint.h>

#define BB  32
#define NSQ 1024
#define NCQ 1024
#define DD  256
#define DP1 257
#define DPAD 272
#define KKW 128
#define KP1 129
#define DH  129   // Hermitian-reduced column count

// ----------------------------- scratch (static device globals; no runtime alloc) ---
static __device__ float2 g_c1 [(size_t)2*BB*NSQ*DH];
static __device__ float2 g_c1T[(size_t)2*BB*DH*NSQ];
static __device__ float  g_sT [(size_t)2*BB*DH*NSQ];
static __device__ float  g_real[(size_t)2*BB*NSQ*DH];
static __device__ float  g_Ls [(size_t)BB*NSQ*DPAD];
static __device__ float  g_Lc [(size_t)BB*NCQ*DPAD];
static __device__ float  g_Llin[(size_t)BB*NCQ*DPAD];
static __device__ float  g_Yt [(size_t)BB*NSQ*KKW];
static __device__ float  g_Wt [(size_t)896*DPAD];     // Wl@0, Ws@384*DPAD, Wc@640*DPAD
static __device__ __align__(16) __nv_bfloat16 g_Lsh [(size_t)BB*NSQ*DPAD];
static __device__ __align__(16) __nv_bfloat16 g_Llh [(size_t)BB*NCQ*DPAD];
static __device__ __align__(16) __nv_bfloat16 g_Lbh [(size_t)BB*NSQ*NCQ];
static __device__ __align__(16) __nv_bfloat16 g_LbTh[(size_t)BB*NCQ*NSQ];
static __device__ __align__(16) __nv_bfloat16 g_HcaTh[(size_t)BB*KKW*NCQ];
static __device__ __align__(16) __nv_bfloat16 g_HsahT[(size_t)BB*KKW*NSQ];
static __device__ float  g_rss[BB*NSQ];
static __device__ float  g_css[BB*NCQ];
static __device__ float  g_amx[BB*NCQ];
static __device__ float  g_ass[BB*NCQ];
static __device__ float  g_xnr[BB*NSQ];
static __device__ float  g_xnc[BB*NCQ];
static __device__ float  g_msc[BB*NCQ];
static __device__ float  g_Hsa[(size_t)BB*NSQ*KKW];
static __device__ float  g_Hca[(size_t)BB*NCQ*KKW];
static __device__ float  g_HcaT[(size_t)BB*KKW*NCQ];
static __device__ float  g_Mxs[(size_t)BB*NSQ*KKW];
static __device__ float  g_MxcT[(size_t)BB*KKW*NCQ];
static __device__ float  g_lgs[BB*NSQ];
static __device__ float  g_lgc[BB*NCQ];
static __device__ float  g_cs [BB*DP1];
static __device__ float  g_cc [BB*DP1];
static __device__ float  g_part[BB*8*DP1];
static __device__ float2 g_tw1024[1024];
static __device__ float2 g_tw256[256];

// ----------------------------- helpers ---------------------------------------------
__device__ __forceinline__ float atanhc(float x){
    x = fminf(fmaxf(x, -1.f + 1e-5f), 1.f - 1e-5f);
    return 0.5f * (log1pf(x) - log1pf(-x));
}
__device__ __forceinline__ float gelu_exact(float v){
    return 0.5f * v * (1.f + erff(v * 0.70710678118654752f));
}
__device__ __forceinline__ float2 cmul(float2 a, float2 b){
    return make_float2(a.x*b.x - a.y*b.y, a.x*b.y + a.y*b.x);
}
__device__ __forceinline__ float2 cadd(float2 a, float2 b){ return make_float2(a.x+b.x, a.y+b.y); }
__device__ __forceinline__ float2 csub(float2 a, float2 b){ return make_float2(a.x-b.x, a.y-b.y); }

__device__ __forceinline__ float wsum(float v){
    #pragma unroll
    for (int o = 16; o; o >>= 1) v += __shfl_xor_sync(0xffffffffu, v, o);
    return v;
}
__device__ __forceinline__ float blockReduceSum(float v){
    __shared__ float sh[32];
    #pragma unroll
    for (int o = 16; o; o >>= 1) v += __shfl_down_sync(0xffffffffu, v, o);
    int lane = threadIdx.x & 31, w = threadIdx.x >> 5;
    if (lane == 0) sh[w] = v;
    __syncthreads();
    int nw = (blockDim.x + 31) >> 5;
    v = (threadIdx.x < (unsigned)nw) ? sh[threadIdx.x] : 0.f;
    if (w == 0){
        #pragma unroll
        for (int o = 16; o; o >>= 1) v += __shfl_down_sync(0xffffffffu, v, o);
        if (lane == 0) sh[0] = v;
    }
    __syncthreads();
    float r = sh[0];
    __syncthreads();
    return r;
}
__device__ __forceinline__ void blockReduceSum3(float& a, float& b, float& c){
    __shared__ float sh3[32][3];
    #pragma unroll
    for (int o = 16; o; o >>= 1){
        a += __shfl_down_sync(0xffffffffu, a, o);
        b += __shfl_down_sync(0xffffffffu, b, o);
        c += __shfl_down_sync(0xffffffffu, c, o);
    }
    int lane = threadIdx.x & 31, w = threadIdx.x >> 5;
    if (lane == 0){ sh3[w][0] = a; sh3[w][1] = b; sh3[w][2] = c; }
    __syncthreads();
    int nw = (blockDim.x + 31) >> 5;
    a = (threadIdx.x < (unsigned)nw) ? sh3[threadIdx.x][0] : 0.f;
    b = (threadIdx.x < (unsigned)nw) ? sh3[threadIdx.x][1] : 0.f;
    c = (threadIdx.x < (unsigned)nw) ? sh3[threadIdx.x][2] : 0.f;
    if (w == 0){
        #pragma unroll
        for (int o = 16; o; o >>= 1){
            a += __shfl_down_sync(0xffffffffu, a, o);
            b += __shfl_down_sync(0xffffffffu, b, o);
            c += __shfl_down_sync(0xffffffffu, c, o);
        }
        if (lane == 0){ sh3[0][0] = a; sh3[0][1] = b; sh3[0][2] = c; }
    }
    __syncthreads();
    a = sh3[0][0]; b = sh3[0][1]; c = sh3[0][2];
    __syncthreads();
}
__device__ __forceinline__ float blockReduceMax(float v){
    __shared__ float sh[32];
    #pragma unroll
    for (int o = 16; o; o >>= 1) v = fmaxf(v, __shfl_down_sync(0xffffffffu, v, o));
    int lane = threadIdx.x & 31, w = threadIdx.x >> 5;
    if (lane == 0) sh[w] = v;
    __syncthreads();
    int nw = (blockDim.x + 31) >> 5;
    v = (threadIdx.x < (unsigned)nw) ? sh[threadIdx.x] : -3.4e38f;
    if (w == 0){
        #pragma unroll
        for (int o = 16; o; o >>= 1) v = fmaxf(v, __shfl_down_sync(0xffffffffu, v, o));
        if (lane == 0) sh[0] = v;
    }
    __syncthreads();
    float r = sh[0];
    __syncthreads();
    return r;
}
__device__ __forceinline__ uint32_t f2tf32(float v){
    uint32_t r;
    asm("cvt.rna.tf32.f32 %0, %1;" : "=r"(r) : "f"(v));
    return r;
}
__device__ __forceinline__ float tf32r(float v){ return __uint_as_float(f2tf32(v)); }
__device__ __forceinline__ void mma_tf32(float* c, const uint32_t* a, const uint32_t* b){
    asm volatile("mma.sync.aligned.m16n8k8.row.col.f32.tf32.tf32.f32 "
        "{%0,%1,%2,%3}, {%4,%5,%6,%7}, {%8,%9}, {%0,%1,%2,%3};"
        : "+f"(c[0]), "+f"(c[1]), "+f"(c[2]), "+f"(c[3])
        : "r"(a[0]), "r"(a[1]), "r"(a[2]), "r"(a[3]), "r"(b[0]), "r"(b[1]));
}
__device__ __forceinline__ void mma_bf16(float* c, const uint32_t* a, const uint32_t* b){
    asm volatile("mma.sync.aligned.m16n8k16.row.col.f32.bf16.bf16.f32 "
        "{%0,%1,%2,%3}, {%4,%5,%6,%7}, {%8,%9}, {%0,%1,%2,%3};"
        : "+f"(c[0]), "+f"(c[1]), "+f"(c[2]), "+f"(c[3])
        : "r"(a[0]), "r"(a[1]), "r"(a[2]), "r"(a[3]), "r"(b[0]), "r"(b[1]));
}
__device__ __forceinline__ void cpa16(uint32_t dsh, const void* src){
    asm volatile("cp.async.ca.shared.global [%0], [%1], 16;" :: "r"(dsh), "l"(src));
}
#define CP_COMMIT() asm volatile("cp.async.commit_group;" ::: "memory")
#define CP_WAIT1()  asm volatile("cp.async.wait_group 1;" ::: "memory")
#define CP_WAIT0()  asm volatile("cp.async.wait_group 0;" ::: "memory")

// ----------------------------- merged setup kernel ---------------------------------
__global__ void k_setup(const float* __restrict__ Wl, const float* __restrict__ Ws,
                        const float* __restrict__ Wc, float* __restrict__ Wt,
                        float* __restrict__ a, float* __restrict__ b,
                        float* __restrict__ c, float* __restrict__ d){
    int blk = blockIdx.x;
    int t = threadIdx.x;                       // 1024
    if (blk < 32){
        int i = blk*1024 + t;
        a[i] = 0.f; b[i] = 0.f; c[i] = 0.f; d[i] = 0.f;
        if (blk == 0){
            double ang = -6.283185307179586476925287 * (double)t / 1024.0;
            g_tw1024[t] = make_float2((float)cos(ang), (float)sin(ang));
            if (t < 256){
                double a2 = -6.283185307179586476925287 * (double)t / 256.0;
                g_tw256[t] = make_float2((float)cos(a2), (float)sin(a2));
            }
        }
        return;
    }
    int r = blk - 32;                          // 0..514
    if (t >= DP1) return;
    const float* src; float* dst;
    if (r < DP1){ src = Wl + (size_t)r*DP1; dst = Wt + (size_t)r*DPAD; }
    else if (r < DP1 + KP1){ int rr = r - DP1; src = Ws + (size_t)rr*DP1; dst = Wt + (size_t)(384+rr)*DPAD; }
    else { int rr = r - DP1 - KP1; src = Wc + (size_t)rr*DP1; dst = Wt + (size_t)(640+rr)*DPAD; }
    dst[t] = tf32r(src[t]);
}

// ----------------------------- radix-4 Stockham FFT kernels ------------------------
__global__ void k_fft256(const float* __restrict__ sent, const float* __restrict__ comm,
                         float2* __restrict__ out){
    __shared__ float2 bufA[4][256];
    __shared__ float2 bufB[4][256];
    __shared__ float2 tws[256];
    __shared__ float  rsum[4][2];
    int tx = threadIdx.x;                      // 64
    int ty = threadIdx.y;                      // 4
    int tid = ty*64 + tx;
    size_t row = (size_t)blockIdx.x*4 + ty;
    bool do_log = row >= (size_t)BB*NSQ;
    const float* x = do_log ? (comm + (row - (size_t)BB*NSQ)*256) : (sent + row*256);
    tws[tid] = g_tw256[tid];

    float v0 = x[tx], v1 = x[tx+64], v2 = x[tx+128], v3 = x[tx+192];
    float ss = v0*v0 + v1*v1 + v2*v2 + v3*v3;
    #pragma unroll
    for (int o = 16; o; o >>= 1) ss += __shfl_down_sync(0xffffffffu, ss, o);
    if ((tx & 31) == 0) rsum[ty][tx >> 5] = ss;
    __syncthreads();
    if (do_log){
        float tot = rsum[ty][0] + rsum[ty][1];
        float yn = sqrtf(fmaxf(tot, 1e-15f));
        float f = atanhc(yn) / yn;
        v0 *= f; v1 *= f; v2 *= f; v3 *= f;
    }
    {
        float pa = v0 + v2, pb = v0 - v2;
        float pc = v1 + v3, pd = v1 - v3;
        bufA[ty][4*tx]     = make_float2(pa + pc, 0.f);
        bufA[ty][4*tx + 1] = make_float2(pb, -pd);
        bufA[ty][4*tx + 2] = make_float2(pa - pc, 0.f);
        bufA[ty][4*tx + 3] = make_float2(pb,  pd);
    }
    __syncthreads();

    float2* X = &bufA[ty][0];
    float2* Y = &bufB[ty][0];
    #pragma unroll
    for (int s = 1; s < 4; s++){
        int Ns = 1 << (2*s);
        int p = tx & (Ns - 1);
        float2 w1 = tws[p * (64/Ns)];
        float2 w2 = cmul(w1, w1);
        float2 w3 = cmul(w2, w1);
        float2 a0 = X[tx];
        float2 a1 = cmul(X[tx + 64],  w1);
        float2 a2 = cmul(X[tx + 128], w2);
        float2 a3 = cmul(X[tx + 192], w3);
        float2 pa = cadd(a0, a2), pb = csub(a0, a2);
        float2 pc = cadd(a1, a3), pd = csub(a1, a3);
        float2 dneg = make_float2(pd.y, -pd.x);
        float2 dpos = make_float2(-pd.y, pd.x);
        int idxD = ((tx >> (2*s)) << (2*s + 2)) + p;
        Y[idxD]          = cadd(pa, pc);
        Y[idxD + Ns]     = cadd(pb, dneg);
        Y[idxD + 2*Ns]   = csub(pa, pc);
        Y[idxD + 3*Ns]   = cadd(pb, dpos);
        __syncthreads();
        float2* tmp = X; X = Y; Y = tmp;
    }
    out[row*DH + tx]      = X[tx];
    out[row*DH + tx + 64] = X[tx + 64];
    if (tx == 0) out[row*DH + 128] = X[128];
}

__global__ void k_fft1024(const float2* __restrict__ in, float* __restrict__ outr){
    __shared__ float2 bufA[1024];
    __shared__ float2 bufB[1024];
    __shared__ float2 tws[1024];
    int t = threadIdx.x;                       // 256
    size_t row = blockIdx.x;
    const float2* src = in + row*1024;
    float2 a0 = src[t], a1 = src[t+256], a2 = src[t+512], a3 = src[t+768];
    #pragma unroll
    for (int i = 0; i < 4; i++)
        tws[t + i*256] = g_tw1024[t + i*256];
    {
        float2 pa = cadd(a0, a2), pb = csub(a0, a2);
        float2 pc = cadd(a1, a3), pd = csub(a1, a3);
        bufA[4*t]     = cadd(pa, pc);
        bufA[4*t + 1] = cadd(pb, make_float2(pd.y, -pd.x));
        bufA[4*t + 2] = csub(pa, pc);
        bufA[4*t + 3] = cadd(pb, make_float2(-pd.y, pd.x));
    }
    __syncthreads();
    float2* X = bufA;
    float2* Y = bufB;
    #pragma unroll
    for (int s = 1; s < 5; s++){
        int Ns = 1 << (2*s);
        int p = t & (Ns - 1);
        float2 w1 = tws[p * (256/Ns)];
        float2 w2 = cmul(w1, w1);
        float2 w3 = cmul(w2, w1);
        float2 b0 = X[t];
        float2 b1 = cmul(X[t + 256], w1);
        float2 b2 = cmul(X[t + 512], w2);
        float2 b3 = cmul(X[t + 768], w3);
        float2 pa = cadd(b0, b2), pb = csub(b0, b2);
        float2 pc = cadd(b1, b3), pd = csub(b1, b3);
        float2 dneg = make_float2(pd.y, -pd.x);
        float2 dpos = make_float2(-pd.y, pd.x);
        int idxD = ((t >> (2*s)) << (2*s + 2)) + p;
        Y[idxD]        = cadd(pa, pc);
        Y[idxD + Ns]   = cadd(pb, dneg);
        Y[idxD + 2*Ns] = csub(pa, pc);
        Y[idxD + 3*Ns] = cadd(pb, dpos);
        __syncthreads();
        float2* tmp = X; X = Y; Y = tmp;
    }
    #pragma unroll
    for (int i = 0; i < 4; i++)
        outr[row*1024 + t + i*256] = X[t + i*256].x;
}

__global__ void k_transpose_ch(const float2* __restrict__ in, float2* __restrict__ out){
    __shared__ float2 tile[32][33];
    int b = blockIdx.z;
    int c0 = blockIdx.x*32, r0 = blockIdx.y*32;
    const float2* src = in + (size_t)b*NSQ*DH;
    for (int i = threadIdx.y; i < 32; i += 8){
        int d = c0 + threadIdx.x;
        tile[i][threadIdx.x] = (d < DH) ? src[(size_t)(r0+i)*DH + d]
                                        : make_float2(0.f, 0.f);
    }
    __syncthreads();
    float2* dst = out + (size_t)b*DH*NSQ;
    for (int i = threadIdx.y; i < 32; i += 8){
        int d = c0 + i;
        if (d < DH) dst[(size_t)d*NSQ + r0 + threadIdx.x] = tile[threadIdx.x][i];
    }
}
__global__ void k_transpose_fh(const float* __restrict__ in, float* __restrict__ out){
    __shared__ float tile[32][33];
    int b = blockIdx.z;
    int d0 = blockIdx.x*32, n0 = blockIdx.y*32;
    const float* src = in + (size_t)b*DH*NSQ;
    for (int i = threadIdx.y; i < 32; i += 8){
        int d = d0 + i;
        tile[i][threadIdx.x] = (d < DH) ? src[(size_t)d*NSQ + n0 + threadIdx.x] : 0.f;
    }
    __syncthreads();
    float* dst = out + (size_t)b*NSQ*DH;
    int d = d0 + threadIdx.x;
    if (d < DH)
        for (int i = threadIdx.y; i < 32; i += 8)
            dst[(size_t)(n0+i)*DH + d] = tile[threadIdx.x][i];
}

// fused Hermitian mirror + euclid_to_lorentz; fp32 tf32-rounded + bf16 (sentence only)
__global__ void k_e2l(const float* __restrict__ rl, float* __restrict__ Ls,
                      float* __restrict__ Lc, __nv_bfloat16* __restrict__ Lsh){
    size_t row = blockIdx.x;                   // 0 .. 2*BB*NSQ-1
    int t = threadIdx.x;                       // 256
    size_t bb = row >> 10;
    int n = (int)(row & 1023);
    float v;
    if (t < DH){
        v = rl[(bb*NSQ + n)*DH + t];
    } else {
        int srcn = (1024 - n) & 1023;
        v = rl[(bb*NSQ + srcn)*DH + (256 - t)];
    }
    float ss = blockReduceSum(v*v);
    float xn = sqrtf(fmaxf(ss, 1e-15f)) + 1e-5f;
    float scl = fminf(1.f, 2.0f / xn);
    v *= scl;
    float vn = sqrtf(fmaxf(ss*scl*scl, 1e-15f));
    float f = sinhf(vn) / vn;
    float* out = (bb < BB) ? Ls : Lc;
    size_t orow = (bb < BB) ? row : row - (size_t)BB*NSQ;
    float tv = coshf(vn), sv = f * v;
    if (t == 0) out[orow*DPAD] = tf32r(tv);
    out[orow*DPAD + 1 + t] = tf32r(sv);
    if (t < DPAD - DP1) out[orow*DPAD + DP1 + t] = 0.f;
    if (bb < BB){
        if (t == 0) Lsh[orow*DPAD] = __float2bfloat16_rn(tv);
        Lsh[orow*DPAD + 1 + t] = __float2bfloat16_rn(sv);
    }
}

// --------- pipelined tensor-core GEMM (pre-rounded TF32; used for linear layers) ---
template<int ATRANS, int BTRANS, int MODE, int ROUND>
__global__ void k_pgemm(const float* __restrict__ A, const float* __restrict__ Bm,
                        const float* __restrict__ bias, float* __restrict__ C,
                        int M, int N, int Klen, int lda, int ldb, int ldc,
                        long sA, long sB, long sC,
                        float* __restrict__ rss, float* __restrict__ css)
{
    constexpr int A_ELE = (ATRANS == 0) ? 128*20 : 16*132;
    constexpr int B_ELE = (BTRANS == 1) ? 128*20 : 16*132;
    __shared__ __align__(16) float As[2][A_ELE];
    __shared__ __align__(16) float Bs[2][B_ELE];

    int bz = blockIdx.z;
    A  += (size_t)bz * sA;
    Bm += (size_t)bz * sB;
    C  += (size_t)bz * sC;
    int bm = blockIdx.y * 128, bn = blockIdx.x * 128;
    int tid = threadIdx.x;
    int wid = tid >> 5, lane = tid & 31;
    int wm = (wid >> 2) * 64;
    int wn = (wid & 3) * 32;
    int g = lane >> 2, tg = lane & 3;

    int KT = (Klen + 15) >> 4;

    uint32_t asBase = (uint32_t)__cvta_generic_to_shared(&As[0][0]);
    uint32_t bsBase = (uint32_t)__cvta_generic_to_shared(&Bs[0][0]);

    auto issueA = [&](int st, int k0){
        uint32_t base = asBase + (uint32_t)(st * A_ELE * 4);
        if (ATRANS == 0){
            #pragma unroll
            for (int i = 0; i < 2; i++){
                int idx = tid + i*256;
                int mm = idx >> 2, k4 = idx & 3;
                cpa16(base + (mm*20 + k4*4)*4, A + (size_t)(bm+mm)*lda + k0 + k4*4);
            }
        } else {
            #pragma unroll
            for (int i = 0; i < 2; i++){
                int idx = tid + i*256;
                int kk = idx >> 5, m4 = idx & 31;
                cpa16(base + (kk*132 + m4*4)*4, A + (size_t)(k0+kk)*lda + bm + m4*4);
            }
        }
    };
    auto issueB = [&](int st, int k0){
        uint32_t base = bsBase + (uint32_t)(st * B_ELE * 4);
        if (BTRANS == 1){
            #pragma unroll
            for (int i = 0; i < 2; i++){
                int idx = tid + i*256;
                int nn = idx >> 2, k4 = idx & 3;
                cpa16(base + (nn*20 + k4*4)*4, Bm + (size_t)(bn+nn)*ldb + k0 + k4*4);
            }
        } else {
            #pragma unroll
            for (int i = 0; i < 2; i++){
                int idx = tid + i*256;
                int kk = idx >> 5, n4 = idx & 31;
                cpa16(base + (kk*132 + n4*4)*4, Bm + (size_t)(k0+kk)*ldb + bn + n4*4);
            }
        }
    };
    auto A_at = [&](int st, int m, int k)->uint32_t{
        const uint32_t* p = reinterpret_cast<const uint32_t*>(&As[st][0]);
        return (ATRANS == 0) ? p[m*20 + k] : p[k*132 + m];
    };
    auto B_at = [&](int st, int n, int k)->uint32_t{
        const uint32_t* p = reinterpret_cast<const uint32_t*>(&Bs[st][0]);
        return (BTRANS == 1) ? p[n*20 + k] : p[k*132 + n];
    };

    float acc[4][4][4];
    #pragma unroll
    for (int mi = 0; mi < 4; mi++)
        #pragma unroll
        for (int ni = 0; ni < 4; ni++)
            #pragma unroll
            for (int r = 0; r < 4; r++) acc[mi][ni][r] = 0.f;

    issueA(0, 0); issueB(0, 0);
    CP_COMMIT();

    for (int kt = 0; kt < KT; kt++){
        int st = kt & 1;
        if (kt + 1 < KT){
            issueA(st ^ 1, (kt+1)*16);
            issueB(st ^ 1, (kt+1)*16);
            CP_COMMIT();
            CP_WAIT1();
        } else {
            CP_WAIT0();
        }
        __syncthreads();

        #pragma unroll
        for (int ks = 0; ks < 2; ks++){
            int kk = ks*8;
            uint32_t bhf[4][2];
            #pragma unroll
            for (int ni = 0; ni < 4; ni++){
                int n = wn + ni*8 + g;
                bhf[ni][0] = B_at(st, n, kk+tg);
                bhf[ni][1] = B_at(st, n, kk+tg+4);
            }
            #pragma unroll
            for (int mi = 0; mi < 4; mi++){
                int m = wm + mi*16;
                uint32_t ahf[4];
                ahf[0] = A_at(st, m+g,   kk+tg);
                ahf[1] = A_at(st, m+g+8, kk+tg);
                ahf[2] = A_at(st, m+g,   kk+tg+4);
                ahf[3] = A_at(st, m+g+8, kk+tg+4);
                #pragma unroll
                for (int ni = 0; ni < 4; ni++)
                    mma_tf32(acc[mi][ni], ahf, bhf[ni]);
            }
        }
        __syncthreads();
    }

    #pragma unroll
    for (int mi = 0; mi < 4; mi++)
        #pragma unroll
        for (int ni = 0; ni < 4; ni++){
            int col = bn + wn + ni*8 + 2*tg;
            #pragma unroll
            for (int r = 0; r < 4; r++){
                int gm = bm + wm + mi*16 + g + (r >= 2 ? 8 : 0);
                int gn = col + (r & 1);
                if (gn >= N) continue;
                float v = acc[mi][ni][r];
                if (MODE == 1) v += bias[gn];
                if (ROUND) v = tf32r(v);
                C[(size_t)gm*ldc + gn] = v;
            }
        }
}

// --------- bf16 GEMM (m16n8k16): A[m][k], B[n][k]; MODE 0 fp32 C, MODE 2 einsum ----
// MODE 2 epilogue stages the 128x128 bf16 tile in shared memory (aliased over the
// mainloop buffers) so BOTH Cb and CbT stores are fully coalesced 128B bursts.
template<int MODE>
__global__ void k_bgemm(const __nv_bfloat16* __restrict__ A,
                        const __nv_bfloat16* __restrict__ Bm,
                        float* __restrict__ C,
                        __nv_bfloat16* __restrict__ Cb, __nv_bfloat16* __restrict__ CbT,
                        int M, int N, int Klen, int lda, int ldb, int ldc, int ldt,
                        long sA, long sB, long sC, long sCb,
                        float* __restrict__ rss, float* __restrict__ css)
{
    __shared__ __align__(16) char smemraw[49152];   // As(12KB) + Bs(12KB) / tile(34KB)
    __nv_bfloat16* AsBuf = reinterpret_cast<__nv_bfloat16*>(smemraw);
    __nv_bfloat16* BsBuf = reinterpret_cast<__nv_bfloat16*>(smemraw + 24576);

    int bz = blockIdx.z;
    A  += (size_t)bz * sA;
    Bm += (size_t)bz * sB;
    if (MODE == 0) C += (size_t)bz * sC;
    else { Cb += (size_t)bz * sCb; CbT += (size_t)bz * sCb; }
    int bm = blockIdx.y * 128, bn = blockIdx.x * 128;
    int tid = threadIdx.x;
    int wid = tid >> 5, lane = tid & 31;
    int wm = (wid >> 2) * 64;
    int wn = (wid & 3) * 32;
    int g = lane >> 2, tg = lane & 3;
    int KT = (Klen + 15) >> 4;

    uint32_t asBase = (uint32_t)__cvta_generic_to_shared(AsBuf);
    uint32_t bsBase = (uint32_t)__cvta_generic_to_shared(BsBuf);

    auto issueA = [&](int st, int k0){
        int mm = tid >> 1, c = tid & 1;
        cpa16(asBase + (uint32_t)(st*6144) + (mm*24 + c*8)*2,
              A + (size_t)(bm+mm)*lda + k0 + c*8);
    };
    auto issueB = [&](int st, int k0){
        int nn = tid >> 1, c = tid & 1;
        cpa16(bsBase + (uint32_t)(st*6144) + (nn*24 + c*8)*2,
              Bm + (size_t)(bn+nn)*ldb + k0 + c*8);
    };

    float acc[4][4][4];
    #pragma unroll
    for (int mi = 0; mi < 4; mi++)
        #pragma unroll
        for (int ni = 0; ni < 4; ni++)
            #pragma unroll
            for (int r = 0; r < 4; r++) acc[mi][ni][r] = 0.f;

    issueA(0, 0); issueB(0, 0);
    CP_COMMIT();

    for (int kt = 0; kt < KT; kt++){
        int st = kt & 1;
        if (kt + 1 < KT){
            issueA(st ^ 1, (kt+1)*16);
            issueB(st ^ 1, (kt+1)*16);
            CP_COMMIT();
            CP_WAIT1();
        } else {
            CP_WAIT0();
        }
        __syncthreads();

        // stage st occupies ELEMENT offset st*3072 (== byte offset st*6144)
        const uint32_t* pA = reinterpret_cast<const uint32_t*>(AsBuf + st*3072);
        const uint32_t* pB = reinterpret_cast<const uint32_t*>(BsBuf + st*3072);
        uint32_t bhf[4][2];
        #pragma unroll
        for (int ni = 0; ni < 4; ni++){
            int n = wn + ni*8 + g;
            bhf[ni][0] = pB[n*12 + tg];
            bhf[ni][1] = pB[n*12 + tg + 4];
        }
        #pragma unroll
        for (int mi = 0; mi < 4; mi++){
            int m = wm + mi*16;
            uint32_t ahf[4];
            ahf[0] = pA[(m+g)*12   + tg];
            ahf[1] = pA[(m+g+8)*12 + tg];
            ahf[2] = pA[(m+g)*12   + tg + 4];
            ahf[3] = pA[(m+g+8)*12 + tg + 4];
            #pragma unroll
            for (int ni = 0; ni < 4; ni++)
                mma_bf16(acc[mi][ni], ahf, bhf[ni]);
        }
        __syncthreads();
    }

    if (MODE == 0){
        #pragma unroll
        for (int mi = 0; mi < 4; mi++)
            #pragma unroll
            for (int ni = 0; ni < 4; ni++){
                int col = bn + wn + ni*8 + 2*tg;
                #pragma unroll
                for (int r = 0; r < 4; r++){
                    int gm = bm + wm + mi*16 + g + (r >= 2 ? 8 : 0);
                    int gn = col + (r & 1);
                    if (gn >= N) continue;
                    C[(size_t)gm*ldc + gn] = acc[mi][ni][r];
                }
            }
    } else {
        // gelu (global col0 -> 0) + SSQ atomics, then smem-staged coalesced stores
        #pragma unroll
        for (int mi = 0; mi < 4; mi++)
            #pragma unroll
            for (int ni = 0; ni < 4; ni++){
                int col = bn + wn + ni*8 + 2*tg;
                #pragma unroll
                for (int r = 0; r < 4; r++){
                    int gn = col + (r & 1);
                    acc[mi][ni][r] = (gn == 0) ? 0.f : gelu_exact(acc[mi][ni][r]);
                }
            }
        #pragma unroll
        for (int mi = 0; mi < 4; mi++){
            #pragma unroll
            for (int half = 0; half < 2; half++){
                float rp = 0.f;
                #pragma unroll
                for (int ni = 0; ni < 4; ni++){
                    float a0 = acc[mi][ni][half*2], a1 = acc[mi][ni][half*2+1];
                    rp += a0*a0 + a1*a1;
                }
                rp += __shfl_down_sync(0xffffffffu, rp, 1);
                rp += __shfl_down_sync(0xffffffffu, rp, 2);
                if (tg == 0)
                    atomicAdd(&rss[(size_t)bz*1024 + bm + wm + mi*16 + g + half*8], rp);
            }
        }
        #pragma unroll
        for (int ni = 0; ni < 4; ni++){
            #pragma unroll
            for (int cb = 0; cb < 2; cb++){
                float cp = 0.f;
                #pragma unroll
                for (int mi = 0; mi < 4; mi++){
                    float a0 = acc[mi][ni][cb], a1 = acc[mi][ni][2+cb];
                    cp += a0*a0 + a1*a1;
                }
                cp += __shfl_down_sync(0xffffffffu, cp, 4);
                cp += __shfl_down_sync(0xffffffffu, cp, 8);
                cp += __shfl_down_sync(0xffffffffu, cp, 16);
                if (g == 0)
                    atomicAdd(&css[(size_t)bz*1024 + bn + wn + ni*8 + 2*tg + cb], cp);
            }
        }
        // stage bf16 tile in smem (aliases mainloop buffers; safe after last sync)
        __syncthreads();
        constexpr int TS = 136;                 // padded row stride in bf16
        __nv_bfloat16* tile = reinterpret_cast<__nv_bfloat16*>(smemraw);
        #pragma unroll
        for (int mi = 0; mi < 4; mi++)
            #pragma unroll
            for (int ni = 0; ni < 4; ni++){
                int ln = wn + ni*8 + 2*tg;
                #pragma unroll
                for (int r = 0; r < 4; r++){
                    int lm = wm + mi*16 + g + (r >= 2 ? 8 : 0);
                    tile[lm*TS + ln + (r & 1)] = __float2bfloat16_rn(acc[mi][ni][r]);
                }
            }
        __syncthreads();
        {
            int row = tid >> 1, half = tid & 1;
            const uint4* srcv = reinterpret_cast<const uint4*>(tile + row*TS + half*64);
            uint4* dstv = reinterpret_cast<uint4*>(Cb + (size_t)(bm+row)*ldc + bn + half*64);
            #pragma unroll
            for (int i = 0; i < 8; i++) dstv[i] = srcv[i];
        }
        {
            int coln = tid >> 1, halfm = tid & 1;
            #pragma unroll
            for (int c8 = 0; c8 < 8; c8++){
                __nv_bfloat16 tmp[8];
                #pragma unroll
                for (int j = 0; j < 8; j++)
                    tmp[j] = tile[(halfm*64 + c8*8 + j)*TS + coln];
                *reinterpret_cast<uint4*>(CbT + (size_t)(bn+coln)*ldt + bm + halfm*64 + c8*8)
                    = *reinterpret_cast<const uint4*>(tmp);
            }
        }
    }
}

// ----------------------------- row-wise kernels ------------------------------------
// read Llin fp32, write full bf16 row (space + time) of Llh
__global__ void k_fix_time(const float* __restrict__ Llin, __nv_bfloat16* __restrict__ Llh){
    size_t row = blockIdx.x;
    int t = threadIdx.x;                                  // 256
    float sp = Llin[row*DPAD + 1 + t];
    float S = blockReduceSum(sp*sp);
    Llh[row*DPAD + 1 + t] = __float2bfloat16_rn(sp);
    if (t == 0) Llh[row*DPAD] = __float2bfloat16_rn(sqrtf(S + 1.f));
}
// warp-per-row poincare on 128-wide space rows
__global__ void k_poincare(const float* __restrict__ Y, float* __restrict__ out){
    size_t row = (size_t)blockIdx.x*8 + (threadIdx.x >> 5);
    int lane = threadIdx.x & 31;
    const float* y = Y + row*KKW;
    float v[4], s = 0.f;
    #pragma unroll
    for (int i = 0; i < 4; i++){ v[i] = y[lane + i*32]; s += v[i]*v[i]; }
    s = wsum(s);
    float inv = 1.f / (sqrtf(s + 1.f) + 1.f);
    float* o = out + row*KKW;
    #pragma unroll
    for (int i = 0; i < 4; i++) o[lane + i*32] = v[i] * inv;
}
// finalize norms; write bf16 time entries into Lbh (col0) and LbTh (row0)
__global__ void k_nfin(const float* __restrict__ rss, const float* __restrict__ css,
                       __nv_bfloat16* __restrict__ Lbh, __nv_bfloat16* __restrict__ LbTh,
                       float* __restrict__ xnr, float* __restrict__ xnc){
    int b = blockIdx.x, n = threadIdx.x;                  // 1024
    float S = rss[b*1024 + n];
    float tv = sqrtf(S + 1.f);
    Lbh[((size_t)b*1024 + n)*1024] = __float2bfloat16_rn(tv);
    LbTh[(size_t)b*1024*1024 + n]  = __float2bfloat16_rn(tv);
    xnr[b*1024 + n] = sqrtf(fmaxf(2.f*S + 1.f, 1e-15f));
    float ts = blockReduceSum(S + 1.f);
    float c = css[b*1024 + n];
    xnc[b*1024 + n] = (n == 0) ? sqrtf(ts) : sqrtf(fmaxf(c, 1e-15f));
}
// mobius_matvec scale from MxcT
__global__ void k_mscale(const float* __restrict__ MxT, const float* __restrict__ xna,
                         float* __restrict__ sc){
    int b = blockIdx.y;
    int m = blockIdx.x*256 + threadIdx.x;
    const float* base = MxT + (size_t)b*KKW*NCQ + m;
    float ss = 0.f;
    #pragma unroll 4
    for (int j = 0; j < KKW; j++){
        float v = base[(size_t)j*NCQ];
        ss += v*v;
    }
    float mxn = sqrtf(fmaxf(ss, 1e-15f));
    float xn = xna[b*NCQ + m];
    sc[b*NCQ + m] = tanhf(mxn / xn * atanhc(xn)) / mxn;
}
// warp-per-row fused Hs pipeline
__global__ void k_hs(const float* __restrict__ Hsa, const float* __restrict__ MxRaw,
                     const float* __restrict__ xnr,
                     const float* __restrict__ whs, float* __restrict__ lg){
    size_t row = (size_t)blockIdx.x*8 + (threadIdx.x >> 5);
    int lane = threadIdx.x & 31;
    const float* my = MxRaw + row*KKW;
    const float* hx = Hsa + row*KKW;
    float yr[4], x[4];
    float mm = 0.f;
    #pragma unroll
    for (int i = 0; i < 4; i++){
        yr[i] = my[lane + i*32];
        x[i]  = hx[lane + i*32];
        mm += yr[i]*yr[i];
    }
    mm = wsum(mm);
    float mxn = sqrtf(fmaxf(mm, 1e-15f));
    float xnb = xnr[row];
    float fac = tanhf(mxn / xnb * atanhc(xnb)) / mxn;

    float xy = 0.f, x2 = 0.f, y2 = 0.f;
    float y[4];
    #pragma unroll
    for (int i = 0; i < 4; i++){
        y[i] = yr[i] * fac;
        xy += x[i]*y[i]; x2 += x[i]*x[i]; y2 += y[i]*y[i];
    }
    xy = wsum(xy); x2 = wsum(x2); y2 = wsum(y2);
    float den = fmaxf(1.f + 2.f*xy + x2*y2, 1e-15f);
    float c1 = (1.f + 2.f*xy + y2) / den, c2 = (1.f - x2) / den;
    float h[4], hh = 0.f;
    #pragma unroll
    for (int i = 0; i < 4; i++){ h[i] = c1*x[i] + c2*y[i]; hh += h[i]*h[i]; }
    hh = wsum(hh);
    float hn = sqrtf(fmaxf(hh, 1e-15f));
    float fa = atanhc(hn) / hn;
    float gv[4], gg = 0.f;
    #pragma unroll
    for (int i = 0; i < 4; i++){ gv[i] = gelu_exact(fa*h[i]); gg += gv[i]*gv[i]; }
    gg = wsum(gg);
    float gn = sqrtf(fmaxf(gg, 1e-15f));
    float fb = tanhf(gn) / gn;
    float mx = 0.f, xn2 = 0.f;
    #pragma unroll
    for (int i = 0; i < 4; i++){
        float hs = fb * gv[i];
        mx += hs * __ldg(&whs[lane + i*32]);
        xn2 += hs*hs;
    }
    mx = wsum(mx); xn2 = wsum(xn2);
    if (lane == 0){
        float xn = sqrtf(fmaxf(xn2, 1e-15f));
        float mxn2 = sqrtf(fmaxf(mx*mx, 1e-15f));
        lg[row] = tanhf(mxn2 / xn * atanhc(xn)) * mx / mxn2;
    }
}
// dual transpose: z<BB: Hca -> HcaT fp32 + HcaTh bf16 ; z>=BB: Hsa -> HsahT bf16
__global__ void k_tbk2(const float* __restrict__ Hca, const float* __restrict__ Hsa,
                       float* __restrict__ HcaT, __nv_bfloat16* __restrict__ HcaTh,
                       __nv_bfloat16* __restrict__ HsahT){
    __shared__ float tile[32][33];
    int z = blockIdx.z;
    bool isHc = z < BB;
    int b = isHc ? z : z - BB;
    int j0 = blockIdx.x*32, m0 = blockIdx.y*32;
    const float* src = (isHc ? Hca : Hsa) + (size_t)b*NCQ*KKW;
    for (int i = threadIdx.y; i < 32; i += 8)
        tile[i][threadIdx.x] = src[(size_t)(m0+i)*KKW + j0 + threadIdx.x];
    __syncthreads();
    size_t base = (size_t)b*KKW*NCQ;
    for (int i = threadIdx.y; i < 32; i += 8){
        float v = tile[threadIdx.x][i];
        size_t idx = base + (size_t)(j0+i)*NCQ + m0 + threadIdx.x;
        if (isHc){ HcaT[idx] = v; HcaTh[idx] = __float2bfloat16_rn(v); }
        else     { HsahT[idx] = __float2bfloat16_rn(v); }
    }
}
// Hc pipeline on transposed inputs, fused Ac-logit accumulation (atomics)
__global__ void k_hc(const float* __restrict__ HcaT, const float* __restrict__ MxcT,
                     const float* __restrict__ sc, const float* __restrict__ whc,
                     float* __restrict__ amx, float* __restrict__ ass){
    int bj = blockIdx.x;
    int b = bj >> 7, j = bj & 127;
    int t = threadIdx.x;                                  // 256
    float wj = __ldg(&whc[j]);
    const float* xrow = HcaT + ((size_t)(b*KKW + j))*NCQ;
    const float* yrow = MxcT + ((size_t)(b*KKW + j))*NCQ;
    const float* srow = sc + (size_t)b*NCQ;
    float x[4], y[4];
    #pragma unroll
    for (int i = 0; i < 4; i++){
        int m = t + i*256;
        x[i] = xrow[m]; y[i] = yrow[m] * srow[m];
    }
    float sxy = 0.f, sx2 = 0.f, sy2 = 0.f;
    #pragma unroll
    for (int i = 0; i < 4; i++){ sxy += x[i]*y[i]; sx2 += x[i]*x[i]; sy2 += y[i]*y[i]; }
    blockReduceSum3(sxy, sx2, sy2);
    float xy = sxy, x2 = sx2, y2 = sy2;
    float den = fmaxf(1.f + 2.f*xy + x2*y2, 1e-15f);
    float c1 = 1.f + 2.f*xy + y2, c2 = 1.f - x2;
    float h[4], hh = 0.f;
    #pragma unroll
    for (int i = 0; i < 4; i++){ h[i] = (c1*x[i] + c2*y[i]) / den; hh += h[i]*h[i]; }
    float hn = sqrtf(fmaxf(blockReduceSum(hh), 1e-15f));
    float fa = atanhc(hn) / hn;
    float g[4], gg = 0.f;
    #pragma unroll
    for (int i = 0; i < 4; i++){ g[i] = gelu_exact(fa*h[i]); gg += g[i]*g[i]; }
    float gn = sqrtf(fmaxf(blockReduceSum(gg), 1e-15f));
    float fb = tanhf(gn) / gn;
    #pragma unroll
    for (int i = 0; i < 4; i++){
        int m = t + i*256;
        float hc = fb * g[i];
        atomicAdd(&amx[b*NCQ + m], hc * wj);
        atomicAdd(&ass[b*NCQ + m], hc * hc);
    }
}
__global__ void k_acfin(const float* __restrict__ amx, const float* __restrict__ ass,
                        float* __restrict__ lg){
    int b = blockIdx.x, m = threadIdx.x;                  // 1024
    float mx = amx[b*NCQ + m];
    float ss = ass[b*NCQ + m];
    float xn = sqrtf(fmaxf(ss, 1e-15f));
    float mxn = sqrtf(fmaxf(mx*mx, 1e-15f));
    lg[b*NCQ + m] = tanhf(mxn / xn * atanhc(xn)) * mx / mxn;
}
__global__ void k_softmax(const float* __restrict__ lg, float* __restrict__ out){
    int b = blockIdx.x, t = threadIdx.x;                  // 256
    float l[4];
    float lm = -3.4e38f;
    #pragma unroll
    for (int i = 0; i < 4; i++){ l[i] = lg[b*1024 + t + i*256]; lm = fmaxf(lm, l[i]); }
    float M = blockReduceMax(lm);
    float es = 0.f, e[4];
    #pragma unroll
    for (int i = 0; i < 4; i++){ e[i] = expf(l[i] - M); es += e[i]; }
    float S = blockReduceSum(es);
    #pragma unroll
    for (int i = 0; i < 4; i++) out[b*1024 + t + i*256] = e[i] / S;
}
__global__ void k_centroid_part(const float* __restrict__ Lx, const float* __restrict__ w,
                                float* __restrict__ part){
    __shared__ float wsh[128];
    int ch = blockIdx.x, b = blockIdx.y;
    int t = threadIdx.x;                                  // 288, t<257 active
    for (int i = t; i < 128; i += blockDim.x) wsh[i] = w[(size_t)b*NSQ + ch*128 + i];
    __syncthreads();
    if (t < DP1){
        const float* base = Lx + ((size_t)b*NSQ + (size_t)ch*128)*DPAD + t;
        float acc = 0.f;
        for (int n = 0; n < 128; n++) acc += wsh[n] * base[(size_t)n*DPAD];
        part[(b*8 + ch)*DP1 + t] = acc;
    }
}
__global__ void k_centroid_fin(const float* __restrict__ part, float* __restrict__ co){
    __shared__ float t0sh;
    int b = blockIdx.x, t = threadIdx.x;                  // 288
    float acc = 0.f;
    if (t < DP1){
        #pragma unroll
        for (int c = 0; c < 8; c++) acc += part[(b*8 + c)*DP1 + t];
    }
    float sp = (t >= 1 && t < DP1) ? acc*acc : 0.f;
    float ssp = blockReduceSum(sp);
    if (t == 0) t0sh = acc;
    __syncthreads();
    float inner = -t0sh*t0sh + ssp;
    float den = sqrtf(fmaxf(fabsf(inner), 1e-8f));
    if (t < DP1) co[(size_t)b*DP1 + t] = acc / den;
}
__global__ void k_concat(const float* __restrict__ cs, const float* __restrict__ cc,
                         float* __restrict__ out){
    int b = blockIdx.x, t = threadIdx.x;                  // 256
    float t0s = cs[(size_t)b*DP1];
    float t0c = cc[(size_t)b*DP1];
    float sps = cs[(size_t)b*DP1 + 1 + t];
    float spc = cc[(size_t)b*DP1 + 1 + t];
    float ns  = sqrtf(fmaxf(blockReduceSum(sps*sps), 1e-15f));
    float ncv = sqrtf(fmaxf(blockReduceSum(spc*spc), 1e-15f));
    float zs = acoshf(fmaxf(t0s, 1.f + 1e-7f)) * sps / ns;
    float zc = acoshf(fmaxf(t0c, 1.f + 1e-7f)) * spc / ncv;
    float vn = sqrtf(fmaxf(blockReduceSum(zs*zs + zc*zc), 1e-15f));
    float f = sinhf(vn) / vn;
    float* o = out + (size_t)b*513;
    if (t == 0) o[0] = coshf(vn);
    o[1 + t]       = f * zs;
    o[1 + DD + t]  = f * zc;
}

// ----------------------------- launch ----------------------------------------------
extern "C" void kernel_launch(void* const* d_in, const int* in_sizes, int n_in,
                              void* d_out, int out_size)
{
    const float* sent = (const float*)d_in[0];
    const float* comm = (const float*)d_in[1];
    const float* WlW  = (const float*)d_in[2];
    const float* Wlb  = (const float*)d_in[3];
    const float* WcW  = (const float*)d_in[4];
    const float* Wcb  = (const float*)d_in[5];
    const float* WsW  = (const float*)d_in[6];
    const float* Wsb  = (const float*)d_in[7];
    const float* whs  = (const float*)d_in[8];
    const float* whc  = (const float*)d_in[9];
    float* out = (float*)d_out;
    (void)in_sizes; (void)n_in; (void)out_size;

    float2 *c1, *c1T;
    float *sT, *rl, *Ls, *Lc, *Llin, *Yt, *Wt, *rss, *css, *amx, *ass, *xnr, *xnc,
          *msc, *Hsa, *Hca, *HcaT, *Mxs, *MxcT, *lgs, *lgc, *cs, *cc, *part;
    __nv_bfloat16 *Lsh, *Llh, *Lbh, *LbTh, *HcaTh, *HsahT;
    cudaGetSymbolAddress((void**)&c1,  g_c1);
    cudaGetSymbolAddress((void**)&c1T, g_c1T);
    cudaGetSymbolAddress((void**)&sT,  g_sT);
    cudaGetSymbolAddress((void**)&rl,  g_real);
    cudaGetSymbolAddress((void**)&Ls,  g_Ls);
    cudaGetSymbolAddress((void**)&Lc,  g_Lc);
    cudaGetSymbolAddress((void**)&Llin,g_Llin);
    cudaGetSymbolAddress((void**)&Yt,  g_Yt);
    cudaGetSymbolAddress((void**)&Wt,  g_Wt);
    cudaGetSymbolAddress((void**)&Lsh, g_Lsh);
    cudaGetSymbolAddress((void**)&Llh, g_Llh);
    cudaGetSymbolAddress((void**)&Lbh, g_Lbh);
    cudaGetSymbolAddress((void**)&LbTh,g_LbTh);
    cudaGetSymbolAddress((void**)&HcaTh,g_HcaTh);
    cudaGetSymbolAddress((void**)&HsahT,g_HsahT);
    cudaGetSymbolAddress((void**)&rss, g_rss);
    cudaGetSymbolAddress((void**)&css, g_css);
    cudaGetSymbolAddress((void**)&amx, g_amx);
    cudaGetSymbolAddress((void**)&ass, g_ass);
    cudaGetSymbolAddress((void**)&xnr, g_xnr);
    cudaGetSymbolAddress((void**)&xnc, g_xnc);
    cudaGetSymbolAddress((void**)&msc, g_msc);
    cudaGetSymbolAddress((void**)&Hsa, g_Hsa);
    cudaGetSymbolAddress((void**)&Hca, g_Hca);
    cudaGetSymbolAddress((void**)&HcaT,g_HcaT);
    cudaGetSymbolAddress((void**)&Mxs, g_Mxs);
    cudaGetSymbolAddress((void**)&MxcT,g_MxcT);
    cudaGetSymbolAddress((void**)&lgs, g_lgs);
    cudaGetSymbolAddress((void**)&lgc, g_lgc);
    cudaGetSymbolAddress((void**)&cs,  g_cs);
    cudaGetSymbolAddress((void**)&cc,  g_cc);
    cudaGetSymbolAddress((void**)&part,g_part);

    const int AS_OFF = BB*513;             // 16416
    const int AC_OFF = AS_OFF + BB*NSQ;    // 49184

    k_setup<<<32 + DP1 + 2*KP1, 1024>>>(WlW, WsW, WcW, Wt, rss, css, amx, ass);

    // ---- dual-branch FFT2 (stage-0 fused, Hermitian-compact) + euclid_to_lorentz ----
    k_fft256<<<2*BB*NSQ/4, dim3(64,4)>>>(sent, comm, c1);
    k_transpose_ch<<<dim3(5, NSQ/32, 2*BB), dim3(32,8)>>>(c1, c1T);
    k_fft1024<<<2*BB*DH, 256>>>(c1T, sT);
    k_transpose_fh<<<dim3(5, NSQ/32, 2*BB), dim3(32,8)>>>(sT, rl);
    k_e2l<<<2*BB*NSQ, 256>>>(rl, Ls, Lc, Lsh);

    // ---- linear layers (tf32; dead time-column skipped) ----
    k_pgemm<0,1,1,0><<<dim3(2,256,1),256>>>(Lc, Wt + (size_t)1*DPAD, Wlb + 1, Llin + 1,
        BB*NCQ, 256, DP1, DPAD, DPAD, DPAD, 0, 0, 0, nullptr, nullptr);
    k_fix_time<<<BB*NCQ, 256>>>(Llin, Llh);

    k_pgemm<0,1,1,0><<<dim3(1,256,1),256>>>(Ls, Wt + (size_t)385*DPAD, Wsb + 1, Yt,
        BB*NSQ, KKW, DP1, DPAD, DPAD, KKW, 0, 0, 0, nullptr, nullptr);
    k_poincare<<<BB*NSQ/8, 256>>>(Yt, Hsa);

    k_pgemm<0,1,1,0><<<dim3(1,256,1),256>>>(Lc, Wt + (size_t)641*DPAD, Wcb + 1, Yt,
        BB*NCQ, KKW, DP1, DPAD, DPAD, KKW, 0, 0, 0, nullptr, nullptr);
    k_poincare<<<BB*NCQ/8, 256>>>(Yt, Hca);

    // ---- big einsum (bf16) + lorentz_act + fused norms, coalesced dual bf16 out ----
    k_bgemm<2><<<dim3(8,8,BB),256>>>(Lsh, Llh, nullptr, Lbh, LbTh,
        NSQ, NCQ, DP1, DPAD, DPAD, NCQ, NSQ,
        (long)NSQ*DPAD, (long)NCQ*DPAD, 0, (long)NSQ*NCQ, rss, css);
    k_nfin<<<BB, 1024>>>(rss, css, Lbh, LbTh, xnr, xnc);

    // ---- transposes for mobius operands ----
    k_tbk2<<<dim3(4, 32, 2*BB), dim3(32,8)>>>(Hca, Hsa, HcaT, HcaTh, HsahT);

    // ---- mobius_matvec GEMMs (bf16) ----
    k_bgemm<0><<<dim3(1,8,BB),256>>>(Lbh, HcaTh, Mxs, nullptr, nullptr,
        NSQ, KKW, NCQ, NCQ, NCQ, KKW, 0,
        (long)NSQ*NCQ, (long)KKW*NCQ, (long)NSQ*KKW, 0, nullptr, nullptr);
    k_bgemm<0><<<dim3(8,1,BB),256>>>(HsahT, LbTh, MxcT, nullptr, nullptr,
        KKW, NCQ, NSQ, NSQ, NSQ, NCQ, 0,
        (long)KKW*NSQ, (long)NCQ*NSQ, (long)KKW*NCQ, 0, nullptr, nullptr);
    k_mscale<<<dim3(NCQ/256, BB), 256>>>(MxcT, xnc, msc);

    // ---- mobius_add + gelu pipelines + attention logits ----
    k_hs<<<BB*NSQ/8, 256>>>(Hsa, Mxs, xnr, whs, lgs);
    k_hc<<<BB*KKW, 256>>>(HcaT, MxcT, msc, whc, amx, ass);
    k_acfin<<<BB, 1024>>>(amx, ass, lgc);

    // ---- softmaxes straight into output ----
    k_softmax<<<BB, 256>>>(lgs, out + AS_OFF);
    k_softmax<<<BB, 256>>>(lgc, out + AC_OFF);

    // ---- centroids + concat ----
    k_centroid_part<<<dim3(8,BB), 288>>>(Ls, out + AS_OFF, part);
    k_centroid_fin<<<BB, 288>>>(part, cs);
    k_centroid_part<<<dim3(8,BB), 288>>>(Lc, out + AC_OFF, part);
    k_centroid_fin<<<BB, 288>>>(part, cc);
    k_concat<<<BB, 256>>>(cs, cc, out);
}

// round 13
// speedup vs baseline: 1.1876x; 1.0443x over previous
#include <cuda_runtime.h>
#include <cuda_bf16.h>
#include <math.h>
#include <stdint.h>

#define BB  32
#define NSQ 1024
#define NCQ 1024
#define DD  256
#define DP1 257
#define DPAD 272
#define KKW 128
#define KP1 129
#define DH  129   // Hermitian-reduced column count

// ----------------------------- scratch (static device globals; no runtime alloc) ---
static __device__ float2 g_c1 [(size_t)2*BB*NSQ*DH];
static __device__ float2 g_c1T[(size_t)2*BB*DH*NSQ];
static __device__ float  g_sT [(size_t)2*BB*DH*NSQ];
static __device__ float  g_real[(size_t)2*BB*NSQ*DH];
static __device__ float  g_Ls [(size_t)BB*NSQ*DPAD];
static __device__ float  g_Lc [(size_t)BB*NCQ*DPAD];
static __device__ float  g_Llin[(size_t)BB*NCQ*DPAD];
static __device__ float  g_Yt [(size_t)BB*NSQ*KKW];
static __device__ __align__(16) __nv_bfloat16 g_Wth[(size_t)896*DPAD]; // Wl@0,Ws@384,Wc@640 (rows)
static __device__ __align__(16) __nv_bfloat16 g_Lsh [(size_t)BB*NSQ*DPAD];
static __device__ __align__(16) __nv_bfloat16 g_Lch [(size_t)BB*NCQ*DPAD];
static __device__ __align__(16) __nv_bfloat16 g_Llh [(size_t)BB*NCQ*DPAD];
static __device__ __align__(16) __nv_bfloat16 g_Lbh [(size_t)BB*NSQ*NCQ];
static __device__ __align__(16) __nv_bfloat16 g_LbTh[(size_t)BB*NCQ*NSQ];
static __device__ __align__(16) __nv_bfloat16 g_HcaTh[(size_t)BB*KKW*NCQ];
static __device__ __align__(16) __nv_bfloat16 g_HsahT[(size_t)BB*KKW*NSQ];
static __device__ float  g_rss[BB*NSQ];
static __device__ float  g_css[BB*NCQ];
static __device__ float  g_amx[BB*NCQ];
static __device__ float  g_ass[BB*NCQ];
static __device__ float  g_xnr[BB*NSQ];
static __device__ float  g_xnc[BB*NCQ];
static __device__ float  g_msc[BB*NCQ];
static __device__ float  g_Hsa[(size_t)BB*NSQ*KKW];
static __device__ float  g_Hca[(size_t)BB*NCQ*KKW];
static __device__ float  g_HcaT[(size_t)BB*KKW*NCQ];
static __device__ float  g_Mxs[(size_t)BB*NSQ*KKW];
static __device__ float  g_MxcT[(size_t)BB*KKW*NCQ];
static __device__ float  g_lgs[BB*NSQ];
static __device__ float  g_cs [BB*DP1];
static __device__ float  g_cc [BB*DP1];
static __device__ float  g_part[2*BB*8*DP1];
static __device__ float2 g_tw1024[1024];
static __device__ float2 g_tw256[256];

// ----------------------------- helpers ---------------------------------------------
__device__ __forceinline__ float atanhc(float x){
    x = fminf(fmaxf(x, -1.f + 1e-5f), 1.f - 1e-5f);
    return 0.5f * (log1pf(x) - log1pf(-x));
}
__device__ __forceinline__ float gelu_exact(float v){
    return 0.5f * v * (1.f + erff(v * 0.70710678118654752f));
}
__device__ __forceinline__ float2 cmul(float2 a, float2 b){
    return make_float2(a.x*b.x - a.y*b.y, a.x*b.y + a.y*b.x);
}
__device__ __forceinline__ float2 cadd(float2 a, float2 b){ return make_float2(a.x+b.x, a.y+b.y); }
__device__ __forceinline__ float2 csub(float2 a, float2 b){ return make_float2(a.x-b.x, a.y-b.y); }

__device__ __forceinline__ float wsum(float v){
    #pragma unroll
    for (int o = 16; o; o >>= 1) v += __shfl_xor_sync(0xffffffffu, v, o);
    return v;
}
__device__ __forceinline__ float blockReduceSum(float v){
    __shared__ float sh[32];
    #pragma unroll
    for (int o = 16; o; o >>= 1) v += __shfl_down_sync(0xffffffffu, v, o);
    int lane = threadIdx.x & 31, w = threadIdx.x >> 5;
    if (lane == 0) sh[w] = v;
    __syncthreads();
    int nw = (blockDim.x + 31) >> 5;
    v = (threadIdx.x < (unsigned)nw) ? sh[threadIdx.x] : 0.f;
    if (w == 0){
        #pragma unroll
        for (int o = 16; o; o >>= 1) v += __shfl_down_sync(0xffffffffu, v, o);
        if (lane == 0) sh[0] = v;
    }
    __syncthreads();
    float r = sh[0];
    __syncthreads();
    return r;
}
__device__ __forceinline__ void blockReduceSum3(float& a, float& b, float& c){
    __shared__ float sh3[32][3];
    #pragma unroll
    for (int o = 16; o; o >>= 1){
        a += __shfl_down_sync(0xffffffffu, a, o);
        b += __shfl_down_sync(0xffffffffu, b, o);
        c += __shfl_down_sync(0xffffffffu, c, o);
    }
    int lane = threadIdx.x & 31, w = threadIdx.x >> 5;
    if (lane == 0){ sh3[w][0] = a; sh3[w][1] = b; sh3[w][2] = c; }
    __syncthreads();
    int nw = (blockDim.x + 31) >> 5;
    a = (threadIdx.x < (unsigned)nw) ? sh3[threadIdx.x][0] : 0.f;
    b = (threadIdx.x < (unsigned)nw) ? sh3[threadIdx.x][1] : 0.f;
    c = (threadIdx.x < (unsigned)nw) ? sh3[threadIdx.x][2] : 0.f;
    if (w == 0){
        #pragma unroll
        for (int o = 16; o; o >>= 1){
            a += __shfl_down_sync(0xffffffffu, a, o);
            b += __shfl_down_sync(0xffffffffu, b, o);
            c += __shfl_down_sync(0xffffffffu, c, o);
        }
        if (lane == 0){ sh3[0][0] = a; sh3[0][1] = b; sh3[0][2] = c; }
    }
    __syncthreads();
    a = sh3[0][0]; b = sh3[0][1]; c = sh3[0][2];
    __syncthreads();
}
__device__ __forceinline__ float blockReduceMax(float v){
    __shared__ float sh[32];
    #pragma unroll
    for (int o = 16; o; o >>= 1) v = fmaxf(v, __shfl_down_sync(0xffffffffu, v, o));
    int lane = threadIdx.x & 31, w = threadIdx.x >> 5;
    if (lane == 0) sh[w] = v;
    __syncthreads();
    int nw = (blockDim.x + 31) >> 5;
    v = (threadIdx.x < (unsigned)nw) ? sh[threadIdx.x] : -3.4e38f;
    if (w == 0){
        #pragma unroll
        for (int o = 16; o; o >>= 1) v = fmaxf(v, __shfl_down_sync(0xffffffffu, v, o));
        if (lane == 0) sh[0] = v;
    }
    __syncthreads();
    float r = sh[0];
    __syncthreads();
    return r;
}
__device__ __forceinline__ uint32_t f2tf32(float v){
    uint32_t r;
    asm("cvt.rna.tf32.f32 %0, %1;" : "=r"(r) : "f"(v));
    return r;
}
__device__ __forceinline__ float tf32r(float v){ return __uint_as_float(f2tf32(v)); }
__device__ __forceinline__ void mma_bf16(float* c, const uint32_t* a, const uint32_t* b){
    asm volatile("mma.sync.aligned.m16n8k16.row.col.f32.bf16.bf16.f32 "
        "{%0,%1,%2,%3}, {%4,%5,%6,%7}, {%8,%9}, {%0,%1,%2,%3};"
        : "+f"(c[0]), "+f"(c[1]), "+f"(c[2]), "+f"(c[3])
        : "r"(a[0]), "r"(a[1]), "r"(a[2]), "r"(a[3]), "r"(b[0]), "r"(b[1]));
}
__device__ __forceinline__ void cpa16(uint32_t dsh, const void* src){
    asm volatile("cp.async.ca.shared.global [%0], [%1], 16;" :: "r"(dsh), "l"(src));
}
#define CP_COMMIT() asm volatile("cp.async.commit_group;" ::: "memory")
#define CP_WAIT1()  asm volatile("cp.async.wait_group 1;" ::: "memory")
#define CP_WAIT0()  asm volatile("cp.async.wait_group 0;" ::: "memory")

// ----------------------------- merged setup kernel ---------------------------------
// blocks 0..31: zero accumulators (+block 0 fills twiddles)
// blocks 32..546: bf16 padded weight copies (pad rows/cols stay zero: static init)
__global__ void k_setup(const float* __restrict__ Wl, const float* __restrict__ Ws,
                        const float* __restrict__ Wc,
                        float* __restrict__ a, float* __restrict__ b,
                        float* __restrict__ c, float* __restrict__ d){
    int blk = blockIdx.x;
    int t = threadIdx.x;                       // 1024
    if (blk < 32){
        int i = blk*1024 + t;
        a[i] = 0.f; b[i] = 0.f; c[i] = 0.f; d[i] = 0.f;
        if (blk == 0){
            double ang = -6.283185307179586476925287 * (double)t / 1024.0;
            g_tw1024[t] = make_float2((float)cos(ang), (float)sin(ang));
            if (t < 256){
                double a2 = -6.283185307179586476925287 * (double)t / 256.0;
                g_tw256[t] = make_float2((float)cos(a2), (float)sin(a2));
            }
        }
        return;
    }
    int r = blk - 32;                          // 0..514
    if (t >= DP1) return;
    const float* src; __nv_bfloat16* dst;
    if (r < DP1){ src = Wl + (size_t)r*DP1; dst = g_Wth + (size_t)r*DPAD; }
    else if (r < DP1 + KP1){ int rr = r - DP1; src = Ws + (size_t)rr*DP1; dst = g_Wth + (size_t)(384+rr)*DPAD; }
    else { int rr = r - DP1 - KP1; src = Wc + (size_t)rr*DP1; dst = g_Wth + (size_t)(640+rr)*DPAD; }
    dst[t] = __float2bfloat16_rn(src[t]);
}

// ----------------------------- radix-4 Stockham FFT kernels ------------------------
__global__ void k_fft256(const float* __restrict__ sent, const float* __restrict__ comm,
                         float2* __restrict__ out){
    __shared__ float2 bufA[4][256];
    __shared__ float2 bufB[4][256];
    __shared__ float2 tws[256];
    __shared__ float  rsum[4][2];
    int tx = threadIdx.x;                      // 64
    int ty = threadIdx.y;                      // 4
    int tid = ty*64 + tx;
    size_t row = (size_t)blockIdx.x*4 + ty;
    bool do_log = row >= (size_t)BB*NSQ;
    const float* x = do_log ? (comm + (row - (size_t)BB*NSQ)*256) : (sent + row*256);
    tws[tid] = g_tw256[tid];

    float v0 = x[tx], v1 = x[tx+64], v2 = x[tx+128], v3 = x[tx+192];
    float ss = v0*v0 + v1*v1 + v2*v2 + v3*v3;
    #pragma unroll
    for (int o = 16; o; o >>= 1) ss += __shfl_down_sync(0xffffffffu, ss, o);
    if ((tx & 31) == 0) rsum[ty][tx >> 5] = ss;
    __syncthreads();
    if (do_log){
        float tot = rsum[ty][0] + rsum[ty][1];
        float yn = sqrtf(fmaxf(tot, 1e-15f));
        float f = atanhc(yn) / yn;
        v0 *= f; v1 *= f; v2 *= f; v3 *= f;
    }
    {
        float pa = v0 + v2, pb = v0 - v2;
        float pc = v1 + v3, pd = v1 - v3;
        bufA[ty][4*tx]     = make_float2(pa + pc, 0.f);
        bufA[ty][4*tx + 1] = make_float2(pb, -pd);
        bufA[ty][4*tx + 2] = make_float2(pa - pc, 0.f);
        bufA[ty][4*tx + 3] = make_float2(pb,  pd);
    }
    __syncthreads();

    float2* X = &bufA[ty][0];
    float2* Y = &bufB[ty][0];
    #pragma unroll
    for (int s = 1; s < 4; s++){
        int Ns = 1 << (2*s);
        int p = tx & (Ns - 1);
        float2 w1 = tws[p * (64/Ns)];
        float2 w2 = cmul(w1, w1);
        float2 w3 = cmul(w2, w1);
        float2 a0 = X[tx];
        float2 a1 = cmul(X[tx + 64],  w1);
        float2 a2 = cmul(X[tx + 128], w2);
        float2 a3 = cmul(X[tx + 192], w3);
        float2 pa = cadd(a0, a2), pb = csub(a0, a2);
        float2 pc = cadd(a1, a3), pd = csub(a1, a3);
        float2 dneg = make_float2(pd.y, -pd.x);
        float2 dpos = make_float2(-pd.y, pd.x);
        int idxD = ((tx >> (2*s)) << (2*s + 2)) + p;
        Y[idxD]          = cadd(pa, pc);
        Y[idxD + Ns]     = cadd(pb, dneg);
        Y[idxD + 2*Ns]   = csub(pa, pc);
        Y[idxD + 3*Ns]   = cadd(pb, dpos);
        __syncthreads();
        float2* tmp = X; X = Y; Y = tmp;
    }
    out[row*DH + tx]      = X[tx];
    out[row*DH + tx + 64] = X[tx + 64];
    if (tx == 0) out[row*DH + 128] = X[128];
}

__global__ void k_fft1024(const float2* __restrict__ in, float* __restrict__ outr){
    __shared__ float2 bufA[1024];
    __shared__ float2 bufB[1024];
    __shared__ float2 tws[1024];
    int t = threadIdx.x;                       // 256
    size_t row = blockIdx.x;
    const float2* src = in + row*1024;
    float2 a0 = src[t], a1 = src[t+256], a2 = src[t+512], a3 = src[t+768];
    #pragma unroll
    for (int i = 0; i < 4; i++)
        tws[t + i*256] = g_tw1024[t + i*256];
    {
        float2 pa = cadd(a0, a2), pb = csub(a0, a2);
        float2 pc = cadd(a1, a3), pd = csub(a1, a3);
        bufA[4*t]     = cadd(pa, pc);
        bufA[4*t + 1] = cadd(pb, make_float2(pd.y, -pd.x));
        bufA[4*t + 2] = csub(pa, pc);
        bufA[4*t + 3] = cadd(pb, make_float2(-pd.y, pd.x));
    }
    __syncthreads();
    float2* X = bufA;
    float2* Y = bufB;
    #pragma unroll
    for (int s = 1; s < 5; s++){
        int Ns = 1 << (2*s);
        int p = t & (Ns - 1);
        float2 w1 = tws[p * (256/Ns)];
        float2 w2 = cmul(w1, w1);
        float2 w3 = cmul(w2, w1);
        float2 b0 = X[t];
        float2 b1 = cmul(X[t + 256], w1);
        float2 b2 = cmul(X[t + 512], w2);
        float2 b3 = cmul(X[t + 768], w3);
        float2 pa = cadd(b0, b2), pb = csub(b0, b2);
        float2 pc = cadd(b1, b3), pd = csub(b1, b3);
        float2 dneg = make_float2(pd.y, -pd.x);
        float2 dpos = make_float2(-pd.y, pd.x);
        int idxD = ((t >> (2*s)) << (2*s + 2)) + p;
        Y[idxD]        = cadd(pa, pc);
        Y[idxD + Ns]   = cadd(pb, dneg);
        Y[idxD + 2*Ns] = csub(pa, pc);
        Y[idxD + 3*Ns] = cadd(pb, dpos);
        __syncthreads();
        float2* tmp = X; X = Y; Y = tmp;
    }
    #pragma unroll
    for (int i = 0; i < 4; i++)
        outr[row*1024 + t + i*256] = X[t + i*256].x;
}

__global__ void k_transpose_ch(const float2* __restrict__ in, float2* __restrict__ out){
    __shared__ float2 tile[32][33];
    int b = blockIdx.z;
    int c0 = blockIdx.x*32, r0 = blockIdx.y*32;
    const float2* src = in + (size_t)b*NSQ*DH;
    for (int i = threadIdx.y; i < 32; i += 8){
        int d = c0 + threadIdx.x;
        tile[i][threadIdx.x] = (d < DH) ? src[(size_t)(r0+i)*DH + d]
                                        : make_float2(0.f, 0.f);
    }
    __syncthreads();
    float2* dst = out + (size_t)b*DH*NSQ;
    for (int i = threadIdx.y; i < 32; i += 8){
        int d = c0 + i;
        if (d < DH) dst[(size_t)d*NSQ + r0 + threadIdx.x] = tile[threadIdx.x][i];
    }
}
__global__ void k_transpose_fh(const float* __restrict__ in, float* __restrict__ out){
    __shared__ float tile[32][33];
    int b = blockIdx.z;
    int d0 = blockIdx.x*32, n0 = blockIdx.y*32;
    const float* src = in + (size_t)b*DH*NSQ;
    for (int i = threadIdx.y; i < 32; i += 8){
        int d = d0 + i;
        tile[i][threadIdx.x] = (d < DH) ? src[(size_t)d*NSQ + n0 + threadIdx.x] : 0.f;
    }
    __syncthreads();
    float* dst = out + (size_t)b*NSQ*DH;
    int d = d0 + threadIdx.x;
    if (d < DH)
        for (int i = threadIdx.y; i < 32; i += 8)
            dst[(size_t)(n0+i)*DH + d] = tile[threadIdx.x][i];
}

// fused Hermitian mirror + euclid_to_lorentz; fp32 (centroid) + bf16 (GEMM operands)
__global__ void k_e2l(const float* __restrict__ rl, float* __restrict__ Ls,
                      float* __restrict__ Lc, __nv_bfloat16* __restrict__ Lsh,
                      __nv_bfloat16* __restrict__ Lch){
    size_t row = blockIdx.x;                   // 0 .. 2*BB*NSQ-1
    int t = threadIdx.x;                       // 256
    size_t bb = row >> 10;
    int n = (int)(row & 1023);
    float v;
    if (t < DH){
        v = rl[(bb*NSQ + n)*DH + t];
    } else {
        int srcn = (1024 - n) & 1023;
        v = rl[(bb*NSQ + srcn)*DH + (256 - t)];
    }
    float ss = blockReduceSum(v*v);
    float xn = sqrtf(fmaxf(ss, 1e-15f)) + 1e-5f;
    float scl = fminf(1.f, 2.0f / xn);
    v *= scl;
    float vn = sqrtf(fmaxf(ss*scl*scl, 1e-15f));
    float f = sinhf(vn) / vn;
    bool isS = bb < BB;
    float* out = isS ? Ls : Lc;
    __nv_bfloat16* outh = isS ? Lsh : Lch;
    size_t orow = isS ? row : row - (size_t)BB*NSQ;
    float tv = coshf(vn), sv = f * v;
    if (t == 0){ out[orow*DPAD] = tv; outh[orow*DPAD] = __float2bfloat16_rn(tv); }
    out[orow*DPAD + 1 + t] = sv;
    outh[orow*DPAD + 1 + t] = __float2bfloat16_rn(sv);
    if (t < DPAD - DP1) out[orow*DPAD + DP1 + t] = 0.f;
}

// --------- bf16 GEMM (m16n8k16): A[m][k], B[n][k] --------------------------------
//  MODE 0: plain fp32 C    MODE 1: fp32 C + bias[n]    MODE 2: einsum epilogue
template<int MODE>
__global__ void k_bgemm(const __nv_bfloat16* __restrict__ A,
                        const __nv_bfloat16* __restrict__ Bm,
                        const float* __restrict__ bias,
                        float* __restrict__ C,
                        __nv_bfloat16* __restrict__ Cb, __nv_bfloat16* __restrict__ CbT,
                        int M, int N, int Klen, int lda, int ldb, int ldc, int ldt,
                        long sA, long sB, long sC, long sCb,
                        float* __restrict__ rss, float* __restrict__ css)
{
    __shared__ __align__(16) char smemraw[49152];   // As(12KB)+Bs(12KB) / tile(34KB)
    __nv_bfloat16* AsBuf = reinterpret_cast<__nv_bfloat16*>(smemraw);
    __nv_bfloat16* BsBuf = reinterpret_cast<__nv_bfloat16*>(smemraw + 24576);

    int bz = blockIdx.z;
    A  += (size_t)bz * sA;
    Bm += (size_t)bz * sB;
    if (MODE != 2) C += (size_t)bz * sC;
    else { Cb += (size_t)bz * sCb; CbT += (size_t)bz * sCb; }
    int bm = blockIdx.y * 128, bn = blockIdx.x * 128;
    int tid = threadIdx.x;
    int wid = tid >> 5, lane = tid & 31;
    int wm = (wid >> 2) * 64;
    int wn = (wid & 3) * 32;
    int g = lane >> 2, tg = lane & 3;
    int KT = (Klen + 15) >> 4;

    uint32_t asBase = (uint32_t)__cvta_generic_to_shared(AsBuf);
    uint32_t bsBase = (uint32_t)__cvta_generic_to_shared(BsBuf);

    auto issueA = [&](int st, int k0){
        int mm = tid >> 1, c = tid & 1;
        cpa16(asBase + (uint32_t)(st*6144) + (mm*24 + c*8)*2,
              A + (size_t)(bm+mm)*lda + k0 + c*8);
    };
    auto issueB = [&](int st, int k0){
        int nn = tid >> 1, c = tid & 1;
        cpa16(bsBase + (uint32_t)(st*6144) + (nn*24 + c*8)*2,
              Bm + (size_t)(bn+nn)*ldb + k0 + c*8);
    };

    float acc[4][4][4];
    #pragma unroll
    for (int mi = 0; mi < 4; mi++)
        #pragma unroll
        for (int ni = 0; ni < 4; ni++)
            #pragma unroll
            for (int r = 0; r < 4; r++) acc[mi][ni][r] = 0.f;

    issueA(0, 0); issueB(0, 0);
    CP_COMMIT();

    for (int kt = 0; kt < KT; kt++){
        int st = kt & 1;
        if (kt + 1 < KT){
            issueA(st ^ 1, (kt+1)*16);
            issueB(st ^ 1, (kt+1)*16);
            CP_COMMIT();
            CP_WAIT1();
        } else {
            CP_WAIT0();
        }
        __syncthreads();

        // stage st occupies ELEMENT offset st*3072 (== byte offset st*6144)
        const uint32_t* pA = reinterpret_cast<const uint32_t*>(AsBuf + st*3072);
        const uint32_t* pB = reinterpret_cast<const uint32_t*>(BsBuf + st*3072);
        uint32_t bhf[4][2];
        #pragma unroll
        for (int ni = 0; ni < 4; ni++){
            int n = wn + ni*8 + g;
            bhf[ni][0] = pB[n*12 + tg];
            bhf[ni][1] = pB[n*12 + tg + 4];
        }
        #pragma unroll
        for (int mi = 0; mi < 4; mi++){
            int m = wm + mi*16;
            uint32_t ahf[4];
            ahf[0] = pA[(m+g)*12   + tg];
            ahf[1] = pA[(m+g+8)*12 + tg];
            ahf[2] = pA[(m+g)*12   + tg + 4];
            ahf[3] = pA[(m+g+8)*12 + tg + 4];
            #pragma unroll
            for (int ni = 0; ni < 4; ni++)
                mma_bf16(acc[mi][ni], ahf, bhf[ni]);
        }
        __syncthreads();
    }

    if (MODE != 2){
        #pragma unroll
        for (int mi = 0; mi < 4; mi++)
            #pragma unroll
            for (int ni = 0; ni < 4; ni++){
                int col = bn + wn + ni*8 + 2*tg;
                #pragma unroll
                for (int r = 0; r < 4; r++){
                    int gm = bm + wm + mi*16 + g + (r >= 2 ? 8 : 0);
                    int gn = col + (r & 1);
                    if (gn >= N) continue;
                    float v = acc[mi][ni][r];
                    if (MODE == 1) v += bias[gn];
                    C[(size_t)gm*ldc + gn] = v;
                }
            }
    } else {
        // gelu (global col0 -> 0) + SSQ atomics, then smem-staged coalesced stores
        #pragma unroll
        for (int mi = 0; mi < 4; mi++)
            #pragma unroll
            for (int ni = 0; ni < 4; ni++){
                int col = bn + wn + ni*8 + 2*tg;
                #pragma unroll
                for (int r = 0; r < 4; r++){
                    int gn = col + (r & 1);
                    acc[mi][ni][r] = (gn == 0) ? 0.f : gelu_exact(acc[mi][ni][r]);
                }
            }
        #pragma unroll
        for (int mi = 0; mi < 4; mi++){
            #pragma unroll
            for (int half = 0; half < 2; half++){
                float rp = 0.f;
                #pragma unroll
                for (int ni = 0; ni < 4; ni++){
                    float a0 = acc[mi][ni][half*2], a1 = acc[mi][ni][half*2+1];
                    rp += a0*a0 + a1*a1;
                }
                rp += __shfl_down_sync(0xffffffffu, rp, 1);
                rp += __shfl_down_sync(0xffffffffu, rp, 2);
                if (tg == 0)
                    atomicAdd(&rss[(size_t)bz*1024 + bm + wm + mi*16 + g + half*8], rp);
            }
        }
        #pragma unroll
        for (int ni = 0; ni < 4; ni++){
            #pragma unroll
            for (int cb = 0; cb < 2; cb++){
                float cp = 0.f;
                #pragma unroll
                for (int mi = 0; mi < 4; mi++){
                    float a0 = acc[mi][ni][cb], a1 = acc[mi][ni][2+cb];
                    cp += a0*a0 + a1*a1;
                }
                cp += __shfl_down_sync(0xffffffffu, cp, 4);
                cp += __shfl_down_sync(0xffffffffu, cp, 8);
                cp += __shfl_down_sync(0xffffffffu, cp, 16);
                if (g == 0)
                    atomicAdd(&css[(size_t)bz*1024 + bn + wn + ni*8 + 2*tg + cb], cp);
            }
        }
        __syncthreads();
        constexpr int TS = 136;                 // padded row stride in bf16
        __nv_bfloat16* tile = reinterpret_cast<__nv_bfloat16*>(smemraw);
        #pragma unroll
        for (int mi = 0; mi < 4; mi++)
            #pragma unroll
            for (int ni = 0; ni < 4; ni++){
                int ln = wn + ni*8 + 2*tg;
                #pragma unroll
                for (int r = 0; r < 4; r++){
                    int lm = wm + mi*16 + g + (r >= 2 ? 8 : 0);
                    tile[lm*TS + ln + (r & 1)] = __float2bfloat16_rn(acc[mi][ni][r]);
                }
            }
        __syncthreads();
        {
            int row = tid >> 1, half = tid & 1;
            const uint4* srcv = reinterpret_cast<const uint4*>(tile + row*TS + half*64);
            uint4* dstv = reinterpret_cast<uint4*>(Cb + (size_t)(bm+row)*ldc + bn + half*64);
            #pragma unroll
            for (int i = 0; i < 8; i++) dstv[i] = srcv[i];
        }
        {
            int coln = tid >> 1, halfm = tid & 1;
            #pragma unroll
            for (int c8 = 0; c8 < 8; c8++){
                __nv_bfloat16 tmp[8];
                #pragma unroll
                for (int j = 0; j < 8; j++)
                    tmp[j] = tile[(halfm*64 + c8*8 + j)*TS + coln];
                *reinterpret_cast<uint4*>(CbT + (size_t)(bn+coln)*ldt + bm + halfm*64 + c8*8)
                    = *reinterpret_cast<const uint4*>(tmp);
            }
        }
    }
}

// ----------------------------- row-wise kernels ------------------------------------
// read Llin fp32, write full bf16 row (space + time) of Llh
__global__ void k_fix_time(const float* __restrict__ Llin, __nv_bfloat16* __restrict__ Llh){
    size_t row = blockIdx.x;
    int t = threadIdx.x;                                  // 256
    float sp = Llin[row*DPAD + 1 + t];
    float S = blockReduceSum(sp*sp);
    Llh[row*DPAD + 1 + t] = __float2bfloat16_rn(sp);
    if (t == 0) Llh[row*DPAD] = __float2bfloat16_rn(sqrtf(S + 1.f));
}
// warp-per-row poincare on 128-wide space rows
__global__ void k_poincare(const float* __restrict__ Y, float* __restrict__ out){
    size_t row = (size_t)blockIdx.x*8 + (threadIdx.x >> 5);
    int lane = threadIdx.x & 31;
    const float* y = Y + row*KKW;
    float v[4], s = 0.f;
    #pragma unroll
    for (int i = 0; i < 4; i++){ v[i] = y[lane + i*32]; s += v[i]*v[i]; }
    s = wsum(s);
    float inv = 1.f / (sqrtf(s + 1.f) + 1.f);
    float* o = out + row*KKW;
    #pragma unroll
    for (int i = 0; i < 4; i++) o[lane + i*32] = v[i] * inv;
}
// finalize norms; write bf16 time entries into Lbh (col0) and LbTh (row0)
__global__ void k_nfin(const float* __restrict__ rss, const float* __restrict__ css,
                       __nv_bfloat16* __restrict__ Lbh, __nv_bfloat16* __restrict__ LbTh,
                       float* __restrict__ xnr, float* __restrict__ xnc){
    int b = blockIdx.x, n = threadIdx.x;                  // 1024
    float S = rss[b*1024 + n];
    float tv = sqrtf(S + 1.f);
    Lbh[((size_t)b*1024 + n)*1024] = __float2bfloat16_rn(tv);
    LbTh[(size_t)b*1024*1024 + n]  = __float2bfloat16_rn(tv);
    xnr[b*1024 + n] = sqrtf(fmaxf(2.f*S + 1.f, 1e-15f));
    float ts = blockReduceSum(S + 1.f);
    float c = css[b*1024 + n];
    xnc[b*1024 + n] = (n == 0) ? sqrtf(ts) : sqrtf(fmaxf(c, 1e-15f));
}
// mobius_matvec scale from MxcT
__global__ void k_mscale(const float* __restrict__ MxT, const float* __restrict__ xna,
                         float* __restrict__ sc){
    int b = blockIdx.y;
    int m = blockIdx.x*256 + threadIdx.x;
    const float* base = MxT + (size_t)b*KKW*NCQ + m;
    float ss = 0.f;
    #pragma unroll 4
    for (int j = 0; j < KKW; j++){
        float v = base[(size_t)j*NCQ];
        ss += v*v;
    }
    float mxn = sqrtf(fmaxf(ss, 1e-15f));
    float xn = xna[b*NCQ + m];
    sc[b*NCQ + m] = tanhf(mxn / xn * atanhc(xn)) / mxn;
}
// warp-per-row fused Hs pipeline
__global__ void k_hs(const float* __restrict__ Hsa, const float* __restrict__ MxRaw,
                     const float* __restrict__ xnr,
                     const float* __restrict__ whs, float* __restrict__ lg){
    size_t row = (size_t)blockIdx.x*8 + (threadIdx.x >> 5);
    int lane = threadIdx.x & 31;
    const float* my = MxRaw + row*KKW;
    const float* hx = Hsa + row*KKW;
    float yr[4], x[4];
    float mm = 0.f;
    #pragma unroll
    for (int i = 0; i < 4; i++){
        yr[i] = my[lane + i*32];
        x[i]  = hx[lane + i*32];
        mm += yr[i]*yr[i];
    }
    mm = wsum(mm);
    float mxn = sqrtf(fmaxf(mm, 1e-15f));
    float xnb = xnr[row];
    float fac = tanhf(mxn / xnb * atanhc(xnb)) / mxn;

    float xy = 0.f, x2 = 0.f, y2 = 0.f;
    float y[4];
    #pragma unroll
    for (int i = 0; i < 4; i++){
        y[i] = yr[i] * fac;
        xy += x[i]*y[i]; x2 += x[i]*x[i]; y2 += y[i]*y[i];
    }
    xy = wsum(xy); x2 = wsum(x2); y2 = wsum(y2);
    float den = fmaxf(1.f + 2.f*xy + x2*y2, 1e-15f);
    float c1 = (1.f + 2.f*xy + y2) / den, c2 = (1.f - x2) / den;
    float h[4], hh = 0.f;
    #pragma unroll
    for (int i = 0; i < 4; i++){ h[i] = c1*x[i] + c2*y[i]; hh += h[i]*h[i]; }
    hh = wsum(hh);
    float hn = sqrtf(fmaxf(hh, 1e-15f));
    float fa = atanhc(hn) / hn;
    float gv[4], gg = 0.f;
    #pragma unroll
    for (int i = 0; i < 4; i++){ gv[i] = gelu_exact(fa*h[i]); gg += gv[i]*gv[i]; }
    gg = wsum(gg);
    float gn = sqrtf(fmaxf(gg, 1e-15f));
    float fb = tanhf(gn) / gn;
    float mx = 0.f, xn2 = 0.f;
    #pragma unroll
    for (int i = 0; i < 4; i++){
        float hs = fb * gv[i];
        mx += hs * __ldg(&whs[lane + i*32]);
        xn2 += hs*hs;
    }
    mx = wsum(mx); xn2 = wsum(xn2);
    if (lane == 0){
        float xn = sqrtf(fmaxf(xn2, 1e-15f));
        float mxn2 = sqrtf(fmaxf(mx*mx, 1e-15f));
        lg[row] = tanhf(mxn2 / xn * atanhc(xn)) * mx / mxn2;
    }
}
// dual transpose: z<BB: Hca -> HcaT fp32 + HcaTh bf16 ; z>=BB: Hsa -> HsahT bf16
__global__ void k_tbk2(const float* __restrict__ Hca, const float* __restrict__ Hsa,
                       float* __restrict__ HcaT, __nv_bfloat16* __restrict__ HcaTh,
                       __nv_bfloat16* __restrict__ HsahT){
    __shared__ float tile[32][33];
    int z = blockIdx.z;
    bool isHc = z < BB;
    int b = isHc ? z : z - BB;
    int j0 = blockIdx.x*32, m0 = blockIdx.y*32;
    const float* src = (isHc ? Hca : Hsa) + (size_t)b*NCQ*KKW;
    for (int i = threadIdx.y; i < 32; i += 8)
        tile[i][threadIdx.x] = src[(size_t)(m0+i)*KKW + j0 + threadIdx.x];
    __syncthreads();
    size_t base = (size_t)b*KKW*NCQ;
    for (int i = threadIdx.y; i < 32; i += 8){
        float v = tile[threadIdx.x][i];
        size_t idx = base + (size_t)(j0+i)*NCQ + m0 + threadIdx.x;
        if (isHc){ HcaT[idx] = v; HcaTh[idx] = __float2bfloat16_rn(v); }
        else     { HsahT[idx] = __float2bfloat16_rn(v); }
    }
}
// Hc pipeline on transposed inputs, fused Ac-logit accumulation (atomics)
__global__ void k_hc(const float* __restrict__ HcaT, const float* __restrict__ MxcT,
                     const float* __restrict__ sc, const float* __restrict__ whc,
                     float* __restrict__ amx, float* __restrict__ ass){
    int bj = blockIdx.x;
    int b = bj >> 7, j = bj & 127;
    int t = threadIdx.x;                                  // 256
    float wj = __ldg(&whc[j]);
    const float* xrow = HcaT + ((size_t)(b*KKW + j))*NCQ;
    const float* yrow = MxcT + ((size_t)(b*KKW + j))*NCQ;
    const float* srow = sc + (size_t)b*NCQ;
    float x[4], y[4];
    #pragma unroll
    for (int i = 0; i < 4; i++){
        int m = t + i*256;
        x[i] = xrow[m]; y[i] = yrow[m] * srow[m];
    }
    float sxy = 0.f, sx2 = 0.f, sy2 = 0.f;
    #pragma unroll
    for (int i = 0; i < 4; i++){ sxy += x[i]*y[i]; sx2 += x[i]*x[i]; sy2 += y[i]*y[i]; }
    blockReduceSum3(sxy, sx2, sy2);
    float xy = sxy, x2 = sx2, y2 = sy2;
    float den = fmaxf(1.f + 2.f*xy + x2*y2, 1e-15f);
    float c1 = 1.f + 2.f*xy + y2, c2 = 1.f - x2;
    float h[4], hh = 0.f;
    #pragma unroll
    for (int i = 0; i < 4; i++){ h[i] = (c1*x[i] + c2*y[i]) / den; hh += h[i]*h[i]; }
    float hn = sqrtf(fmaxf(blockReduceSum(hh), 1e-15f));
    float fa = atanhc(hn) / hn;
    float g[4], gg = 0.f;
    #pragma unroll
    for (int i = 0; i < 4; i++){ g[i] = gelu_exact(fa*h[i]); gg += g[i]*g[i]; }
    float gn = sqrtf(fmaxf(blockReduceSum(gg), 1e-15f));
    float fb = tanhf(gn) / gn;
    #pragma unroll
    for (int i = 0; i < 4; i++){
        int m = t + i*256;
        float hc = fb * g[i];
        atomicAdd(&amx[b*NCQ + m], hc * wj);
        atomicAdd(&ass[b*NCQ + m], hc * hc);
    }
}
// As softmax (reads precomputed logits)
__global__ void k_softmax(const float* __restrict__ lg, float* __restrict__ out){
    int b = blockIdx.x, t = threadIdx.x;                  // 256
    float l[4];
    float lm = -3.4e38f;
    #pragma unroll
    for (int i = 0; i < 4; i++){ l[i] = lg[b*1024 + t + i*256]; lm = fmaxf(lm, l[i]); }
    float M = blockReduceMax(lm);
    float es = 0.f, e[4];
    #pragma unroll
    for (int i = 0; i < 4; i++){ e[i] = expf(l[i] - M); es += e[i]; }
    float S = blockReduceSum(es);
    #pragma unroll
    for (int i = 0; i < 4; i++) out[b*1024 + t + i*256] = e[i] / S;
}
// Ac softmax with fused logit computation from amx/ass
__global__ void k_softmax_ac(const float* __restrict__ amx, const float* __restrict__ ass,
                             float* __restrict__ out){
    int b = blockIdx.x, t = threadIdx.x;                  // 256
    float l[4];
    float lm = -3.4e38f;
    #pragma unroll
    for (int i = 0; i < 4; i++){
        int m = t + i*256;
        float mx = amx[b*NCQ + m];
        float ssv = ass[b*NCQ + m];
        float xn = sqrtf(fmaxf(ssv, 1e-15f));
        float mxn = sqrtf(fmaxf(mx*mx, 1e-15f));
        l[i] = tanhf(mxn / xn * atanhc(xn)) * mx / mxn;
        lm = fmaxf(lm, l[i]);
    }
    float M = blockReduceMax(lm);
    float es = 0.f, e[4];
    #pragma unroll
    for (int i = 0; i < 4; i++){ e[i] = expf(l[i] - M); es += e[i]; }
    float S = blockReduceSum(es);
    #pragma unroll
    for (int i = 0; i < 4; i++) out[b*1024 + t + i*256] = e[i] / S;
}
// dual-branch centroid partials: z<BB sentence (Ls, As), z>=BB comment (Lc, Ac)
__global__ void k_centroid_part(const float* __restrict__ Ls, const float* __restrict__ Lc,
                                const float* __restrict__ outw, int asoff, int acoff,
                                float* __restrict__ part){
    __shared__ float wsh[128];
    int ch = blockIdx.x, z = blockIdx.y;
    bool isS = z < BB;
    int b = isS ? z : z - BB;
    const float* Lx = isS ? Ls : Lc;
    const float* w = outw + (isS ? asoff : acoff) + (size_t)b*NSQ;
    int t = threadIdx.x;                                  // 288, t<257 active
    for (int i = t; i < 128; i += blockDim.x) wsh[i] = w[ch*128 + i];
    __syncthreads();
    if (t < DP1){
        const float* base = Lx + ((size_t)b*NSQ + (size_t)ch*128)*DPAD + t;
        float acc = 0.f;
        for (int n = 0; n < 128; n++) acc += wsh[n] * base[(size_t)n*DPAD];
        part[(z*8 + ch)*DP1 + t] = acc;
    }
}
__global__ void k_centroid_fin(const float* __restrict__ part, float* __restrict__ cs,
                               float* __restrict__ cc){
    __shared__ float t0sh;
    int z = blockIdx.x, t = threadIdx.x;                  // 288
    float acc = 0.f;
    if (t < DP1){
        #pragma unroll
        for (int c = 0; c < 8; c++) acc += part[(z*8 + c)*DP1 + t];
    }
    float sp = (t >= 1 && t < DP1) ? acc*acc : 0.f;
    float ssp = blockReduceSum(sp);
    if (t == 0) t0sh = acc;
    __syncthreads();
    float inner = -t0sh*t0sh + ssp;
    float den = sqrtf(fmaxf(fabsf(inner), 1e-8f));
    float* co = (z < BB) ? cs : cc;
    int b = (z < BB) ? z : z - BB;
    if (t < DP1) co[(size_t)b*DP1 + t] = acc / den;
}
__global__ void k_concat(const float* __restrict__ cs, const float* __restrict__ cc,
                         float* __restrict__ out){
    int b = blockIdx.x, t = threadIdx.x;                  // 256
    float t0s = cs[(size_t)b*DP1];
    float t0c = cc[(size_t)b*DP1];
    float sps = cs[(size_t)b*DP1 + 1 + t];
    float spc = cc[(size_t)b*DP1 + 1 + t];
    float ns  = sqrtf(fmaxf(blockReduceSum(sps*sps), 1e-15f));
    float ncv = sqrtf(fmaxf(blockReduceSum(spc*spc), 1e-15f));
    float zs = acoshf(fmaxf(t0s, 1.f + 1e-7f)) * sps / ns;
    float zc = acoshf(fmaxf(t0c, 1.f + 1e-7f)) * spc / ncv;
    float vn = sqrtf(fmaxf(blockReduceSum(zs*zs + zc*zc), 1e-15f));
    float f = sinhf(vn) / vn;
    float* o = out + (size_t)b*513;
    if (t == 0) o[0] = coshf(vn);
    o[1 + t]       = f * zs;
    o[1 + DD + t]  = f * zc;
}

// ----------------------------- launch ----------------------------------------------
extern "C" void kernel_launch(void* const* d_in, const int* in_sizes, int n_in,
                              void* d_out, int out_size)
{
    const float* sent = (const float*)d_in[0];
    const float* comm = (const float*)d_in[1];
    const float* WlW  = (const float*)d_in[2];
    const float* Wlb  = (const float*)d_in[3];
    const float* WcW  = (const float*)d_in[4];
    const float* Wcb  = (const float*)d_in[5];
    const float* WsW  = (const float*)d_in[6];
    const float* Wsb  = (const float*)d_in[7];
    const float* whs  = (const float*)d_in[8];
    const float* whc  = (const float*)d_in[9];
    float* out = (float*)d_out;
    (void)in_sizes; (void)n_in; (void)out_size;

    float2 *c1, *c1T;
    float *sT, *rl, *Ls, *Lc, *Llin, *Yt, *rss, *css, *amx, *ass, *xnr, *xnc,
          *msc, *Hsa, *Hca, *HcaT, *Mxs, *MxcT, *lgs, *cs, *cc, *part;
    __nv_bfloat16 *Lsh, *Lch, *Llh, *Lbh, *LbTh, *HcaTh, *HsahT, *Wth;
    cudaGetSymbolAddress((void**)&c1,  g_c1);
    cudaGetSymbolAddress((void**)&c1T, g_c1T);
    cudaGetSymbolAddress((void**)&sT,  g_sT);
    cudaGetSymbolAddress((void**)&rl,  g_real);
    cudaGetSymbolAddress((void**)&Ls,  g_Ls);
    cudaGetSymbolAddress((void**)&Lc,  g_Lc);
    cudaGetSymbolAddress((void**)&Llin,g_Llin);
    cudaGetSymbolAddress((void**)&Yt,  g_Yt);
    cudaGetSymbolAddress((void**)&Wth, g_Wth);
    cudaGetSymbolAddress((void**)&Lsh, g_Lsh);
    cudaGetSymbolAddress((void**)&Lch, g_Lch);
    cudaGetSymbolAddress((void**)&Llh, g_Llh);
    cudaGetSymbolAddress((void**)&Lbh, g_Lbh);
    cudaGetSymbolAddress((void**)&LbTh,g_LbTh);
    cudaGetSymbolAddress((void**)&HcaTh,g_HcaTh);
    cudaGetSymbolAddress((void**)&HsahT,g_HsahT);
    cudaGetSymbolAddress((void**)&rss, g_rss);
    cudaGetSymbolAddress((void**)&css, g_css);
    cudaGetSymbolAddress((void**)&amx, g_amx);
    cudaGetSymbolAddress((void**)&ass, g_ass);
    cudaGetSymbolAddress((void**)&xnr, g_xnr);
    cudaGetSymbolAddress((void**)&xnc, g_xnc);
    cudaGetSymbolAddress((void**)&msc, g_msc);
    cudaGetSymbolAddress((void**)&Hsa, g_Hsa);
    cudaGetSymbolAddress((void**)&Hca, g_Hca);
    cudaGetSymbolAddress((void**)&HcaT,g_HcaT);
    cudaGetSymbolAddress((void**)&Mxs, g_Mxs);
    cudaGetSymbolAddress((void**)&MxcT,g_MxcT);
    cudaGetSymbolAddress((void**)&lgs, g_lgs);
    cudaGetSymbolAddress((void**)&cs,  g_cs);
    cudaGetSymbolAddress((void**)&cc,  g_cc);
    cudaGetSymbolAddress((void**)&part,g_part);

    const int AS_OFF = BB*513;             // 16416
    const int AC_OFF = AS_OFF + BB*NSQ;    // 49184

    k_setup<<<32 + DP1 + 2*KP1, 1024>>>(WlW, WsW, WcW, rss, css, amx, ass);

    // ---- dual-branch FFT2 (stage-0 fused, Hermitian-compact) + euclid_to_lorentz ----
    k_fft256<<<2*BB*NSQ/4, dim3(64,4)>>>(sent, comm, c1);
    k_transpose_ch<<<dim3(5, NSQ/32, 2*BB), dim3(32,8)>>>(c1, c1T);
    k_fft1024<<<2*BB*DH, 256>>>(c1T, sT);
    k_transpose_fh<<<dim3(5, NSQ/32, 2*BB), dim3(32,8)>>>(sT, rl);
    k_e2l<<<2*BB*NSQ, 256>>>(rl, Ls, Lc, Lsh, Lch);

    // ---- linear layers (bf16; dead time-column skipped: W rows 1..) ----
    k_bgemm<1><<<dim3(2,256,1),256>>>(Lch, Wth + (size_t)1*DPAD, Wlb + 1, Llin + 1,
        nullptr, nullptr, BB*NCQ, 256, DP1, DPAD, DPAD, DPAD, 0,
        0, 0, 0, 0, nullptr, nullptr);
    k_fix_time<<<BB*NCQ, 256>>>(Llin, Llh);

    k_bgemm<1><<<dim3(1,256,1),256>>>(Lsh, Wth + (size_t)385*DPAD, Wsb + 1, Yt,
        nullptr, nullptr, BB*NSQ, KKW, DP1, DPAD, DPAD, KKW, 0,
        0, 0, 0, 0, nullptr, nullptr);
    k_poincare<<<BB*NSQ/8, 256>>>(Yt, Hsa);

    k_bgemm<1><<<dim3(1,256,1),256>>>(Lch, Wth + (size_t)641*DPAD, Wcb + 1, Yt,
        nullptr, nullptr, BB*NCQ, KKW, DP1, DPAD, DPAD, KKW, 0,
        0, 0, 0, 0, nullptr, nullptr);
    k_poincare<<<BB*NCQ/8, 256>>>(Yt, Hca);

    // ---- big einsum (bf16) + lorentz_act + fused norms, coalesced dual bf16 out ----
    k_bgemm<2><<<dim3(8,8,BB),256>>>(Lsh, Llh, nullptr, nullptr, Lbh, LbTh,
        NSQ, NCQ, DP1, DPAD, DPAD, NCQ, NSQ,
        (long)NSQ*DPAD, (long)NCQ*DPAD, 0, (long)NSQ*NCQ, rss, css);
    k_nfin<<<BB, 1024>>>(rss, css, Lbh, LbTh, xnr, xnc);

    // ---- transposes for mobius operands ----
    k_tbk2<<<dim3(4, 32, 2*BB), dim3(32,8)>>>(Hca, Hsa, HcaT, HcaTh, HsahT);

    // ---- mobius_matvec GEMMs (bf16) ----
    k_bgemm<0><<<dim3(1,8,BB),256>>>(Lbh, HcaTh, nullptr, Mxs, nullptr, nullptr,
        NSQ, KKW, NCQ, NCQ, NCQ, KKW, 0,
        (long)NSQ*NCQ, (long)KKW*NCQ, (long)NSQ*KKW, 0, nullptr, nullptr);
    k_bgemm<0><<<dim3(8,1,BB),256>>>(HsahT, LbTh, nullptr, MxcT, nullptr, nullptr,
        KKW, NCQ, NSQ, NSQ, NSQ, NCQ, 0,
        (long)KKW*NSQ, (long)NCQ*NSQ, (long)KKW*NCQ, 0, nullptr, nullptr);
    k_mscale<<<dim3(NCQ/256, BB), 256>>>(MxcT, xnc, msc);

    // ---- mobius_add + gelu pipelines + attention logits ----
    k_hs<<<BB*NSQ/8, 256>>>(Hsa, Mxs, xnr, whs, lgs);
    k_hc<<<BB*KKW, 256>>>(HcaT, MxcT, msc, whc, amx, ass);

    // ---- softmaxes straight into output (Ac logit fused) ----
    k_softmax<<<BB, 256>>>(lgs, out + AS_OFF);
    k_softmax_ac<<<BB, 256>>>(amx, ass, out + AC_OFF);

    // ---- centroids (dual-branch) + concat ----
    k_centroid_part<<<dim3(8, 2*BB), 288>>>(Ls, Lc, out, AS_OFF, AC_OFF, part);
    k_centroid_fin<<<2*BB, 288>>>(part, cs, cc);
    k_concat<<<BB, 256>>>(cs, cc, out);
}

// round 14
// speedup vs baseline: 1.2055x; 1.0151x over previous
#include <cuda_runtime.h>
#include <cuda_bf16.h>
#include <math.h>
#include <stdint.h>

#define BB  32
#define NSQ 1024
#define NCQ 1024
#define DD  256
#define DP1 257
#define DPAD 272
#define KKW 128
#define KP1 129
#define DH  129   // Hermitian-reduced column count

// ----------------------------- scratch (static device globals; no runtime alloc) ---
static __device__ float2 g_c1 [(size_t)2*BB*NSQ*DH];
static __device__ float2 g_c1T[(size_t)2*BB*DH*NSQ];
static __device__ float  g_sT [(size_t)2*BB*DH*NSQ];
static __device__ float  g_real[(size_t)2*BB*NSQ*DH];
static __device__ float  g_Ls [(size_t)BB*NSQ*DPAD];
static __device__ float  g_Lc [(size_t)BB*NCQ*DPAD];
static __device__ float  g_Llin[(size_t)BB*NCQ*DPAD];
static __device__ float  g_Yt [(size_t)BB*NSQ*KKW];
static __device__ __align__(16) __nv_bfloat16 g_Wth[(size_t)896*DPAD]; // Wl@0,Ws@384,Wc@640
static __device__ __align__(16) __nv_bfloat16 g_Wtl[(size_t)896*DPAD]; // lo residuals
static __device__ __align__(16) __nv_bfloat16 g_Lsh [(size_t)BB*NSQ*DPAD];
static __device__ __align__(16) __nv_bfloat16 g_Lch [(size_t)BB*NCQ*DPAD];
static __device__ __align__(16) __nv_bfloat16 g_Llh [(size_t)BB*NCQ*DPAD];
static __device__ __align__(16) __nv_bfloat16 g_Lbh [(size_t)BB*NSQ*NCQ];
static __device__ __align__(16) __nv_bfloat16 g_LbTh[(size_t)BB*NCQ*NSQ];
static __device__ __align__(16) __nv_bfloat16 g_HcaTh[(size_t)BB*KKW*NCQ];
static __device__ __align__(16) __nv_bfloat16 g_HsahT[(size_t)BB*KKW*NSQ];
static __device__ float  g_rss[BB*NSQ];
static __device__ float  g_css[BB*NCQ];
static __device__ float  g_amx[BB*NCQ];
static __device__ float  g_ass[BB*NCQ];
static __device__ float  g_xnr[BB*NSQ];
static __device__ float  g_xnc[BB*NCQ];
static __device__ float  g_msc[BB*NCQ];
static __device__ float  g_Hsa[(size_t)BB*NSQ*KKW];
static __device__ float  g_Hca[(size_t)BB*NCQ*KKW];
static __device__ float  g_HcaT[(size_t)BB*KKW*NCQ];
static __device__ float  g_Mxs[(size_t)BB*NSQ*KKW];
static __device__ float  g_MxcT[(size_t)BB*KKW*NCQ];
static __device__ float  g_lgs[BB*NSQ];
static __device__ float  g_cs [BB*DP1];
static __device__ float  g_cc [BB*DP1];
static __device__ float  g_part[2*BB*8*DP1];
static __device__ float2 g_tw1024[1024];
static __device__ float2 g_tw256[256];

// ----------------------------- helpers ---------------------------------------------
__device__ __forceinline__ float atanhc(float x){
    x = fminf(fmaxf(x, -1.f + 1e-5f), 1.f - 1e-5f);
    return 0.5f * (log1pf(x) - log1pf(-x));
}
__device__ __forceinline__ float gelu_exact(float v){
    return 0.5f * v * (1.f + erff(v * 0.70710678118654752f));
}
__device__ __forceinline__ float2 cmul(float2 a, float2 b){
    return make_float2(a.x*b.x - a.y*b.y, a.x*b.y + a.y*b.x);
}
__device__ __forceinline__ float2 cadd(float2 a, float2 b){ return make_float2(a.x+b.x, a.y+b.y); }
__device__ __forceinline__ float2 csub(float2 a, float2 b){ return make_float2(a.x-b.x, a.y-b.y); }

__device__ __forceinline__ float wsum(float v){
    #pragma unroll
    for (int o = 16; o; o >>= 1) v += __shfl_xor_sync(0xffffffffu, v, o);
    return v;
}
__device__ __forceinline__ float blockReduceSum(float v){
    __shared__ float sh[32];
    #pragma unroll
    for (int o = 16; o; o >>= 1) v += __shfl_down_sync(0xffffffffu, v, o);
    int lane = threadIdx.x & 31, w = threadIdx.x >> 5;
    if (lane == 0) sh[w] = v;
    __syncthreads();
    int nw = (blockDim.x + 31) >> 5;
    v = (threadIdx.x < (unsigned)nw) ? sh[threadIdx.x] : 0.f;
    if (w == 0){
        #pragma unroll
        for (int o = 16; o; o >>= 1) v += __shfl_down_sync(0xffffffffu, v, o);
        if (lane == 0) sh[0] = v;
    }
    __syncthreads();
    float r = sh[0];
    __syncthreads();
    return r;
}
__device__ __forceinline__ float blockReduceMax(float v){
    __shared__ float sh[32];
    #pragma unroll
    for (int o = 16; o; o >>= 1) v = fmaxf(v, __shfl_down_sync(0xffffffffu, v, o));
    int lane = threadIdx.x & 31, w = threadIdx.x >> 5;
    if (lane == 0) sh[w] = v;
    __syncthreads();
    int nw = (blockDim.x + 31) >> 5;
    v = (threadIdx.x < (unsigned)nw) ? sh[threadIdx.x] : -3.4e38f;
    if (w == 0){
        #pragma unroll
        for (int o = 16; o; o >>= 1) v = fmaxf(v, __shfl_down_sync(0xffffffffu, v, o));
        if (lane == 0) sh[0] = v;
    }
    __syncthreads();
    float r = sh[0];
    __syncthreads();
    return r;
}
__device__ __forceinline__ void mma_bf16(float* c, const uint32_t* a, const uint32_t* b){
    asm volatile("mma.sync.aligned.m16n8k16.row.col.f32.bf16.bf16.f32 "
        "{%0,%1,%2,%3}, {%4,%5,%6,%7}, {%8,%9}, {%0,%1,%2,%3};"
        : "+f"(c[0]), "+f"(c[1]), "+f"(c[2]), "+f"(c[3])
        : "r"(a[0]), "r"(a[1]), "r"(a[2]), "r"(a[3]), "r"(b[0]), "r"(b[1]));
}
__device__ __forceinline__ void cpa16(uint32_t dsh, const void* src){
    asm volatile("cp.async.ca.shared.global [%0], [%1], 16;" :: "r"(dsh), "l"(src));
}
#define CP_COMMIT() asm volatile("cp.async.commit_group;" ::: "memory")
#define CP_WAIT1()  asm volatile("cp.async.wait_group 1;" ::: "memory")
#define CP_WAIT0()  asm volatile("cp.async.wait_group 0;" ::: "memory")

// ----------------------------- merged setup kernel ---------------------------------
// blocks 0..31: zero accumulators (+block 0 fills twiddles)
// blocks 32..546: bf16 hi/lo padded weight copies (pad stays zero: static init)
__global__ void k_setup(const float* __restrict__ Wl, const float* __restrict__ Ws,
                        const float* __restrict__ Wc,
                        float* __restrict__ a, float* __restrict__ b,
                        float* __restrict__ c, float* __restrict__ d){
    int blk = blockIdx.x;
    int t = threadIdx.x;                       // 1024
    if (blk < 32){
        int i = blk*1024 + t;
        a[i] = 0.f; b[i] = 0.f; c[i] = 0.f; d[i] = 0.f;
        if (blk == 0){
            double ang = -6.283185307179586476925287 * (double)t / 1024.0;
            g_tw1024[t] = make_float2((float)cos(ang), (float)sin(ang));
            if (t < 256){
                double a2 = -6.283185307179586476925287 * (double)t / 256.0;
                g_tw256[t] = make_float2((float)cos(a2), (float)sin(a2));
            }
        }
        return;
    }
    int r = blk - 32;                          // 0..514
    if (t >= DP1) return;
    const float* src; size_t drow;
    if (r < DP1){ src = Wl + (size_t)r*DP1; drow = (size_t)r*DPAD; }
    else if (r < DP1 + KP1){ int rr = r - DP1; src = Ws + (size_t)rr*DP1; drow = (size_t)(384+rr)*DPAD; }
    else { int rr = r - DP1 - KP1; src = Wc + (size_t)rr*DP1; drow = (size_t)(640+rr)*DPAD; }
    float w = src[t];
    __nv_bfloat16 hi = __float2bfloat16_rn(w);
    g_Wth[drow + t] = hi;
    g_Wtl[drow + t] = __float2bfloat16_rn(w - __bfloat162float(hi));
}

// ----------------------------- radix-4 Stockham FFT kernels ------------------------
__global__ void k_fft256(const float* __restrict__ sent, const float* __restrict__ comm,
                         float2* __restrict__ out){
    __shared__ float2 bufA[4][256];
    __shared__ float2 bufB[4][256];
    __shared__ float2 tws[256];
    __shared__ float  rsum[4][2];
    int tx = threadIdx.x;                      // 64
    int ty = threadIdx.y;                      // 4
    int tid = ty*64 + tx;
    size_t row = (size_t)blockIdx.x*4 + ty;
    bool do_log = row >= (size_t)BB*NSQ;
    const float* x = do_log ? (comm + (row - (size_t)BB*NSQ)*256) : (sent + row*256);
    tws[tid] = g_tw256[tid];

    float v0 = x[tx], v1 = x[tx+64], v2 = x[tx+128], v3 = x[tx+192];
    float ss = v0*v0 + v1*v1 + v2*v2 + v3*v3;
    #pragma unroll
    for (int o = 16; o; o >>= 1) ss += __shfl_down_sync(0xffffffffu, ss, o);
    if ((tx & 31) == 0) rsum[ty][tx >> 5] = ss;
    __syncthreads();
    if (do_log){
        float tot = rsum[ty][0] + rsum[ty][1];
        float yn = sqrtf(fmaxf(tot, 1e-15f));
        float f = atanhc(yn) / yn;
        v0 *= f; v1 *= f; v2 *= f; v3 *= f;
    }
    {
        float pa = v0 + v2, pb = v0 - v2;
        float pc = v1 + v3, pd = v1 - v3;
        bufA[ty][4*tx]     = make_float2(pa + pc, 0.f);
        bufA[ty][4*tx + 1] = make_float2(pb, -pd);
        bufA[ty][4*tx + 2] = make_float2(pa - pc, 0.f);
        bufA[ty][4*tx + 3] = make_float2(pb,  pd);
    }
    __syncthreads();

    float2* X = &bufA[ty][0];
    float2* Y = &bufB[ty][0];
    #pragma unroll
    for (int s = 1; s < 4; s++){
        int Ns = 1 << (2*s);
        int p = tx & (Ns - 1);
        float2 w1 = tws[p * (64/Ns)];
        float2 w2 = cmul(w1, w1);
        float2 w3 = cmul(w2, w1);
        float2 a0 = X[tx];
        float2 a1 = cmul(X[tx + 64],  w1);
        float2 a2 = cmul(X[tx + 128], w2);
        float2 a3 = cmul(X[tx + 192], w3);
        float2 pa = cadd(a0, a2), pb = csub(a0, a2);
        float2 pc = cadd(a1, a3), pd = csub(a1, a3);
        float2 dneg = make_float2(pd.y, -pd.x);
        float2 dpos = make_float2(-pd.y, pd.x);
        int idxD = ((tx >> (2*s)) << (2*s + 2)) + p;
        Y[idxD]          = cadd(pa, pc);
        Y[idxD + Ns]     = cadd(pb, dneg);
        Y[idxD + 2*Ns]   = csub(pa, pc);
        Y[idxD + 3*Ns]   = cadd(pb, dpos);
        __syncthreads();
        float2* tmp = X; X = Y; Y = tmp;
    }
    out[row*DH + tx]      = X[tx];
    out[row*DH + tx + 64] = X[tx + 64];
    if (tx == 0) out[row*DH + 128] = X[128];
}

__global__ void k_fft1024(const float2* __restrict__ in, float* __restrict__ outr){
    __shared__ float2 bufA[1024];
    __shared__ float2 bufB[1024];
    __shared__ float2 tws[1024];
    int t = threadIdx.x;                       // 256
    size_t row = blockIdx.x;
    const float2* src = in + row*1024;
    float2 a0 = src[t], a1 = src[t+256], a2 = src[t+512], a3 = src[t+768];
    #pragma unroll
    for (int i = 0; i < 4; i++)
        tws[t + i*256] = g_tw1024[t + i*256];
    {
        float2 pa = cadd(a0, a2), pb = csub(a0, a2);
        float2 pc = cadd(a1, a3), pd = csub(a1, a3);
        bufA[4*t]     = cadd(pa, pc);
        bufA[4*t + 1] = cadd(pb, make_float2(pd.y, -pd.x));
        bufA[4*t + 2] = csub(pa, pc);
        bufA[4*t + 3] = cadd(pb, make_float2(-pd.y, pd.x));
    }
    __syncthreads();
    float2* X = bufA;
    float2* Y = bufB;
    #pragma unroll
    for (int s = 1; s < 5; s++){
        int Ns = 1 << (2*s);
        int p = t & (Ns - 1);
        float2 w1 = tws[p * (256/Ns)];
        float2 w2 = cmul(w1, w1);
        float2 w3 = cmul(w2, w1);
        float2 b0 = X[t];
        float2 b1 = cmul(X[t + 256], w1);
        float2 b2 = cmul(X[t + 512], w2);
        float2 b3 = cmul(X[t + 768], w3);
        float2 pa = cadd(b0, b2), pb = csub(b0, b2);
        float2 pc = cadd(b1, b3), pd = csub(b1, b3);
        float2 dneg = make_float2(pd.y, -pd.x);
        float2 dpos = make_float2(-pd.y, pd.x);
        int idxD = ((t >> (2*s)) << (2*s + 2)) + p;
        Y[idxD]        = cadd(pa, pc);
        Y[idxD + Ns]   = cadd(pb, dneg);
        Y[idxD + 2*Ns] = csub(pa, pc);
        Y[idxD + 3*Ns] = cadd(pb, dpos);
        __syncthreads();
        float2* tmp = X; X = Y; Y = tmp;
    }
    #pragma unroll
    for (int i = 0; i < 4; i++)
        outr[row*1024 + t + i*256] = X[t + i*256].x;
}

__global__ void k_transpose_ch(const float2* __restrict__ in, float2* __restrict__ out){
    __shared__ float2 tile[32][33];
    int b = blockIdx.z;
    int c0 = blockIdx.x*32, r0 = blockIdx.y*32;
    const float2* src = in + (size_t)b*NSQ*DH;
    for (int i = threadIdx.y; i < 32; i += 8){
        int d = c0 + threadIdx.x;
        tile[i][threadIdx.x] = (d < DH) ? src[(size_t)(r0+i)*DH + d]
                                        : make_float2(0.f, 0.f);
    }
    __syncthreads();
    float2* dst = out + (size_t)b*DH*NSQ;
    for (int i = threadIdx.y; i < 32; i += 8){
        int d = c0 + i;
        if (d < DH) dst[(size_t)d*NSQ + r0 + threadIdx.x] = tile[threadIdx.x][i];
    }
}
__global__ void k_transpose_fh(const float* __restrict__ in, float* __restrict__ out){
    __shared__ float tile[32][33];
    int b = blockIdx.z;
    int d0 = blockIdx.x*32, n0 = blockIdx.y*32;
    const float* src = in + (size_t)b*DH*NSQ;
    for (int i = threadIdx.y; i < 32; i += 8){
        int d = d0 + i;
        tile[i][threadIdx.x] = (d < DH) ? src[(size_t)d*NSQ + n0 + threadIdx.x] : 0.f;
    }
    __syncthreads();
    float* dst = out + (size_t)b*NSQ*DH;
    int d = d0 + threadIdx.x;
    if (d < DH)
        for (int i = threadIdx.y; i < 32; i += 8)
            dst[(size_t)(n0+i)*DH + d] = tile[threadIdx.x][i];
}

// fused Hermitian mirror + euclid_to_lorentz; fp32 (centroid) + bf16 (GEMM operands)
__global__ void k_e2l(const float* __restrict__ rl, float* __restrict__ Ls,
                      float* __restrict__ Lc, __nv_bfloat16* __restrict__ Lsh,
                      __nv_bfloat16* __restrict__ Lch){
    size_t row = blockIdx.x;                   // 0 .. 2*BB*NSQ-1
    int t = threadIdx.x;                       // 256
    size_t bb = row >> 10;
    int n = (int)(row & 1023);
    float v;
    if (t < DH){
        v = rl[(bb*NSQ + n)*DH + t];
    } else {
        int srcn = (1024 - n) & 1023;
        v = rl[(bb*NSQ + srcn)*DH + (256 - t)];
    }
    float ss = blockReduceSum(v*v);
    float xn = sqrtf(fmaxf(ss, 1e-15f)) + 1e-5f;
    float scl = fminf(1.f, 2.0f / xn);
    v *= scl;
    float vn = sqrtf(fmaxf(ss*scl*scl, 1e-15f));
    float f = sinhf(vn) / vn;
    bool isS = bb < BB;
    float* out = isS ? Ls : Lc;
    __nv_bfloat16* outh = isS ? Lsh : Lch;
    size_t orow = isS ? row : row - (size_t)BB*NSQ;
    float tv = coshf(vn), sv = f * v;
    if (t == 0){ out[orow*DPAD] = tv; outh[orow*DPAD] = __float2bfloat16_rn(tv); }
    out[orow*DPAD + 1 + t] = sv;
    outh[orow*DPAD + 1 + t] = __float2bfloat16_rn(sv);
    if (t < DPAD - DP1) out[orow*DPAD + DP1 + t] = 0.f;
}

// --------- bf16 GEMM (m16n8k16): A[m][k], B[n][k] --------------------------------
//  MODE 0: plain fp32 C        MODE 1: fp32 C + bias[n] (SPLITB: B = Bh + Bl)
//  MODE 2: einsum epilogue     MODE 3: fp32 C + fused mscale (xnc in, msc out)
template<int MODE, int SPLITB>
__global__ void k_bgemm(const __nv_bfloat16* __restrict__ A,
                        const __nv_bfloat16* __restrict__ Bm,
                        const __nv_bfloat16* __restrict__ Bl,
                        const float* __restrict__ bias,
                        float* __restrict__ C,
                        __nv_bfloat16* __restrict__ Cb, __nv_bfloat16* __restrict__ CbT,
                        int M, int N, int Klen, int lda, int ldb, int ldc, int ldt,
                        long sA, long sB, long sC, long sCb,
                        float* __restrict__ rss, float* __restrict__ css)
{
    __shared__ __align__(16) char smemraw[49152];
    // layout: As @0 (12KB), Bl @12288 (12KB, SPLITB only), Bs @24576 (12KB)
    __nv_bfloat16* AsBuf = reinterpret_cast<__nv_bfloat16*>(smemraw);
    __nv_bfloat16* BlBuf = reinterpret_cast<__nv_bfloat16*>(smemraw + 12288);
    __nv_bfloat16* BsBuf = reinterpret_cast<__nv_bfloat16*>(smemraw + 24576);

    int bz = blockIdx.z;
    A  += (size_t)bz * sA;
    Bm += (size_t)bz * sB;
    if (MODE != 2) C += (size_t)bz * sC;
    else { Cb += (size_t)bz * sCb; CbT += (size_t)bz * sCb; }
    int bm = blockIdx.y * 128, bn = blockIdx.x * 128;
    int tid = threadIdx.x;
    int wid = tid >> 5, lane = tid & 31;
    int wm = (wid >> 2) * 64;
    int wn = (wid & 3) * 32;
    int g = lane >> 2, tg = lane & 3;
    int KT = (Klen + 15) >> 4;

    uint32_t asBase = (uint32_t)__cvta_generic_to_shared(AsBuf);
    uint32_t blBase = (uint32_t)__cvta_generic_to_shared(BlBuf);
    uint32_t bsBase = (uint32_t)__cvta_generic_to_shared(BsBuf);

    auto issueA = [&](int st, int k0){
        int mm = tid >> 1, c = tid & 1;
        cpa16(asBase + (uint32_t)(st*6144) + (mm*24 + c*8)*2,
              A + (size_t)(bm+mm)*lda + k0 + c*8);
    };
    auto issueB = [&](int st, int k0){
        int nn = tid >> 1, c = tid & 1;
        cpa16(bsBase + (uint32_t)(st*6144) + (nn*24 + c*8)*2,
              Bm + (size_t)(bn+nn)*ldb + k0 + c*8);
        if (SPLITB)
            cpa16(blBase + (uint32_t)(st*6144) + (nn*24 + c*8)*2,
                  Bl + (size_t)(bn+nn)*ldb + k0 + c*8);
    };

    float acc[4][4][4];
    #pragma unroll
    for (int mi = 0; mi < 4; mi++)
        #pragma unroll
        for (int ni = 0; ni < 4; ni++)
            #pragma unroll
            for (int r = 0; r < 4; r++) acc[mi][ni][r] = 0.f;

    issueA(0, 0); issueB(0, 0);
    CP_COMMIT();

    for (int kt = 0; kt < KT; kt++){
        int st = kt & 1;
        if (kt + 1 < KT){
            issueA(st ^ 1, (kt+1)*16);
            issueB(st ^ 1, (kt+1)*16);
            CP_COMMIT();
            CP_WAIT1();
        } else {
            CP_WAIT0();
        }
        __syncthreads();

        const uint32_t* pA = reinterpret_cast<const uint32_t*>(AsBuf + st*3072);
        const uint32_t* pB = reinterpret_cast<const uint32_t*>(BsBuf + st*3072);
        uint32_t bhf[4][2];
        #pragma unroll
        for (int ni = 0; ni < 4; ni++){
            int n = wn + ni*8 + g;
            bhf[ni][0] = pB[n*12 + tg];
            bhf[ni][1] = pB[n*12 + tg + 4];
        }
        uint32_t blf[4][2];
        if (SPLITB){
            const uint32_t* pL = reinterpret_cast<const uint32_t*>(BlBuf + st*3072);
            #pragma unroll
            for (int ni = 0; ni < 4; ni++){
                int n = wn + ni*8 + g;
                blf[ni][0] = pL[n*12 + tg];
                blf[ni][1] = pL[n*12 + tg + 4];
            }
        }
        #pragma unroll
        for (int mi = 0; mi < 4; mi++){
            int m = wm + mi*16;
            uint32_t ahf[4];
            ahf[0] = pA[(m+g)*12   + tg];
            ahf[1] = pA[(m+g+8)*12 + tg];
            ahf[2] = pA[(m+g)*12   + tg + 4];
            ahf[3] = pA[(m+g+8)*12 + tg + 4];
            #pragma unroll
            for (int ni = 0; ni < 4; ni++){
                mma_bf16(acc[mi][ni], ahf, bhf[ni]);
                if (SPLITB) mma_bf16(acc[mi][ni], ahf, blf[ni]);
            }
        }
        __syncthreads();
    }

    if (MODE != 2){
        #pragma unroll
        for (int mi = 0; mi < 4; mi++)
            #pragma unroll
            for (int ni = 0; ni < 4; ni++){
                int col = bn + wn + ni*8 + 2*tg;
                #pragma unroll
                for (int r = 0; r < 4; r++){
                    int gm = bm + wm + mi*16 + g + (r >= 2 ? 8 : 0);
                    int gn = col + (r & 1);
                    if (gn >= N) continue;
                    float v = acc[mi][ni][r];
                    if (MODE == 1) v += bias[gn];
                    C[(size_t)gm*ldc + gn] = v;
                }
            }
        if (MODE == 3){
            // fused mscale: per-column SSQ over the block's full 128-row column
            __syncthreads();
            float* colss = reinterpret_cast<float*>(smemraw);
            if (tid < 128) colss[tid] = 0.f;
            __syncthreads();
            #pragma unroll
            for (int ni = 0; ni < 4; ni++){
                #pragma unroll
                for (int cb = 0; cb < 2; cb++){
                    float cp = 0.f;
                    #pragma unroll
                    for (int mi = 0; mi < 4; mi++){
                        float a0 = acc[mi][ni][cb], a1 = acc[mi][ni][2+cb];
                        cp += a0*a0 + a1*a1;
                    }
                    cp += __shfl_down_sync(0xffffffffu, cp, 4);
                    cp += __shfl_down_sync(0xffffffffu, cp, 8);
                    cp += __shfl_down_sync(0xffffffffu, cp, 16);
                    if (g == 0)
                        atomicAdd(&colss[wn + ni*8 + 2*tg + cb], cp);
                }
            }
            __syncthreads();
            if (tid < 128){
                float ssv = colss[tid];
                float mxn = sqrtf(fmaxf(ssv, 1e-15f));
                float xnv = rss[(size_t)bz*1024 + bn + tid];       // xnc
                css[(size_t)bz*1024 + bn + tid] =                  // msc
                    tanhf(mxn / xnv * atanhc(xnv)) / mxn;
            }
        }
    } else {
        // gelu (global col0 -> 0) + SSQ atomics, then smem-staged coalesced stores
        #pragma unroll
        for (int mi = 0; mi < 4; mi++)
            #pragma unroll
            for (int ni = 0; ni < 4; ni++){
                int col = bn + wn + ni*8 + 2*tg;
                #pragma unroll
                for (int r = 0; r < 4; r++){
                    int gn = col + (r & 1);
                    acc[mi][ni][r] = (gn == 0) ? 0.f : gelu_exact(acc[mi][ni][r]);
                }
            }
        #pragma unroll
        for (int mi = 0; mi < 4; mi++){
            #pragma unroll
            for (int half = 0; half < 2; half++){
                float rp = 0.f;
                #pragma unroll
                for (int ni = 0; ni < 4; ni++){
                    float a0 = acc[mi][ni][half*2], a1 = acc[mi][ni][half*2+1];
                    rp += a0*a0 + a1*a1;
                }
                rp += __shfl_down_sync(0xffffffffu, rp, 1);
                rp += __shfl_down_sync(0xffffffffu, rp, 2);
                if (tg == 0)
                    atomicAdd(&rss[(size_t)bz*1024 + bm + wm + mi*16 + g + half*8], rp);
            }
        }
        #pragma unroll
        for (int ni = 0; ni < 4; ni++){
            #pragma unroll
            for (int cb = 0; cb < 2; cb++){
                float cp = 0.f;
                #pragma unroll
                for (int mi = 0; mi < 4; mi++){
                    float a0 = acc[mi][ni][cb], a1 = acc[mi][ni][2+cb];
                    cp += a0*a0 + a1*a1;
                }
                cp += __shfl_down_sync(0xffffffffu, cp, 4);
                cp += __shfl_down_sync(0xffffffffu, cp, 8);
                cp += __shfl_down_sync(0xffffffffu, cp, 16);
                if (g == 0)
                    atomicAdd(&css[(size_t)bz*1024 + bn + wn + ni*8 + 2*tg + cb], cp);
            }
        }
        __syncthreads();
        constexpr int TS = 136;                 // padded row stride in bf16
        __nv_bfloat16* tile = reinterpret_cast<__nv_bfloat16*>(smemraw);
        #pragma unroll
        for (int mi = 0; mi < 4; mi++)
            #pragma unroll
            for (int ni = 0; ni < 4; ni++){
                int ln = wn + ni*8 + 2*tg;
                #pragma unroll
                for (int r = 0; r < 4; r++){
                    int lm = wm + mi*16 + g + (r >= 2 ? 8 : 0);
                    tile[lm*TS + ln + (r & 1)] = __float2bfloat16_rn(acc[mi][ni][r]);
                }
            }
        __syncthreads();
        {
            int row = tid >> 1, half = tid & 1;
            const uint4* srcv = reinterpret_cast<const uint4*>(tile + row*TS + half*64);
            uint4* dstv = reinterpret_cast<uint4*>(Cb + (size_t)(bm+row)*ldc + bn + half*64);
            #pragma unroll
            for (int i = 0; i < 8; i++) dstv[i] = srcv[i];
        }
        {
            int coln = tid >> 1, halfm = tid & 1;
            #pragma unroll
            for (int c8 = 0; c8 < 8; c8++){
                __nv_bfloat16 tmp[8];
                #pragma unroll
                for (int j = 0; j < 8; j++)
                    tmp[j] = tile[(halfm*64 + c8*8 + j)*TS + coln];
                *reinterpret_cast<uint4*>(CbT + (size_t)(bn+coln)*ldt + bm + halfm*64 + c8*8)
                    = *reinterpret_cast<const uint4*>(tmp);
            }
        }
    }
}

// ----------------------------- row-wise kernels ------------------------------------
// warp-per-row: read Llin fp32, write full bf16 row (space + time) of Llh
__global__ void k_fix_time(const float* __restrict__ Llin, __nv_bfloat16* __restrict__ Llh){
    size_t row = (size_t)blockIdx.x*8 + (threadIdx.x >> 5);
    int lane = threadIdx.x & 31;
    const float* p = Llin + row*DPAD + 1;
    float v[8], s = 0.f;
    #pragma unroll
    for (int i = 0; i < 8; i++){ v[i] = p[lane + i*32]; s += v[i]*v[i]; }
    s = wsum(s);
    __nv_bfloat16* o = Llh + row*DPAD;
    #pragma unroll
    for (int i = 0; i < 8; i++) o[1 + lane + i*32] = __float2bfloat16_rn(v[i]);
    if (lane == 0) o[0] = __float2bfloat16_rn(sqrtf(s + 1.f));
}
// warp-per-row poincare on 128-wide space rows
__global__ void k_poincare(const float* __restrict__ Y, float* __restrict__ out){
    size_t row = (size_t)blockIdx.x*8 + (threadIdx.x >> 5);
    int lane = threadIdx.x & 31;
    const float* y = Y + row*KKW;
    float v[4], s = 0.f;
    #pragma unroll
    for (int i = 0; i < 4; i++){ v[i] = y[lane + i*32]; s += v[i]*v[i]; }
    s = wsum(s);
    float inv = 1.f / (sqrtf(s + 1.f) + 1.f);
    float* o = out + row*KKW;
    #pragma unroll
    for (int i = 0; i < 4; i++) o[lane + i*32] = v[i] * inv;
}
// finalize norms; write bf16 time entries into Lbh (col0) and LbTh (row0)
__global__ void k_nfin(const float* __restrict__ rss, const float* __restrict__ css,
                       __nv_bfloat16* __restrict__ Lbh, __nv_bfloat16* __restrict__ LbTh,
                       float* __restrict__ xnr, float* __restrict__ xnc){
    int b = blockIdx.x, n = threadIdx.x;                  // 1024
    float S = rss[b*1024 + n];
    float tv = sqrtf(S + 1.f);
    Lbh[((size_t)b*1024 + n)*1024] = __float2bfloat16_rn(tv);
    LbTh[(size_t)b*1024*1024 + n]  = __float2bfloat16_rn(tv);
    xnr[b*1024 + n] = sqrtf(fmaxf(2.f*S + 1.f, 1e-15f));
    float ts = blockReduceSum(S + 1.f);
    float c = css[b*1024 + n];
    xnc[b*1024 + n] = (n == 0) ? sqrtf(ts) : sqrtf(fmaxf(c, 1e-15f));
}
// warp-per-row fused Hs pipeline
__global__ void k_hs(const float* __restrict__ Hsa, const float* __restrict__ MxRaw,
                     const float* __restrict__ xnr,
                     const float* __restrict__ whs, float* __restrict__ lg){
    size_t row = (size_t)blockIdx.x*8 + (threadIdx.x >> 5);
    int lane = threadIdx.x & 31;
    const float* my = MxRaw + row*KKW;
    const float* hx = Hsa + row*KKW;
    float yr[4], x[4];
    float mm = 0.f;
    #pragma unroll
    for (int i = 0; i < 4; i++){
        yr[i] = my[lane + i*32];
        x[i]  = hx[lane + i*32];
        mm += yr[i]*yr[i];
    }
    mm = wsum(mm);
    float mxn = sqrtf(fmaxf(mm, 1e-15f));
    float xnb = xnr[row];
    float fac = tanhf(mxn / xnb * atanhc(xnb)) / mxn;

    float xy = 0.f, x2 = 0.f, y2 = 0.f;
    float y[4];
    #pragma unroll
    for (int i = 0; i < 4; i++){
        y[i] = yr[i] * fac;
        xy += x[i]*y[i]; x2 += x[i]*x[i]; y2 += y[i]*y[i];
    }
    xy = wsum(xy); x2 = wsum(x2); y2 = wsum(y2);
    float den = fmaxf(1.f + 2.f*xy + x2*y2, 1e-15f);
    float c1 = (1.f + 2.f*xy + y2) / den, c2 = (1.f - x2) / den;
    float h[4], hh = 0.f;
    #pragma unroll
    for (int i = 0; i < 4; i++){ h[i] = c1*x[i] + c2*y[i]; hh += h[i]*h[i]; }
    hh = wsum(hh);
    float hn = sqrtf(fmaxf(hh, 1e-15f));
    float fa = atanhc(hn) / hn;
    float gv[4], gg = 0.f;
    #pragma unroll
    for (int i = 0; i < 4; i++){ gv[i] = gelu_exact(fa*h[i]); gg += gv[i]*gv[i]; }
    gg = wsum(gg);
    float gn = sqrtf(fmaxf(gg, 1e-15f));
    float fb = tanhf(gn) / gn;
    float mx = 0.f, xn2 = 0.f;
    #pragma unroll
    for (int i = 0; i < 4; i++){
        float hs = fb * gv[i];
        mx += hs * __ldg(&whs[lane + i*32]);
        xn2 += hs*hs;
    }
    mx = wsum(mx); xn2 = wsum(xn2);
    if (lane == 0){
        float xn = sqrtf(fmaxf(xn2, 1e-15f));
        float mxn2 = sqrtf(fmaxf(mx*mx, 1e-15f));
        lg[row] = tanhf(mxn2 / xn * atanhc(xn)) * mx / mxn2;
    }
}
// dual transpose: z<BB: Hca -> HcaT fp32 + HcaTh bf16 ; z>=BB: Hsa -> HsahT bf16
__global__ void k_tbk2(const float* __restrict__ Hca, const float* __restrict__ Hsa,
                       float* __restrict__ HcaT, __nv_bfloat16* __restrict__ HcaTh,
                       __nv_bfloat16* __restrict__ HsahT){
    __shared__ float tile[32][33];
    int z = blockIdx.z;
    bool isHc = z < BB;
    int b = isHc ? z : z - BB;
    int j0 = blockIdx.x*32, m0 = blockIdx.y*32;
    const float* src = (isHc ? Hca : Hsa) + (size_t)b*NCQ*KKW;
    for (int i = threadIdx.y; i < 32; i += 8)
        tile[i][threadIdx.x] = src[(size_t)(m0+i)*KKW + j0 + threadIdx.x];
    __syncthreads();
    size_t base = (size_t)b*KKW*NCQ;
    for (int i = threadIdx.y; i < 32; i += 8){
        float v = tile[threadIdx.x][i];
        size_t idx = base + (size_t)(j0+i)*NCQ + m0 + threadIdx.x;
        if (isHc){ HcaT[idx] = v; HcaTh[idx] = __float2bfloat16_rn(v); }
        else     { HsahT[idx] = __float2bfloat16_rn(v); }
    }
}
// warp-per-row Hc pipeline: one warp per (b,j) row of 1024; shuffle-only reductions
__global__ void k_hc(const float* __restrict__ HcaT, const float* __restrict__ MxcT,
                     const float* __restrict__ sc, const float* __restrict__ whc,
                     float* __restrict__ amx, float* __restrict__ ass){
    int wg = blockIdx.x*8 + (threadIdx.x >> 5);           // 0..BB*KKW-1
    int b = wg >> 7, j = wg & 127;
    int lane = threadIdx.x & 31;
    float wj = __ldg(&whc[j]);
    const float* xrow = HcaT + ((size_t)(b*KKW + j))*NCQ;
    const float* yrow = MxcT + ((size_t)(b*KKW + j))*NCQ;
    const float* srow = sc + (size_t)b*NCQ;
    float x[32], y[32];
    float sxy = 0.f, sx2 = 0.f, sy2 = 0.f;
    #pragma unroll
    for (int i = 0; i < 32; i++){
        int m = lane + i*32;
        x[i] = xrow[m];
        y[i] = yrow[m] * srow[m];
        sxy += x[i]*y[i]; sx2 += x[i]*x[i]; sy2 += y[i]*y[i];
    }
    sxy = wsum(sxy); sx2 = wsum(sx2); sy2 = wsum(sy2);
    float den = fmaxf(1.f + 2.f*sxy + sx2*sy2, 1e-15f);
    float c1 = (1.f + 2.f*sxy + sy2) / den, c2 = (1.f - sx2) / den;
    float hh = 0.f;
    #pragma unroll
    for (int i = 0; i < 32; i++){ y[i] = c1*x[i] + c2*y[i]; hh += y[i]*y[i]; }  // y := h
    hh = wsum(hh);
    float hn = sqrtf(fmaxf(hh, 1e-15f));
    float fa = atanhc(hn) / hn;
    float gg = 0.f;
    #pragma unroll
    for (int i = 0; i < 32; i++){ x[i] = gelu_exact(fa*y[i]); gg += x[i]*x[i]; } // x := g
    gg = wsum(gg);
    float gn = sqrtf(fmaxf(gg, 1e-15f));
    float fb = tanhf(gn) / gn;
    #pragma unroll
    for (int i = 0; i < 32; i++){
        int m = lane + i*32;
        float hc = fb * x[i];
        atomicAdd(&amx[b*NCQ + m], hc * wj);
        atomicAdd(&ass[b*NCQ + m], hc * hc);
    }
}
// As softmax (reads precomputed logits)
__global__ void k_softmax(const float* __restrict__ lg, float* __restrict__ out){
    int b = blockIdx.x, t = threadIdx.x;                  // 256
    float l[4];
    float lm = -3.4e38f;
    #pragma unroll
    for (int i = 0; i < 4; i++){ l[i] = lg[b*1024 + t + i*256]; lm = fmaxf(lm, l[i]); }
    float M = blockReduceMax(lm);
    float es = 0.f, e[4];
    #pragma unroll
    for (int i = 0; i < 4; i++){ e[i] = expf(l[i] - M); es += e[i]; }
    float S = blockReduceSum(es);
    #pragma unroll
    for (int i = 0; i < 4; i++) out[b*1024 + t + i*256] = e[i] / S;
}
// Ac softmax with fused logit computation from amx/ass
__global__ void k_softmax_ac(const float* __restrict__ amx, const float* __restrict__ ass,
                             float* __restrict__ out){
    int b = blockIdx.x, t = threadIdx.x;                  // 256
    float l[4];
    float lm = -3.4e38f;
    #pragma unroll
    for (int i = 0; i < 4; i++){
        int m = t + i*256;
        float mx = amx[b*NCQ + m];
        float ssv = ass[b*NCQ + m];
        float xn = sqrtf(fmaxf(ssv, 1e-15f));
        float mxn = sqrtf(fmaxf(mx*mx, 1e-15f));
        l[i] = tanhf(mxn / xn * atanhc(xn)) * mx / mxn;
        lm = fmaxf(lm, l[i]);
    }
    float M = blockReduceMax(lm);
    float es = 0.f, e[4];
    #pragma unroll
    for (int i = 0; i < 4; i++){ e[i] = expf(l[i] - M); es += e[i]; }
    float S = blockReduceSum(es);
    #pragma unroll
    for (int i = 0; i < 4; i++) out[b*1024 + t + i*256] = e[i] / S;
}
// dual-branch centroid partials: z<BB sentence (Ls, As), z>=BB comment (Lc, Ac)
__global__ void k_centroid_part(const float* __restrict__ Ls, const float* __restrict__ Lc,
                                const float* __restrict__ outw, int asoff, int acoff,
                                float* __restrict__ part){
    __shared__ float wsh[128];
    int ch = blockIdx.x, z = blockIdx.y;
    bool isS = z < BB;
    int b = isS ? z : z - BB;
    const float* Lx = isS ? Ls : Lc;
    const float* w = outw + (isS ? asoff : acoff) + (size_t)b*NSQ;
    int t = threadIdx.x;                                  // 288, t<257 active
    for (int i = t; i < 128; i += blockDim.x) wsh[i] = w[ch*128 + i];
    __syncthreads();
    if (t < DP1){
        const float* base = Lx + ((size_t)b*NSQ + (size_t)ch*128)*DPAD + t;
        float acc = 0.f;
        for (int n = 0; n < 128; n++) acc += wsh[n] * base[(size_t)n*DPAD];
        part[(z*8 + ch)*DP1 + t] = acc;
    }
}
__global__ void k_centroid_fin(const float* __restrict__ part, float* __restrict__ cs,
                               float* __restrict__ cc){
    __shared__ float t0sh;
    int z = blockIdx.x, t = threadIdx.x;                  // 288
    float acc = 0.f;
    if (t < DP1){
        #pragma unroll
        for (int c = 0; c < 8; c++) acc += part[(z*8 + c)*DP1 + t];
    }
    float sp = (t >= 1 && t < DP1) ? acc*acc : 0.f;
    float ssp = blockReduceSum(sp);
    if (t == 0) t0sh = acc;
    __syncthreads();
    float inner = -t0sh*t0sh + ssp;
    float den = sqrtf(fmaxf(fabsf(inner), 1e-8f));
    float* co = (z < BB) ? cs : cc;
    int b = (z < BB) ? z : z - BB;
    if (t < DP1) co[(size_t)b*DP1 + t] = acc / den;
}
__global__ void k_concat(const float* __restrict__ cs, const float* __restrict__ cc,
                         float* __restrict__ out){
    int b = blockIdx.x, t = threadIdx.x;                  // 256
    float t0s = cs[(size_t)b*DP1];
    float t0c = cc[(size_t)b*DP1];
    float sps = cs[(size_t)b*DP1 + 1 + t];
    float spc = cc[(size_t)b*DP1 + 1 + t];
    float ns  = sqrtf(fmaxf(blockReduceSum(sps*sps), 1e-15f));
    float ncv = sqrtf(fmaxf(blockReduceSum(spc*spc), 1e-15f));
    float zs = acoshf(fmaxf(t0s, 1.f + 1e-7f)) * sps / ns;
    float zc = acoshf(fmaxf(t0c, 1.f + 1e-7f)) * spc / ncv;
    float vn = sqrtf(fmaxf(blockReduceSum(zs*zs + zc*zc), 1e-15f));
    float f = sinhf(vn) / vn;
    float* o = out + (size_t)b*513;
    if (t == 0) o[0] = coshf(vn);
    o[1 + t]       = f * zs;
    o[1 + DD + t]  = f * zc;
}

// ----------------------------- launch ----------------------------------------------
extern "C" void kernel_launch(void* const* d_in, const int* in_sizes, int n_in,
                              void* d_out, int out_size)
{
    const float* sent = (const float*)d_in[0];
    const float* comm = (const float*)d_in[1];
    const float* WlW  = (const float*)d_in[2];
    const float* Wlb  = (const float*)d_in[3];
    const float* WcW  = (const float*)d_in[4];
    const float* Wcb  = (const float*)d_in[5];
    const float* WsW  = (const float*)d_in[6];
    const float* Wsb  = (const float*)d_in[7];
    const float* whs  = (const float*)d_in[8];
    const float* whc  = (const float*)d_in[9];
    float* out = (float*)d_out;
    (void)in_sizes; (void)n_in; (void)out_size;

    float2 *c1, *c1T;
    float *sT, *rl, *Ls, *Lc, *Llin, *Yt, *rss, *css, *amx, *ass, *xnr, *xnc,
          *msc, *Hsa, *Hca, *HcaT, *Mxs, *MxcT, *lgs, *cs, *cc, *part;
    __nv_bfloat16 *Lsh, *Lch, *Llh, *Lbh, *LbTh, *HcaTh, *HsahT, *Wth, *Wtl;
    cudaGetSymbolAddress((void**)&c1,  g_c1);
    cudaGetSymbolAddress((void**)&c1T, g_c1T);
    cudaGetSymbolAddress((void**)&sT,  g_sT);
    cudaGetSymbolAddress((void**)&rl,  g_real);
    cudaGetSymbolAddress((void**)&Ls,  g_Ls);
    cudaGetSymbolAddress((void**)&Lc,  g_Lc);
    cudaGetSymbolAddress((void**)&Llin,g_Llin);
    cudaGetSymbolAddress((void**)&Yt,  g_Yt);
    cudaGetSymbolAddress((void**)&Wth, g_Wth);
    cudaGetSymbolAddress((void**)&Wtl, g_Wtl);
    cudaGetSymbolAddress((void**)&Lsh, g_Lsh);
    cudaGetSymbolAddress((void**)&Lch, g_Lch);
    cudaGetSymbolAddress((void**)&Llh, g_Llh);
    cudaGetSymbolAddress((void**)&Lbh, g_Lbh);
    cudaGetSymbolAddress((void**)&LbTh,g_LbTh);
    cudaGetSymbolAddress((void**)&HcaTh,g_HcaTh);
    cudaGetSymbolAddress((void**)&HsahT,g_HsahT);
    cudaGetSymbolAddress((void**)&rss, g_rss);
    cudaGetSymbolAddress((void**)&css, g_css);
    cudaGetSymbolAddress((void**)&amx, g_amx);
    cudaGetSymbolAddress((void**)&ass, g_ass);
    cudaGetSymbolAddress((void**)&xnr, g_xnr);
    cudaGetSymbolAddress((void**)&xnc, g_xnc);
    cudaGetSymbolAddress((void**)&msc, g_msc);
    cudaGetSymbolAddress((void**)&Hsa, g_Hsa);
    cudaGetSymbolAddress((void**)&Hca, g_Hca);
    cudaGetSymbolAddress((void**)&HcaT,g_HcaT);
    cudaGetSymbolAddress((void**)&Mxs, g_Mxs);
    cudaGetSymbolAddress((void**)&MxcT,g_MxcT);
    cudaGetSymbolAddress((void**)&lgs, g_lgs);
    cudaGetSymbolAddress((void**)&cs,  g_cs);
    cudaGetSymbolAddress((void**)&cc,  g_cc);
    cudaGetSymbolAddress((void**)&part,g_part);

    const int AS_OFF = BB*513;             // 16416
    const int AC_OFF = AS_OFF + BB*NSQ;    // 49184

    k_setup<<<32 + DP1 + 2*KP1, 1024>>>(WlW, WsW, WcW, rss, css, amx, ass);

    // ---- dual-branch FFT2 (stage-0 fused, Hermitian-compact) + euclid_to_lorentz ----
    k_fft256<<<2*BB*NSQ/4, dim3(64,4)>>>(sent, comm, c1);
    k_transpose_ch<<<dim3(5, NSQ/32, 2*BB), dim3(32,8)>>>(c1, c1T);
    k_fft1024<<<2*BB*DH, 256>>>(c1T, sT);
    k_transpose_fh<<<dim3(5, NSQ/32, 2*BB), dim3(32,8)>>>(sT, rl);
    k_e2l<<<2*BB*NSQ, 256>>>(rl, Ls, Lc, Lsh, Lch);

    // ---- linear layers (bf16 with split-B weights; dead time-column skipped) ----
    k_bgemm<1,1><<<dim3(2,256,1),256>>>(Lch, Wth + (size_t)1*DPAD, Wtl + (size_t)1*DPAD,
        Wlb + 1, Llin + 1, nullptr, nullptr,
        BB*NCQ, 256, DP1, DPAD, DPAD, DPAD, 0, 0, 0, 0, 0, nullptr, nullptr);
    k_fix_time<<<BB*NCQ/8, 256>>>(Llin, Llh);

    k_bgemm<1,1><<<dim3(1,256,1),256>>>(Lsh, Wth + (size_t)385*DPAD, Wtl + (size_t)385*DPAD,
        Wsb + 1, Yt, nullptr, nullptr,
        BB*NSQ, KKW, DP1, DPAD, DPAD, KKW, 0, 0, 0, 0, 0, nullptr, nullptr);
    k_poincare<<<BB*NSQ/8, 256>>>(Yt, Hsa);

    k_bgemm<1,1><<<dim3(1,256,1),256>>>(Lch, Wth + (size_t)641*DPAD, Wtl + (size_t)641*DPAD,
        Wcb + 1, Yt, nullptr, nullptr,
        BB*NCQ, KKW, DP1, DPAD, DPAD, KKW, 0, 0, 0, 0, 0, nullptr, nullptr);
    k_poincare<<<BB*NCQ/8, 256>>>(Yt, Hca);

    // ---- big einsum (bf16) + lorentz_act + fused norms, coalesced dual bf16 out ----
    k_bgemm<2,0><<<dim3(8,8,BB),256>>>(Lsh, Llh, nullptr, nullptr, nullptr, Lbh, LbTh,
        NSQ, NCQ, DP1, DPAD, DPAD, NCQ, NSQ,
        (long)NSQ*DPAD, (long)NCQ*DPAD, 0, (long)NSQ*NCQ, rss, css);
    k_nfin<<<BB, 1024>>>(rss, css, Lbh, LbTh, xnr, xnc);

    // ---- transposes for mobius operands ----
    k_tbk2<<<dim3(4, 32, 2*BB), dim3(32,8)>>>(Hca, Hsa, HcaT, HcaTh, HsahT);

    // ---- mobius_matvec GEMMs (bf16); MxcT GEMM fuses mscale ----
    k_bgemm<0,0><<<dim3(1,8,BB),256>>>(Lbh, HcaTh, nullptr, nullptr, Mxs, nullptr, nullptr,
        NSQ, KKW, NCQ, NCQ, NCQ, KKW, 0,
        (long)NSQ*NCQ, (long)KKW*NCQ, (long)NSQ*KKW, 0, nullptr, nullptr);
    k_bgemm<3,0><<<dim3(8,1,BB),256>>>(HsahT, LbTh, nullptr, nullptr, MxcT, nullptr, nullptr,
        KKW, NCQ, NSQ, NSQ, NSQ, NCQ, 0,
        (long)KKW*NSQ, (long)NCQ*NSQ, (long)KKW*NCQ, 0, xnc, msc);

    // ---- mobius_add + gelu pipelines + attention logits ----
    k_hs<<<BB*NSQ/8, 256>>>(Hsa, Mxs, xnr, whs, lgs);
    k_hc<<<BB*KKW/8, 256>>>(HcaT, MxcT, msc, whc, amx, ass);

    // ---- softmaxes straight into output (Ac logit fused) ----
    k_softmax<<<BB, 256>>>(lgs, out + AS_OFF);
    k_softmax_ac<<<BB, 256>>>(amx, ass, out + AC_OFF);

    // ---- centroids (dual-branch) + concat ----
    k_centroid_part<<<dim3(8, 2*BB), 288>>>(Ls, Lc, out, AS_OFF, AC_OFF, part);
    k_centroid_fin<<<2*BB, 288>>>(part, cs, cc);
    k_concat<<<BB, 256>>>(cs, cc, out);
}

// round 16
// speedup vs baseline: 1.2282x; 1.0188x over previous
#include <cuda_runtime.h>
#include <cuda_bf16.h>
#include <math.h>
#include <stdint.h>

#define BB  32
#define NSQ 1024
#define NCQ 1024
#define DD  256
#define DP1 257
#define DPAD 272
#define KKW 128
#define KP1 129
#define DH  129   // Hermitian-reduced column count

// ----------------------------- scratch (static device globals; no runtime alloc) ---
static __device__ float2 g_c1 [(size_t)2*BB*NSQ*DH];
static __device__ float2 g_c1T[(size_t)2*BB*DH*NSQ];
static __device__ float  g_sT [(size_t)2*BB*DH*NSQ];
static __device__ float  g_real[(size_t)2*BB*NSQ*DH];
static __device__ float  g_Ls [(size_t)BB*NSQ*DPAD];
static __device__ float  g_Lc [(size_t)BB*NCQ*DPAD];
static __device__ __align__(16) __nv_bfloat16 g_Wth[(size_t)896*DPAD]; // Wl@0,Ws@384,Wc@640
static __device__ __align__(16) __nv_bfloat16 g_Wtl[(size_t)896*DPAD]; // lo residuals
static __device__ __align__(16) __nv_bfloat16 g_Lsh [(size_t)BB*NSQ*DPAD];
static __device__ __align__(16) __nv_bfloat16 g_Lch [(size_t)BB*NCQ*DPAD];
static __device__ __align__(16) __nv_bfloat16 g_Llh [(size_t)BB*NCQ*DPAD];
static __device__ __align__(16) __nv_bfloat16 g_Lbh [(size_t)BB*NSQ*NCQ];
static __device__ __align__(16) __nv_bfloat16 g_LbTh[(size_t)BB*NCQ*NSQ];
static __device__ __align__(16) __nv_bfloat16 g_HcaTh[(size_t)BB*KKW*NCQ];
static __device__ __align__(16) __nv_bfloat16 g_HsahT[(size_t)BB*KKW*NSQ];
static __device__ float  g_rss[BB*NSQ];
static __device__ float  g_css[BB*NCQ];
static __device__ float  g_amx[BB*NCQ];
static __device__ float  g_ass[BB*NCQ];
static __device__ float  g_lacc[BB*NCQ];      // Wl row-SSQ accumulator
static __device__ float  g_xnr[BB*NSQ];
static __device__ float  g_xnc[BB*NCQ];
static __device__ float  g_msc[BB*NCQ];
static __device__ float  g_Hsa[(size_t)BB*NSQ*KKW];
static __device__ float  g_Hca[(size_t)BB*NCQ*KKW];
static __device__ float  g_HcaT[(size_t)BB*KKW*NCQ];
static __device__ float  g_Mxs[(size_t)BB*NSQ*KKW];
static __device__ float  g_MxcT[(size_t)BB*KKW*NCQ];
static __device__ float  g_lgs[BB*NSQ];
static __device__ float  g_cs [BB*DP1];
static __device__ float  g_cc [BB*DP1];
static __device__ float  g_part[2*BB*8*DP1];
static __device__ float2 g_tw1024[1024];
static __device__ float2 g_tw256[256];

// ----------------------------- helpers ---------------------------------------------
__device__ __forceinline__ float atanhc(float x){
    x = fminf(fmaxf(x, -1.f + 1e-5f), 1.f - 1e-5f);
    return 0.5f * (log1pf(x) - log1pf(-x));
}
__device__ __forceinline__ float gelu_exact(float v){
    return 0.5f * v * (1.f + erff(v * 0.70710678118654752f));
}
__device__ __forceinline__ float2 cmul(float2 a, float2 b){
    return make_float2(a.x*b.x - a.y*b.y, a.x*b.y + a.y*b.x);
}
__device__ __forceinline__ float2 cadd(float2 a, float2 b){ return make_float2(a.x+b.x, a.y+b.y); }
__device__ __forceinline__ float2 csub(float2 a, float2 b){ return make_float2(a.x-b.x, a.y-b.y); }

__device__ __forceinline__ float wsum(float v){
    #pragma unroll
    for (int o = 16; o; o >>= 1) v += __shfl_xor_sync(0xffffffffu, v, o);
    return v;
}
__device__ __forceinline__ float blockReduceSum(float v){
    __shared__ float sh[32];
    #pragma unroll
    for (int o = 16; o; o >>= 1) v += __shfl_down_sync(0xffffffffu, v, o);
    int lane = threadIdx.x & 31, w = threadIdx.x >> 5;
    if (lane == 0) sh[w] = v;
    __syncthreads();
    int nw = (blockDim.x + 31) >> 5;
    v = (threadIdx.x < (unsigned)nw) ? sh[threadIdx.x] : 0.f;
    if (w == 0){
        #pragma unroll
        for (int o = 16; o; o >>= 1) v += __shfl_down_sync(0xffffffffu, v, o);
        if (lane == 0) sh[0] = v;
    }
    __syncthreads();
    float r = sh[0];
    __syncthreads();
    return r;
}
__device__ __forceinline__ float blockReduceMax(float v){
    __shared__ float sh[32];
    #pragma unroll
    for (int o = 16; o; o >>= 1) v = fmaxf(v, __shfl_down_sync(0xffffffffu, v, o));
    int lane = threadIdx.x & 31, w = threadIdx.x >> 5;
    if (lane == 0) sh[w] = v;
    __syncthreads();
    int nw = (blockDim.x + 31) >> 5;
    v = (threadIdx.x < (unsigned)nw) ? sh[threadIdx.x] : -3.4e38f;
    if (w == 0){
        #pragma unroll
        for (int o = 16; o; o >>= 1) v = fmaxf(v, __shfl_down_sync(0xffffffffu, v, o));
        if (lane == 0) sh[0] = v;
    }
    __syncthreads();
    float r = sh[0];
    __syncthreads();
    return r;
}
__device__ __forceinline__ void mma_bf16(float* c, const uint32_t* a, const uint32_t* b){
    asm volatile("mma.sync.aligned.m16n8k16.row.col.f32.bf16.bf16.f32 "
        "{%0,%1,%2,%3}, {%4,%5,%6,%7}, {%8,%9}, {%0,%1,%2,%3};"
        : "+f"(c[0]), "+f"(c[1]), "+f"(c[2]), "+f"(c[3])
        : "r"(a[0]), "r"(a[1]), "r"(a[2]), "r"(a[3]), "r"(b[0]), "r"(b[1]));
}
__device__ __forceinline__ void cpa16(uint32_t dsh, const void* src){
    asm volatile("cp.async.ca.shared.global [%0], [%1], 16;" :: "r"(dsh), "l"(src));
}
#define CP_COMMIT() asm volatile("cp.async.commit_group;" ::: "memory")
#define CP_WAIT1()  asm volatile("cp.async.wait_group 1;" ::: "memory")
#define CP_WAIT0()  asm volatile("cp.async.wait_group 0;" ::: "memory")

// ----------------------------- merged setup kernel ---------------------------------
__global__ void k_setup(const float* __restrict__ Wl, const float* __restrict__ Ws,
                        const float* __restrict__ Wc,
                        float* __restrict__ a, float* __restrict__ b,
                        float* __restrict__ c, float* __restrict__ d,
                        float* __restrict__ e){
    int blk = blockIdx.x;
    int t = threadIdx.x;                       // 1024
    if (blk < 32){
        int i = blk*1024 + t;
        a[i] = 0.f; b[i] = 0.f; c[i] = 0.f; d[i] = 0.f; e[i] = 0.f;
        if (blk == 0){
            double ang = -6.283185307179586476925287 * (double)t / 1024.0;
            g_tw1024[t] = make_float2((float)cos(ang), (float)sin(ang));
            if (t < 256){
                double a2 = -6.283185307179586476925287 * (double)t / 256.0;
                g_tw256[t] = make_float2((float)cos(a2), (float)sin(a2));
            }
        }
        return;
    }
    int r = blk - 32;                          // 0..514
    if (t >= DP1) return;
    const float* src; size_t drow;
    if (r < DP1){ src = Wl + (size_t)r*DP1; drow = (size_t)r*DPAD; }
    else if (r < DP1 + KP1){ int rr = r - DP1; src = Ws + (size_t)rr*DP1; drow = (size_t)(384+rr)*DPAD; }
    else { int rr = r - DP1 - KP1; src = Wc + (size_t)rr*DP1; drow = (size_t)(640+rr)*DPAD; }
    float w = src[t];
    __nv_bfloat16 hi = __float2bfloat16_rn(w);
    g_Wth[drow + t] = hi;
    g_Wtl[drow + t] = __float2bfloat16_rn(w - __bfloat162float(hi));
}

// ----------------------------- radix-4 Stockham FFT kernels ------------------------
__global__ void k_fft256(const float* __restrict__ sent, const float* __restrict__ comm,
                         float2* __restrict__ out){
    __shared__ float2 bufA[4][256];
    __shared__ float2 bufB[4][256];
    __shared__ float2 tws[256];
    __shared__ float  rsum[4][2];
    int tx = threadIdx.x;                      // 64
    int ty = threadIdx.y;                      // 4
    int tid = ty*64 + tx;
    size_t row = (size_t)blockIdx.x*4 + ty;
    bool do_log = row >= (size_t)BB*NSQ;
    const float* x = do_log ? (comm + (row - (size_t)BB*NSQ)*256) : (sent + row*256);
    tws[tid] = g_tw256[tid];

    float v0 = x[tx], v1 = x[tx+64], v2 = x[tx+128], v3 = x[tx+192];
    float ss = v0*v0 + v1*v1 + v2*v2 + v3*v3;
    #pragma unroll
    for (int o = 16; o; o >>= 1) ss += __shfl_down_sync(0xffffffffu, ss, o);
    if ((tx & 31) == 0) rsum[ty][tx >> 5] = ss;
    __syncthreads();
    if (do_log){
        float tot = rsum[ty][0] + rsum[ty][1];
        float yn = sqrtf(fmaxf(tot, 1e-15f));
        float f = atanhc(yn) / yn;
        v0 *= f; v1 *= f; v2 *= f; v3 *= f;
    }
    {
        float pa = v0 + v2, pb = v0 - v2;
        float pc = v1 + v3, pd = v1 - v3;
        bufA[ty][4*tx]     = make_float2(pa + pc, 0.f);
        bufA[ty][4*tx + 1] = make_float2(pb, -pd);
        bufA[ty][4*tx + 2] = make_float2(pa - pc, 0.f);
        bufA[ty][4*tx + 3] = make_float2(pb,  pd);
    }
    __syncthreads();

    float2* X = &bufA[ty][0];
    float2* Y = &bufB[ty][0];
    #pragma unroll
    for (int s = 1; s < 4; s++){
        int Ns = 1 << (2*s);
        int p = tx & (Ns - 1);
        float2 w1 = tws[p * (64/Ns)];
        float2 w2 = cmul(w1, w1);
        float2 w3 = cmul(w2, w1);
        float2 a0 = X[tx];
        float2 a1 = cmul(X[tx + 64],  w1);
        float2 a2 = cmul(X[tx + 128], w2);
        float2 a3 = cmul(X[tx + 192], w3);
        float2 pa = cadd(a0, a2), pb = csub(a0, a2);
        float2 pc = cadd(a1, a3), pd = csub(a1, a3);
        float2 dneg = make_float2(pd.y, -pd.x);
        float2 dpos = make_float2(-pd.y, pd.x);
        int idxD = ((tx >> (2*s)) << (2*s + 2)) + p;
        Y[idxD]          = cadd(pa, pc);
        Y[idxD + Ns]     = cadd(pb, dneg);
        Y[idxD + 2*Ns]   = csub(pa, pc);
        Y[idxD + 3*Ns]   = cadd(pb, dpos);
        __syncthreads();
        float2* tmp = X; X = Y; Y = tmp;
    }
    out[row*DH + tx]      = X[tx];
    out[row*DH + tx + 64] = X[tx + 64];
    if (tx == 0) out[row*DH + 128] = X[128];
}

__global__ void k_fft1024(const float2* __restrict__ in, float* __restrict__ outr){
    __shared__ float2 bufA[1024];
    __shared__ float2 bufB[1024];
    int t = threadIdx.x;                       // 256
    size_t row = blockIdx.x;
    const float2* src = in + row*1024;
    float2 a0 = src[t], a1 = src[t+256], a2 = src[t+512], a3 = src[t+768];
    {
        float2 pa = cadd(a0, a2), pb = csub(a0, a2);
        float2 pc = cadd(a1, a3), pd = csub(a1, a3);
        bufA[4*t]     = cadd(pa, pc);
        bufA[4*t + 1] = cadd(pb, make_float2(pd.y, -pd.x));
        bufA[4*t + 2] = csub(pa, pc);
        bufA[4*t + 3] = cadd(pb, make_float2(-pd.y, pd.x));
    }
    __syncthreads();
    float2* X = bufA;
    float2* Y = bufB;
    #pragma unroll
    for (int s = 1; s < 5; s++){
        int Ns = 1 << (2*s);
        int p = t & (Ns - 1);
        float2 w1 = __ldg(&g_tw1024[p * (256/Ns)]);
        float2 w2 = cmul(w1, w1);
        float2 w3 = cmul(w2, w1);
        float2 b0 = X[t];
        float2 b1 = cmul(X[t + 256], w1);
        float2 b2 = cmul(X[t + 512], w2);
        float2 b3 = cmul(X[t + 768], w3);
        float2 pa = cadd(b0, b2), pb = csub(b0, b2);
        float2 pc = cadd(b1, b3), pd = csub(b1, b3);
        float2 dneg = make_float2(pd.y, -pd.x);
        float2 dpos = make_float2(-pd.y, pd.x);
        int idxD = ((t >> (2*s)) << (2*s + 2)) + p;
        Y[idxD]        = cadd(pa, pc);
        Y[idxD + Ns]   = cadd(pb, dneg);
        Y[idxD + 2*Ns] = csub(pa, pc);
        Y[idxD + 3*Ns] = cadd(pb, dpos);
        __syncthreads();
        float2* tmp = X; X = Y; Y = tmp;
    }
    #pragma unroll
    for (int i = 0; i < 4; i++)
        outr[row*1024 + t + i*256] = X[t + i*256].x;
}

__global__ void k_transpose_ch(const float2* __restrict__ in, float2* __restrict__ out){
    __shared__ float2 tile[32][33];
    int b = blockIdx.z;
    int c0 = blockIdx.x*32, r0 = blockIdx.y*32;
    const float2* src = in + (size_t)b*NSQ*DH;
    for (int i = threadIdx.y; i < 32; i += 8){
        int d = c0 + threadIdx.x;
        tile[i][threadIdx.x] = (d < DH) ? src[(size_t)(r0+i)*DH + d]
                                        : make_float2(0.f, 0.f);
    }
    __syncthreads();
    float2* dst = out + (size_t)b*DH*NSQ;
    for (int i = threadIdx.y; i < 32; i += 8){
        int d = c0 + i;
        if (d < DH) dst[(size_t)d*NSQ + r0 + threadIdx.x] = tile[threadIdx.x][i];
    }
}
__global__ void k_transpose_fh(const float* __restrict__ in, float* __restrict__ out){
    __shared__ float tile[32][33];
    int b = blockIdx.z;
    int d0 = blockIdx.x*32, n0 = blockIdx.y*32;
    const float* src = in + (size_t)b*DH*NSQ;
    for (int i = threadIdx.y; i < 32; i += 8){
        int d = d0 + i;
        tile[i][threadIdx.x] = (d < DH) ? src[(size_t)d*NSQ + n0 + threadIdx.x] : 0.f;
    }
    __syncthreads();
    float* dst = out + (size_t)b*NSQ*DH;
    int d = d0 + threadIdx.x;
    if (d < DH)
        for (int i = threadIdx.y; i < 32; i += 8)
            dst[(size_t)(n0+i)*DH + d] = tile[threadIdx.x][i];
}

// fused Hermitian mirror + euclid_to_lorentz; fp32 (centroid) + bf16 (GEMM operands)
__global__ void k_e2l(const float* __restrict__ rl, float* __restrict__ Ls,
                      float* __restrict__ Lc, __nv_bfloat16* __restrict__ Lsh,
                      __nv_bfloat16* __restrict__ Lch){
    size_t row = blockIdx.x;                   // 0 .. 2*BB*NSQ-1
    int t = threadIdx.x;                       // 256
    size_t bb = row >> 10;
    int n = (int)(row & 1023);
    float v;
    if (t < DH){
        v = rl[(bb*NSQ + n)*DH + t];
    } else {
        int srcn = (1024 - n) & 1023;
        v = rl[(bb*NSQ + srcn)*DH + (256 - t)];
    }
    float ss = blockReduceSum(v*v);
    float xn = sqrtf(fmaxf(ss, 1e-15f)) + 1e-5f;
    float scl = fminf(1.f, 2.0f / xn);
    v *= scl;
    float vn = sqrtf(fmaxf(ss*scl*scl, 1e-15f));
    float f = sinhf(vn) / vn;
    bool isS = bb < BB;
    float* out = isS ? Ls : Lc;
    __nv_bfloat16* outh = isS ? Lsh : Lch;
    size_t orow = isS ? row : row - (size_t)BB*NSQ;
    float tv = coshf(vn), sv = f * v;
    if (t == 0){ out[orow*DPAD] = tv; outh[orow*DPAD] = __float2bfloat16_rn(tv); }
    out[orow*DPAD + 1 + t] = sv;
    outh[orow*DPAD + 1 + t] = __float2bfloat16_rn(sv);
    if (t < DPAD - DP1) out[orow*DPAD + DP1 + t] = 0.f;
}

// --------- bf16 GEMM (m16n8k16): A[m][k], B[n][k] --------------------------------
//  MODE 0: plain fp32 C            MODE 2: einsum epilogue
//  MODE 3: fp32 C + fused mscale (rss=xnc in, css=msc out)
//  MODE 4: bias + fused poincare -> fp32 C (requires gridDim.x==1, N==128)
//  MODE 5: bias + bf16 Cb store + global row-SSQ atomics into rss
template<int MODE, int SPLITB>
__global__ void k_bgemm(const __nv_bfloat16* __restrict__ A,
                        const __nv_bfloat16* __restrict__ Bm,
                        const __nv_bfloat16* __restrict__ Bl,
                        const float* __restrict__ bias,
                        float* __restrict__ C,
                        __nv_bfloat16* __restrict__ Cb, __nv_bfloat16* __restrict__ CbT,
                        int M, int N, int Klen, int lda, int ldb, int ldc, int ldt,
                        long sA, long sB, long sC, long sCb,
                        float* __restrict__ rss, float* __restrict__ css)
{
    __shared__ __align__(16) char smemraw[49152];
    __nv_bfloat16* AsBuf = reinterpret_cast<__nv_bfloat16*>(smemraw);
    __nv_bfloat16* BlBuf = reinterpret_cast<__nv_bfloat16*>(smemraw + 12288);
    __nv_bfloat16* BsBuf = reinterpret_cast<__nv_bfloat16*>(smemraw + 24576);

    int bz = blockIdx.z;
    A  += (size_t)bz * sA;
    Bm += (size_t)bz * sB;
    if (MODE != 2) C += (size_t)bz * sC;
    else { Cb += (size_t)bz * sCb; CbT += (size_t)bz * sCb; }
    int bm = blockIdx.y * 128, bn = blockIdx.x * 128;
    int tid = threadIdx.x;
    int wid = tid >> 5, lane = tid & 31;
    int wm = (wid >> 2) * 64;
    int wn = (wid & 3) * 32;
    int g = lane >> 2, tg = lane & 3;
    int KT = (Klen + 15) >> 4;

    uint32_t asBase = (uint32_t)__cvta_generic_to_shared(AsBuf);
    uint32_t blBase = (uint32_t)__cvta_generic_to_shared(BlBuf);
    uint32_t bsBase = (uint32_t)__cvta_generic_to_shared(BsBuf);

    auto issueA = [&](int st, int k0){
        int mm = tid >> 1, c = tid & 1;
        cpa16(asBase + (uint32_t)(st*6144) + (mm*24 + c*8)*2,
              A + (size_t)(bm+mm)*lda + k0 + c*8);
    };
    auto issueB = [&](int st, int k0){
        int nn = tid >> 1, c = tid & 1;
        cpa16(bsBase + (uint32_t)(st*6144) + (nn*24 + c*8)*2,
              Bm + (size_t)(bn+nn)*ldb + k0 + c*8);
        if (SPLITB)
            cpa16(blBase + (uint32_t)(st*6144) + (nn*24 + c*8)*2,
                  Bl + (size_t)(bn+nn)*ldb + k0 + c*8);
    };

    float acc[4][4][4];
    #pragma unroll
    for (int mi = 0; mi < 4; mi++)
        #pragma unroll
        for (int ni = 0; ni < 4; ni++)
            #pragma unroll
            for (int r = 0; r < 4; r++) acc[mi][ni][r] = 0.f;

    issueA(0, 0); issueB(0, 0);
    CP_COMMIT();

    for (int kt = 0; kt < KT; kt++){
        int st = kt & 1;
        if (kt + 1 < KT){
            issueA(st ^ 1, (kt+1)*16);
            issueB(st ^ 1, (kt+1)*16);
            CP_COMMIT();
            CP_WAIT1();
        } else {
            CP_WAIT0();
        }
        __syncthreads();

        const uint32_t* pA = reinterpret_cast<const uint32_t*>(AsBuf + st*3072);
        const uint32_t* pB = reinterpret_cast<const uint32_t*>(BsBuf + st*3072);
        uint32_t bhf[4][2];
        #pragma unroll
        for (int ni = 0; ni < 4; ni++){
            int n = wn + ni*8 + g;
            bhf[ni][0] = pB[n*12 + tg];
            bhf[ni][1] = pB[n*12 + tg + 4];
        }
        uint32_t blf[4][2];
        if (SPLITB){
            const uint32_t* pL = reinterpret_cast<const uint32_t*>(BlBuf + st*3072);
            #pragma unroll
            for (int ni = 0; ni < 4; ni++){
                int n = wn + ni*8 + g;
                blf[ni][0] = pL[n*12 + tg];
                blf[ni][1] = pL[n*12 + tg + 4];
            }
        }
        #pragma unroll
        for (int mi = 0; mi < 4; mi++){
            int m = wm + mi*16;
            uint32_t ahf[4];
            ahf[0] = pA[(m+g)*12   + tg];
            ahf[1] = pA[(m+g+8)*12 + tg];
            ahf[2] = pA[(m+g)*12   + tg + 4];
            ahf[3] = pA[(m+g+8)*12 + tg + 4];
            #pragma unroll
            for (int ni = 0; ni < 4; ni++){
                mma_bf16(acc[mi][ni], ahf, bhf[ni]);
                if (SPLITB) mma_bf16(acc[mi][ni], ahf, blf[ni]);
            }
        }
        __syncthreads();
    }

    if (MODE == 0 || MODE == 3){
        #pragma unroll
        for (int mi = 0; mi < 4; mi++)
            #pragma unroll
            for (int ni = 0; ni < 4; ni++){
                int col = bn + wn + ni*8 + 2*tg;
                #pragma unroll
                for (int r = 0; r < 4; r++){
                    int gm = bm + wm + mi*16 + g + (r >= 2 ? 8 : 0);
                    int gn = col + (r & 1);
                    if (gn >= N) continue;
                    C[(size_t)gm*ldc + gn] = acc[mi][ni][r];
                }
            }
        if (MODE == 3){
            __syncthreads();
            float* colss = reinterpret_cast<float*>(smemraw);
            if (tid < 128) colss[tid] = 0.f;
            __syncthreads();
            #pragma unroll
            for (int ni = 0; ni < 4; ni++){
                #pragma unroll
                for (int cb = 0; cb < 2; cb++){
                    float cp = 0.f;
                    #pragma unroll
                    for (int mi = 0; mi < 4; mi++){
                        float a0 = acc[mi][ni][cb], a1 = acc[mi][ni][2+cb];
                        cp += a0*a0 + a1*a1;
                    }
                    cp += __shfl_down_sync(0xffffffffu, cp, 4);
                    cp += __shfl_down_sync(0xffffffffu, cp, 8);
                    cp += __shfl_down_sync(0xffffffffu, cp, 16);
                    if (g == 0)
                        atomicAdd(&colss[wn + ni*8 + 2*tg + cb], cp);
                }
            }
            __syncthreads();
            if (tid < 128){
                float ssv = colss[tid];
                float mxn = sqrtf(fmaxf(ssv, 1e-15f));
                float xnv = rss[(size_t)bz*1024 + bn + tid];       // xnc
                css[(size_t)bz*1024 + bn + tid] =                  // msc
                    tanhf(mxn / xnv * atanhc(xnv)) / mxn;
            }
        }
    } else if (MODE == 4){
        // bias + fused poincare (single N-block: each block owns complete rows)
        #pragma unroll
        for (int mi = 0; mi < 4; mi++)
            #pragma unroll
            for (int ni = 0; ni < 4; ni++){
                int col = wn + ni*8 + 2*tg;
                #pragma unroll
                for (int r = 0; r < 4; r++)
                    acc[mi][ni][r] += bias[col + (r & 1)];
            }
        __syncthreads();
        float* rowss = reinterpret_cast<float*>(smemraw);
        if (tid < 128) rowss[tid] = 0.f;
        __syncthreads();
        #pragma unroll
        for (int mi = 0; mi < 4; mi++){
            #pragma unroll
            for (int half = 0; half < 2; half++){
                float rp = 0.f;
                #pragma unroll
                for (int ni = 0; ni < 4; ni++){
                    float a0 = acc[mi][ni][half*2], a1 = acc[mi][ni][half*2+1];
                    rp += a0*a0 + a1*a1;
                }
                rp += __shfl_down_sync(0xffffffffu, rp, 1);
                rp += __shfl_down_sync(0xffffffffu, rp, 2);
                if (tg == 0)
                    atomicAdd(&rowss[wm + mi*16 + g + half*8], rp);
            }
        }
        __syncthreads();
        #pragma unroll
        for (int mi = 0; mi < 4; mi++){
            float inv0 = 1.f / (sqrtf(rowss[wm + mi*16 + g]     + 1.f) + 1.f);
            float inv1 = 1.f / (sqrtf(rowss[wm + mi*16 + g + 8] + 1.f) + 1.f);
            #pragma unroll
            for (int ni = 0; ni < 4; ni++){
                int col = wn + ni*8 + 2*tg;
                #pragma unroll
                for (int r = 0; r < 4; r++){
                    int gm = bm + wm + mi*16 + g + (r >= 2 ? 8 : 0);
                    float inv = (r >= 2) ? inv1 : inv0;
                    C[(size_t)gm*ldc + col + (r & 1)] = acc[mi][ni][r] * inv;
                }
            }
        }
    } else if (MODE == 5){
        // bias + bf16 Cb store + global row-SSQ atomics into rss
        #pragma unroll
        for (int mi = 0; mi < 4; mi++)
            #pragma unroll
            for (int ni = 0; ni < 4; ni++){
                int col = bn + wn + ni*8 + 2*tg;
                #pragma unroll
                for (int r = 0; r < 4; r++){
                    float v = acc[mi][ni][r] + bias[col + (r & 1)];
                    acc[mi][ni][r] = v;
                    int gm = bm + wm + mi*16 + g + (r >= 2 ? 8 : 0);
                    Cb[(size_t)gm*ldc + col + (r & 1)] = __float2bfloat16_rn(v);
                }
            }
        #pragma unroll
        for (int mi = 0; mi < 4; mi++){
            #pragma unroll
            for (int half = 0; half < 2; half++){
                float rp = 0.f;
                #pragma unroll
                for (int ni = 0; ni < 4; ni++){
                    float a0 = acc[mi][ni][half*2], a1 = acc[mi][ni][half*2+1];
                    rp += a0*a0 + a1*a1;
                }
                rp += __shfl_down_sync(0xffffffffu, rp, 1);
                rp += __shfl_down_sync(0xffffffffu, rp, 2);
                if (tg == 0)
                    atomicAdd(&rss[bm + wm + mi*16 + g + half*8], rp);
            }
        }
    } else {
        // MODE 2: gelu (global col0 -> 0) + SSQ atomics + smem-staged coalesced out
        #pragma unroll
        for (int mi = 0; mi < 4; mi++)
            #pragma unroll
            for (int ni = 0; ni < 4; ni++){
                int col = bn + wn + ni*8 + 2*tg;
                #pragma unroll
                for (int r = 0; r < 4; r++){
                    int gn = col + (r & 1);
                    acc[mi][ni][r] = (gn == 0) ? 0.f : gelu_exact(acc[mi][ni][r]);
                }
            }
        #pragma unroll
        for (int mi = 0; mi < 4; mi++){
            #pragma unroll
            for (int half = 0; half < 2; half++){
                float rp = 0.f;
                #pragma unroll
                for (int ni = 0; ni < 4; ni++){
                    float a0 = acc[mi][ni][half*2], a1 = acc[mi][ni][half*2+1];
                    rp += a0*a0 + a1*a1;
                }
                rp += __shfl_down_sync(0xffffffffu, rp, 1);
                rp += __shfl_down_sync(0xffffffffu, rp, 2);
                if (tg == 0)
                    atomicAdd(&rss[(size_t)bz*1024 + bm + wm + mi*16 + g + half*8], rp);
            }
        }
        #pragma unroll
        for (int ni = 0; ni < 4; ni++){
            #pragma unroll
            for (int cb = 0; cb < 2; cb++){
                float cp = 0.f;
                #pragma unroll
                for (int mi = 0; mi < 4; mi++){
                    float a0 = acc[mi][ni][cb], a1 = acc[mi][ni][2+cb];
                    cp += a0*a0 + a1*a1;
                }
                cp += __shfl_down_sync(0xffffffffu, cp, 4);
                cp += __shfl_down_sync(0xffffffffu, cp, 8);
                cp += __shfl_down_sync(0xffffffffu, cp, 16);
                if (g == 0)
                    atomicAdd(&css[(size_t)bz*1024 + bn + wn + ni*8 + 2*tg + cb], cp);
            }
        }
        __syncthreads();
        constexpr int TS = 136;
        __nv_bfloat16* tile = reinterpret_cast<__nv_bfloat16*>(smemraw);
        #pragma unroll
        for (int mi = 0; mi < 4; mi++)
            #pragma unroll
            for (int ni = 0; ni < 4; ni++){
                int ln = wn + ni*8 + 2*tg;
                #pragma unroll
                for (int r = 0; r < 4; r++){
                    int lm = wm + mi*16 + g + (r >= 2 ? 8 : 0);
                    tile[lm*TS + ln + (r & 1)] = __float2bfloat16_rn(acc[mi][ni][r]);
                }
            }
        __syncthreads();
        {
            int row = tid >> 1, half = tid & 1;
            const uint4* srcv = reinterpret_cast<const uint4*>(tile + row*TS + half*64);
            uint4* dstv = reinterpret_cast<uint4*>(Cb + (size_t)(bm+row)*ldc + bn + half*64);
            #pragma unroll
            for (int i = 0; i < 8; i++) dstv[i] = srcv[i];
        }
        {
            int coln = tid >> 1, halfm = tid & 1;
            #pragma unroll
            for (int c8 = 0; c8 < 8; c8++){
                __nv_bfloat16 tmp[8];
                #pragma unroll
                for (int j = 0; j < 8; j++)
                    tmp[j] = tile[(halfm*64 + c8*8 + j)*TS + coln];
                *reinterpret_cast<uint4*>(CbT + (size_t)(bn+coln)*ldt + bm + halfm*64 + c8*8)
                    = *reinterpret_cast<const uint4*>(tmp);
            }
        }
    }
}

// ----------------------------- row-wise kernels ------------------------------------
// time column of Llh from accumulated row SSQ
__global__ void k_lltime(const float* __restrict__ acc, __nv_bfloat16* __restrict__ Llh){
    int i = blockIdx.x*1024 + threadIdx.x;
    Llh[(size_t)i*DPAD] = __float2bfloat16_rn(sqrtf(acc[i] + 1.f));
}
// finalize norms; write bf16 time entries into Lbh (col0) and LbTh (row0)
__global__ void k_nfin(const float* __restrict__ rss, const float* __restrict__ css,
                       __nv_bfloat16* __restrict__ Lbh, __nv_bfloat16* __restrict__ LbTh,
                       float* __restrict__ xnr, float* __restrict__ xnc){
    int b = blockIdx.x, n = threadIdx.x;                  // 1024
    float S = rss[b*1024 + n];
    float tv = sqrtf(S + 1.f);
    Lbh[((size_t)b*1024 + n)*1024] = __float2bfloat16_rn(tv);
    LbTh[(size_t)b*1024*1024 + n]  = __float2bfloat16_rn(tv);
    xnr[b*1024 + n] = sqrtf(fmaxf(2.f*S + 1.f, 1e-15f));
    float ts = blockReduceSum(S + 1.f);
    float c = css[b*1024 + n];
    xnc[b*1024 + n] = (n == 0) ? sqrtf(ts) : sqrtf(fmaxf(c, 1e-15f));
}
// warp-per-row fused Hs pipeline
__global__ void k_hs(const float* __restrict__ Hsa, const float* __restrict__ MxRaw,
                     const float* __restrict__ xnr,
                     const float* __restrict__ whs, float* __restrict__ lg){
    size_t row = (size_t)blockIdx.x*8 + (threadIdx.x >> 5);
    int lane = threadIdx.x & 31;
    const float* my = MxRaw + row*KKW;
    const float* hx = Hsa + row*KKW;
    float yr[4], x[4];
    float mm = 0.f;
    #pragma unroll
    for (int i = 0; i < 4; i++){
        yr[i] = my[lane + i*32];
        x[i]  = hx[lane + i*32];
        mm += yr[i]*yr[i];
    }
    mm = wsum(mm);
    float mxn = sqrtf(fmaxf(mm, 1e-15f));
    float xnb = xnr[row];
    float fac = tanhf(mxn / xnb * atanhc(xnb)) / mxn;

    float xy = 0.f, x2 = 0.f, y2 = 0.f;
    float y[4];
    #pragma unroll
    for (int i = 0; i < 4; i++){
        y[i] = yr[i] * fac;
        xy += x[i]*y[i]; x2 += x[i]*x[i]; y2 += y[i]*y[i];
    }
    xy = wsum(xy); x2 = wsum(x2); y2 = wsum(y2);
    float den = fmaxf(1.f + 2.f*xy + x2*y2, 1e-15f);
    float c1 = (1.f + 2.f*xy + y2) / den, c2 = (1.f - x2) / den;
    float h[4], hh = 0.f;
    #pragma unroll
    for (int i = 0; i < 4; i++){ h[i] = c1*x[i] + c2*y[i]; hh += h[i]*h[i]; }
    hh = wsum(hh);
    float hn = sqrtf(fmaxf(hh, 1e-15f));
    float fa = atanhc(hn) / hn;
    float gv[4], gg = 0.f;
    #pragma unroll
    for (int i = 0; i < 4; i++){ gv[i] = gelu_exact(fa*h[i]); gg += gv[i]*gv[i]; }
    gg = wsum(gg);
    float gn = sqrtf(fmaxf(gg, 1e-15f));
    float fb = tanhf(gn) / gn;
    float mx = 0.f, xn2 = 0.f;
    #pragma unroll
    for (int i = 0; i < 4; i++){
        float hs = fb * gv[i];
        mx += hs * __ldg(&whs[lane + i*32]);
        xn2 += hs*hs;
    }
    mx = wsum(mx); xn2 = wsum(xn2);
    if (lane == 0){
        float xn = sqrtf(fmaxf(xn2, 1e-15f));
        float mxn2 = sqrtf(fmaxf(mx*mx, 1e-15f));
        lg[row] = tanhf(mxn2 / xn * atanhc(xn)) * mx / mxn2;
    }
}
// dual transpose: z<BB: Hca -> HcaT fp32 + HcaTh bf16 ; z>=BB: Hsa -> HsahT bf16
__global__ void k_tbk2(const float* __restrict__ Hca, const float* __restrict__ Hsa,
                       float* __restrict__ HcaT, __nv_bfloat16* __restrict__ HcaTh,
                       __nv_bfloat16* __restrict__ HsahT){
    __shared__ float tile[32][33];
    int z = blockIdx.z;
    bool isHc = z < BB;
    int b = isHc ? z : z - BB;
    int j0 = blockIdx.x*32, m0 = blockIdx.y*32;
    const float* src = (isHc ? Hca : Hsa) + (size_t)b*NCQ*KKW;
    for (int i = threadIdx.y; i < 32; i += 8)
        tile[i][threadIdx.x] = src[(size_t)(m0+i)*KKW + j0 + threadIdx.x];
    __syncthreads();
    size_t base = (size_t)b*KKW*NCQ;
    for (int i = threadIdx.y; i < 32; i += 8){
        float v = tile[threadIdx.x][i];
        size_t idx = base + (size_t)(j0+i)*NCQ + m0 + threadIdx.x;
        if (isHc){ HcaT[idx] = v; HcaTh[idx] = __float2bfloat16_rn(v); }
        else     { HsahT[idx] = __float2bfloat16_rn(v); }
    }
}
// warp-per-row Hc pipeline: one warp per (b,j) row of 1024; shuffle-only reductions
__global__ void k_hc(const float* __restrict__ HcaT, const float* __restrict__ MxcT,
                     const float* __restrict__ sc, const float* __restrict__ whc,
                     float* __restrict__ amx, float* __restrict__ ass){
    int wg = blockIdx.x*8 + (threadIdx.x >> 5);           // 0..BB*KKW-1
    int b = wg >> 7, j = wg & 127;
    int lane = threadIdx.x & 31;
    float wj = __ldg(&whc[j]);
    const float* xrow = HcaT + ((size_t)(b*KKW + j))*NCQ;
    const float* yrow = MxcT + ((size_t)(b*KKW + j))*NCQ;
    const float* srow = sc + (size_t)b*NCQ;
    float x[32], y[32];
    float sxy = 0.f, sx2 = 0.f, sy2 = 0.f;
    #pragma unroll
    for (int i = 0; i < 32; i++){
        int m = lane + i*32;
        x[i] = xrow[m];
        y[i] = yrow[m] * srow[m];
        sxy += x[i]*y[i]; sx2 += x[i]*x[i]; sy2 += y[i]*y[i];
    }
    sxy = wsum(sxy); sx2 = wsum(sx2); sy2 = wsum(sy2);
    float den = fmaxf(1.f + 2.f*sxy + sx2*sy2, 1e-15f);
    float c1 = (1.f + 2.f*sxy + sy2) / den, c2 = (1.f - sx2) / den;
    float hh = 0.f;
    #pragma unroll
    for (int i = 0; i < 32; i++){ y[i] = c1*x[i] + c2*y[i]; hh += y[i]*y[i]; }
    hh = wsum(hh);
    float hn = sqrtf(fmaxf(hh, 1e-15f));
    float fa = atanhc(hn) / hn;
    float gg = 0.f;
    #pragma unroll
    for (int i = 0; i < 32; i++){ x[i] = gelu_exact(fa*y[i]); gg += x[i]*x[i]; }
    gg = wsum(gg);
    float gn = sqrtf(fmaxf(gg, 1e-15f));
    float fb = tanhf(gn) / gn;
    #pragma unroll
    for (int i = 0; i < 32; i++){
        int m = lane + i*32;
        float hc = fb * x[i];
        atomicAdd(&amx[b*NCQ + m], hc * wj);
        atomicAdd(&ass[b*NCQ + m], hc * hc);
    }
}
// As softmax (reads precomputed logits)
__global__ void k_softmax(const float* __restrict__ lg, float* __restrict__ out){
    int b = blockIdx.x, t = threadIdx.x;                  // 256
    float l[4];
    float lm = -3.4e38f;
    #pragma unroll
    for (int i = 0; i < 4; i++){ l[i] = lg[b*1024 + t + i*256]; lm = fmaxf(lm, l[i]); }
    float M = blockReduceMax(lm);
    float es = 0.f, e[4];
    #pragma unroll
    for (int i = 0; i < 4; i++){ e[i] = expf(l[i] - M); es += e[i]; }
    float S = blockReduceSum(es);
    #pragma unroll
    for (int i = 0; i < 4; i++) out[b*1024 + t + i*256] = e[i] / S;
}
// Ac softmax with fused logit computation from amx/ass
__global__ void k_softmax_ac(const float* __restrict__ amx, const float* __restrict__ ass,
                             float* __restrict__ out){
    int b = blockIdx.x, t = threadIdx.x;                  // 256
    float l[4];
    float lm = -3.4e38f;
    #pragma unroll
    for (int i = 0; i < 4; i++){
        int m = t + i*256;
        float mx = amx[b*NCQ + m];
        float ssv = ass[b*NCQ + m];
        float xn = sqrtf(fmaxf(ssv, 1e-15f));
        float mxn = sqrtf(fmaxf(mx*mx, 1e-15f));
        l[i] = tanhf(mxn / xn * atanhc(xn)) * mx / mxn;
        lm = fmaxf(lm, l[i]);
    }
    float M = blockReduceMax(lm);
    float es = 0.f, e[4];
    #pragma unroll
    for (int i = 0; i < 4; i++){ e[i] = expf(l[i] - M); es += e[i]; }
    float S = blockReduceSum(es);
    #pragma unroll
    for (int i = 0; i < 4; i++) out[b*1024 + t + i*256] = e[i] / S;
}
// dual-branch centroid partials: z<BB sentence (Ls, As), z>=BB comment (Lc, Ac)
__global__ void k_centroid_part(const float* __restrict__ Ls, const float* __restrict__ Lc,
                                const float* __restrict__ outw, int asoff, int acoff,
                                float* __restrict__ part){
    __shared__ float wsh[128];
    int ch = blockIdx.x, z = blockIdx.y;
    bool isS = z < BB;
    int b = isS ? z : z - BB;
    const float* Lx = isS ? Ls : Lc;
    const float* w = outw + (isS ? asoff : acoff) + (size_t)b*NSQ;
    int t = threadIdx.x;                                  // 288, t<257 active
    for (int i = t; i < 128; i += blockDim.x) wsh[i] = w[ch*128 + i];
    __syncthreads();
    if (t < DP1){
        const float* base = Lx + ((size_t)b*NSQ + (size_t)ch*128)*DPAD + t;
        float acc = 0.f;
        for (int n = 0; n < 128; n++) acc += wsh[n] * base[(size_t)n*DPAD];
        part[(z*8 + ch)*DP1 + t] = acc;
    }
}
__global__ void k_centroid_fin(const float* __restrict__ part, float* __restrict__ cs,
                               float* __restrict__ cc){
    __shared__ float t0sh;
    int z = blockIdx.x, t = threadIdx.x;                  // 288
    float acc = 0.f;
    if (t < DP1){
        #pragma unroll
        for (int c = 0; c < 8; c++) acc += part[(z*8 + c)*DP1 + t];
    }
    float sp = (t >= 1 && t < DP1) ? acc*acc : 0.f;
    float ssp = blockReduceSum(sp);
    if (t == 0) t0sh = acc;
    __syncthreads();
    float inner = -t0sh*t0sh + ssp;
    float den = sqrtf(fmaxf(fabsf(inner), 1e-8f));
    float* co = (z < BB) ? cs : cc;
    int b = (z < BB) ? z : z - BB;
    if (t < DP1) co[(size_t)b*DP1 + t] = acc / den;
}
__global__ void k_concat(const float* __restrict__ cs, const float* __restrict__ cc,
                         float* __restrict__ out){
    int b = blockIdx.x, t = threadIdx.x;                  // 256
    float t0s = cs[(size_t)b*DP1];
    float t0c = cc[(size_t)b*DP1];
    float sps = cs[(size_t)b*DP1 + 1 + t];
    float spc = cc[(size_t)b*DP1 + 1 + t];
    float ns  = sqrtf(fmaxf(blockReduceSum(sps*sps), 1e-15f));
    float ncv = sqrtf(fmaxf(blockReduceSum(spc*spc), 1e-15f));
    float zs = acoshf(fmaxf(t0s, 1.f + 1e-7f)) * sps / ns;
    float zc = acoshf(fmaxf(t0c, 1.f + 1e-7f)) * spc / ncv;
    float vn = sqrtf(fmaxf(blockReduceSum(zs*zs + zc*zc), 1e-15f));
    float f = sinhf(vn) / vn;
    float* o = out + (size_t)b*513;
    if (t == 0) o[0] = coshf(vn);
    o[1 + t]       = f * zs;
    o[1 + DD + t]  = f * zc;
}

// ----------------------------- launch ----------------------------------------------
extern "C" void kernel_launch(void* const* d_in, const int* in_sizes, int n_in,
                              void* d_out, int out_size)
{
    const float* sent = (const float*)d_in[0];
    const float* comm = (const float*)d_in[1];
    const float* WlW  = (const float*)d_in[2];
    const float* Wlb  = (const float*)d_in[3];
    const float* WcW  = (const float*)d_in[4];
    const float* Wcb  = (const float*)d_in[5];
    const float* WsW  = (const float*)d_in[6];
    const float* Wsb  = (const float*)d_in[7];
    const float* whs  = (const float*)d_in[8];
    const float* whc  = (const float*)d_in[9];
    float* out = (float*)d_out;
    (void)in_sizes; (void)n_in; (void)out_size;

    float2 *c1, *c1T;
    float *sT, *rl, *Ls, *Lc, *rss, *css, *amx, *ass, *lacc, *xnr, *xnc,
          *msc, *Hsa, *Hca, *HcaT, *Mxs, *MxcT, *lgs, *cs, *cc, *part;
    __nv_bfloat16 *Lsh, *Lch, *Llh, *Lbh, *LbTh, *HcaTh, *HsahT, *Wth, *Wtl;
    cudaGetSymbolAddress((void**)&c1,  g_c1);
    cudaGetSymbolAddress((void**)&c1T, g_c1T);
    cudaGetSymbolAddress((void**)&sT,  g_sT);
    cudaGetSymbolAddress((void**)&rl,  g_real);
    cudaGetSymbolAddress((void**)&Ls,  g_Ls);
    cudaGetSymbolAddress((void**)&Lc,  g_Lc);
    cudaGetSymbolAddress((void**)&Wth, g_Wth);
    cudaGetSymbolAddress((void**)&Wtl, g_Wtl);
    cudaGetSymbolAddress((void**)&Lsh, g_Lsh);
    cudaGetSymbolAddress((void**)&Lch, g_Lch);
    cudaGetSymbolAddress((void**)&Llh, g_Llh);
    cudaGetSymbolAddress((void**)&Lbh, g_Lbh);
    cudaGetSymbolAddress((void**)&LbTh,g_LbTh);
    cudaGetSymbolAddress((void**)&HcaTh,g_HcaTh);
    cudaGetSymbolAddress((void**)&HsahT,g_HsahT);
    cudaGetSymbolAddress((void**)&rss, g_rss);
    cudaGetSymbolAddress((void**)&css, g_css);
    cudaGetSymbolAddress((void**)&amx, g_amx);
    cudaGetSymbolAddress((void**)&ass, g_ass);
    cudaGetSymbolAddress((void**)&lacc,g_lacc);
    cudaGetSymbolAddress((void**)&xnr, g_xnr);
    cudaGetSymbolAddress((void**)&xnc, g_xnc);
    cudaGetSymbolAddress((void**)&msc, g_msc);
    cudaGetSymbolAddress((void**)&Hsa, g_Hsa);
    cudaGetSymbolAddress((void**)&Hca, g_Hca);
    cudaGetSymbolAddress((void**)&HcaT,g_HcaT);
    cudaGetSymbolAddress((void**)&Mxs, g_Mxs);
    cudaGetSymbolAddress((void**)&MxcT,g_MxcT);
    cudaGetSymbolAddress((void**)&lgs, g_lgs);
    cudaGetSymbolAddress((void**)&cs,  g_cs);
    cudaGetSymbolAddress((void**)&cc,  g_cc);
    cudaGetSymbolAddress((void**)&part,g_part);

    const int AS_OFF = BB*513;             // 16416
    const int AC_OFF = AS_OFF + BB*NSQ;    // 49184

    k_setup<<<32 + DP1 + 2*KP1, 1024>>>(WlW, WsW, WcW, rss, css, amx, ass, lacc);

    // ---- dual-branch FFT2 (stage-0 fused, Hermitian-compact) + euclid_to_lorentz ----
    k_fft256<<<2*BB*NSQ/4, dim3(64,4)>>>(sent, comm, c1);
    k_transpose_ch<<<dim3(5, NSQ/32, 2*BB), dim3(32,8)>>>(c1, c1T);
    k_fft1024<<<2*BB*DH, 256>>>(c1T, sT);
    k_transpose_fh<<<dim3(5, NSQ/32, 2*BB), dim3(32,8)>>>(sT, rl);
    k_e2l<<<2*BB*NSQ, 256>>>(rl, Ls, Lc, Lsh, Lch);

    // ---- linear layers (bf16 split-B weights; fused epilogues) ----
    // Wl: bias + direct bf16 Llh space store + row-SSQ atomics -> lacc
    k_bgemm<5,1><<<dim3(2,256,1),256>>>(Lch, Wth + (size_t)1*DPAD, Wtl + (size_t)1*DPAD,
        Wlb + 1, nullptr, Llh + 1, nullptr,
        BB*NCQ, 256, DP1, DPAD, DPAD, DPAD, 0, 0, 0, 0, 0, lacc, nullptr);
    k_lltime<<<32, 1024>>>(lacc, Llh);

    // Ws: bias + fused poincare -> Hsa
    k_bgemm<4,1><<<dim3(1,256,1),256>>>(Lsh, Wth + (size_t)385*DPAD, Wtl + (size_t)385*DPAD,
        Wsb + 1, Hsa, nullptr, nullptr,
        BB*NSQ, KKW, DP1, DPAD, DPAD, KKW, 0, 0, 0, 0, 0, nullptr, nullptr);
    // Wc: bias + fused poincare -> Hca
    k_bgemm<4,1><<<dim3(1,256,1),256>>>(Lch, Wth + (size_t)641*DPAD, Wtl + (size_t)641*DPAD,
        Wcb + 1, Hca, nullptr, nullptr,
        BB*NCQ, KKW, DP1, DPAD, DPAD, KKW, 0, 0, 0, 0, 0, nullptr, nullptr);

    // ---- big einsum (bf16) + lorentz_act + fused norms, coalesced dual bf16 out ----
    k_bgemm<2,0><<<dim3(8,8,BB),256>>>(Lsh, Llh, nullptr, nullptr, nullptr, Lbh, LbTh,
        NSQ, NCQ, DP1, DPAD, DPAD, NCQ, NSQ,
        (long)NSQ*DPAD, (long)NCQ*DPAD, 0, (long)NSQ*NCQ, rss, css);
    k_nfin<<<BB, 1024>>>(rss, css, Lbh, LbTh, xnr, xnc);

    // ---- transposes for mobius operands ----
    k_tbk2<<<dim3(4, 32, 2*BB), dim3(32,8)>>>(Hca, Hsa, HcaT, HcaTh, HsahT);

    // ---- mobius_matvec GEMMs (bf16); MxcT GEMM fuses mscale ----
    k_bgemm<0,0><<<dim3(1,8,BB),256>>>(Lbh, HcaTh, nullptr, nullptr, Mxs, nullptr, nullptr,
        NSQ, KKW, NCQ, NCQ, NCQ, KKW, 0,
        (long)NSQ*NCQ, (long)KKW*NCQ, (long)NSQ*KKW, 0, nullptr, nullptr);
    k_bgemm<3,0><<<dim3(8,1,BB),256>>>(HsahT, LbTh, nullptr, nullptr, MxcT, nullptr, nullptr,
        KKW, NCQ, NSQ, NSQ, NSQ, NCQ, 0,
        (long)KKW*NSQ, (long)NCQ*NSQ, (long)KKW*NCQ, 0, xnc, msc);

    // ---- mobius_add + gelu pipelines + attention logits ----
    k_hs<<<BB*NSQ/8, 256>>>(Hsa, Mxs, xnr, whs, lgs);
    k_hc<<<BB*KKW/8, 256>>>(HcaT, MxcT, msc, whc, amx, ass);

    // ---- softmaxes straight into output (Ac logit fused) ----
    k_softmax<<<BB, 256>>>(lgs, out + AS_OFF);
    k_softmax_ac<<<BB, 256>>>(amx, ass, out + AC_OFF);

    // ---- centroids (dual-branch) + concat ----
    k_centroid_part<<<dim3(8, 2*BB), 288>>>(Ls, Lc, out, AS_OFF, AC_OFF, part);
    k_centroid_fin<<<2*BB, 288>>>(part, cs, cc);
    k_concat<<<BB, 256>>>(cs, cc, out);
}

// round 17
// speedup vs baseline: 1.2431x; 1.0121x over previous
#include <cuda_runtime.h>
#include <cuda_bf16.h>
#include <math.h>
#include <stdint.h>

#define BB  32
#define NSQ 1024
#define NCQ 1024
#define DD  256
#define DP1 257
#define DPAD 272
#define KKW 128
#define KP1 129
#define DH  129   // Hermitian-reduced column count

// ----------------------------- scratch (static device globals; no runtime alloc) ---
static __device__ float2 g_c1 [(size_t)2*BB*NSQ*DH];
static __device__ float2 g_c1T[(size_t)2*BB*DH*NSQ];
static __device__ float  g_sT [(size_t)2*BB*DH*NSQ];
static __device__ float  g_real[(size_t)2*BB*NSQ*DH];
static __device__ float  g_Ls [(size_t)BB*NSQ*DPAD];
static __device__ float  g_Lc [(size_t)BB*NCQ*DPAD];
static __device__ __align__(16) __nv_bfloat16 g_Wth[(size_t)896*DPAD]; // Wl@0,Ws@384,Wc@640
static __device__ __align__(16) __nv_bfloat16 g_Wtl[(size_t)896*DPAD]; // lo residuals
static __device__ __align__(16) __nv_bfloat16 g_Lsh [(size_t)BB*NSQ*DPAD];
static __device__ __align__(16) __nv_bfloat16 g_Lch [(size_t)BB*NCQ*DPAD];
static __device__ __align__(16) __nv_bfloat16 g_Llh [(size_t)BB*NCQ*DPAD];
static __device__ __align__(16) __nv_bfloat16 g_Lbh [(size_t)BB*NSQ*NCQ];
static __device__ __align__(16) __nv_bfloat16 g_LbTh[(size_t)BB*NCQ*NSQ];
static __device__ __align__(16) __nv_bfloat16 g_HcaTh[(size_t)BB*KKW*NCQ];
static __device__ __align__(16) __nv_bfloat16 g_HsahT[(size_t)BB*KKW*NSQ];
static __device__ float  g_rss[BB*NSQ];
static __device__ float  g_css[BB*NCQ];
static __device__ float  g_amx[BB*NCQ];
static __device__ float  g_ass[BB*NCQ];
static __device__ float  g_lacc[BB*NCQ];      // Wl row-SSQ accumulator
static __device__ float  g_xnr[BB*NSQ];
static __device__ float  g_xnc[BB*NCQ];
static __device__ float  g_msc[BB*NCQ];
static __device__ float  g_Hsa[(size_t)BB*NSQ*KKW];
static __device__ float  g_Hca[(size_t)BB*NCQ*KKW];
static __device__ float  g_HcaT[(size_t)BB*KKW*NCQ];
static __device__ float  g_Mxs[(size_t)BB*NSQ*KKW];
static __device__ float  g_MxcT[(size_t)BB*KKW*NCQ];
static __device__ float  g_lgs[BB*NSQ];
static __device__ float  g_cs [BB*DP1];
static __device__ float  g_cc [BB*DP1];
static __device__ float  g_part[2*BB*8*DP1];
static __device__ float2 g_tw1024[1024];
static __device__ float2 g_tw256[256];

// ----------------------------- helpers ---------------------------------------------
__device__ __forceinline__ float atanhc(float x){
    x = fminf(fmaxf(x, -1.f + 1e-5f), 1.f - 1e-5f);
    return 0.5f * (log1pf(x) - log1pf(-x));
}
__device__ __forceinline__ float gelu_exact(float v){
    return 0.5f * v * (1.f + erff(v * 0.70710678118654752f));
}
__device__ __forceinline__ float2 cmul(float2 a, float2 b){
    return make_float2(a.x*b.x - a.y*b.y, a.x*b.y + a.y*b.x);
}
__device__ __forceinline__ float2 cadd(float2 a, float2 b){ return make_float2(a.x+b.x, a.y+b.y); }
__device__ __forceinline__ float2 csub(float2 a, float2 b){ return make_float2(a.x-b.x, a.y-b.y); }

__device__ __forceinline__ float wsum(float v){
    #pragma unroll
    for (int o = 16; o; o >>= 1) v += __shfl_xor_sync(0xffffffffu, v, o);
    return v;
}
__device__ __forceinline__ float blockReduceSum(float v){
    __shared__ float sh[32];
    #pragma unroll
    for (int o = 16; o; o >>= 1) v += __shfl_down_sync(0xffffffffu, v, o);
    int lane = threadIdx.x & 31, w = threadIdx.x >> 5;
    if (lane == 0) sh[w] = v;
    __syncthreads();
    int nw = (blockDim.x + 31) >> 5;
    v = (threadIdx.x < (unsigned)nw) ? sh[threadIdx.x] : 0.f;
    if (w == 0){
        #pragma unroll
        for (int o = 16; o; o >>= 1) v += __shfl_down_sync(0xffffffffu, v, o);
        if (lane == 0) sh[0] = v;
    }
    __syncthreads();
    float r = sh[0];
    __syncthreads();
    return r;
}
__device__ __forceinline__ float blockReduceMax(float v){
    __shared__ float sh[32];
    #pragma unroll
    for (int o = 16; o; o >>= 1) v = fmaxf(v, __shfl_down_sync(0xffffffffu, v, o));
    int lane = threadIdx.x & 31, w = threadIdx.x >> 5;
    if (lane == 0) sh[w] = v;
    __syncthreads();
    int nw = (blockDim.x + 31) >> 5;
    v = (threadIdx.x < (unsigned)nw) ? sh[threadIdx.x] : -3.4e38f;
    if (w == 0){
        #pragma unroll
        for (int o = 16; o; o >>= 1) v = fmaxf(v, __shfl_down_sync(0xffffffffu, v, o));
        if (lane == 0) sh[0] = v;
    }
    __syncthreads();
    float r = sh[0];
    __syncthreads();
    return r;
}
__device__ __forceinline__ void mma_bf16(float* c, const uint32_t* a, const uint32_t* b){
    asm volatile("mma.sync.aligned.m16n8k16.row.col.f32.bf16.bf16.f32 "
        "{%0,%1,%2,%3}, {%4,%5,%6,%7}, {%8,%9}, {%0,%1,%2,%3};"
        : "+f"(c[0]), "+f"(c[1]), "+f"(c[2]), "+f"(c[3])
        : "r"(a[0]), "r"(a[1]), "r"(a[2]), "r"(a[3]), "r"(b[0]), "r"(b[1]));
}
__device__ __forceinline__ void cpa16(uint32_t dsh, const void* src){
    asm volatile("cp.async.ca.shared.global [%0], [%1], 16;" :: "r"(dsh), "l"(src));
}
#define CP_COMMIT() asm volatile("cp.async.commit_group;" ::: "memory")
#define CP_WAIT1()  asm volatile("cp.async.wait_group 1;" ::: "memory")
#define CP_WAIT0()  asm volatile("cp.async.wait_group 0;" ::: "memory")

// ----------------------------- merged setup kernel ---------------------------------
__global__ void k_setup(const float* __restrict__ Wl, const float* __restrict__ Ws,
                        const float* __restrict__ Wc,
                        float* __restrict__ a, float* __restrict__ b,
                        float* __restrict__ c, float* __restrict__ d,
                        float* __restrict__ e){
    int blk = blockIdx.x;
    int t = threadIdx.x;                       // 1024
    if (blk < 32){
        int i = blk*1024 + t;
        a[i] = 0.f; b[i] = 0.f; c[i] = 0.f; d[i] = 0.f; e[i] = 0.f;
        if (blk == 0){
            double ang = -6.283185307179586476925287 * (double)t / 1024.0;
            g_tw1024[t] = make_float2((float)cos(ang), (float)sin(ang));
            if (t < 256){
                double a2 = -6.283185307179586476925287 * (double)t / 256.0;
                g_tw256[t] = make_float2((float)cos(a2), (float)sin(a2));
            }
        }
        return;
    }
    int r = blk - 32;                          // 0..514
    if (t >= DP1) return;
    const float* src; size_t drow;
    if (r < DP1){ src = Wl + (size_t)r*DP1; drow = (size_t)r*DPAD; }
    else if (r < DP1 + KP1){ int rr = r - DP1; src = Ws + (size_t)rr*DP1; drow = (size_t)(384+rr)*DPAD; }
    else { int rr = r - DP1 - KP1; src = Wc + (size_t)rr*DP1; drow = (size_t)(640+rr)*DPAD; }
    float w = src[t];
    __nv_bfloat16 hi = __float2bfloat16_rn(w);
    g_Wth[drow + t] = hi;
    g_Wtl[drow + t] = __float2bfloat16_rn(w - __bfloat162float(hi));
}

// ----------------------------- radix-4 Stockham FFT kernels ------------------------
__global__ void k_fft256(const float* __restrict__ sent, const float* __restrict__ comm,
                         float2* __restrict__ out){
    __shared__ float2 bufA[4][256];
    __shared__ float2 bufB[4][256];
    __shared__ float  rsum[4][2];
    int tx = threadIdx.x;                      // 64
    int ty = threadIdx.y;                      // 4
    size_t row = (size_t)blockIdx.x*4 + ty;
    bool do_log = row >= (size_t)BB*NSQ;
    const float* x = do_log ? (comm + (row - (size_t)BB*NSQ)*256) : (sent + row*256);

    float v0 = x[tx], v1 = x[tx+64], v2 = x[tx+128], v3 = x[tx+192];
    float ss = v0*v0 + v1*v1 + v2*v2 + v3*v3;
    #pragma unroll
    for (int o = 16; o; o >>= 1) ss += __shfl_down_sync(0xffffffffu, ss, o);
    if ((tx & 31) == 0) rsum[ty][tx >> 5] = ss;
    __syncthreads();
    if (do_log){
        float tot = rsum[ty][0] + rsum[ty][1];
        float yn = sqrtf(fmaxf(tot, 1e-15f));
        float f = atanhc(yn) / yn;
        v0 *= f; v1 *= f; v2 *= f; v3 *= f;
    }
    {
        float pa = v0 + v2, pb = v0 - v2;
        float pc = v1 + v3, pd = v1 - v3;
        bufA[ty][4*tx]     = make_float2(pa + pc, 0.f);
        bufA[ty][4*tx + 1] = make_float2(pb, -pd);
        bufA[ty][4*tx + 2] = make_float2(pa - pc, 0.f);
        bufA[ty][4*tx + 3] = make_float2(pb,  pd);
    }
    __syncthreads();

    float2* X = &bufA[ty][0];
    float2* Y = &bufB[ty][0];
    #pragma unroll
    for (int s = 1; s < 4; s++){
        int Ns = 1 << (2*s);
        int p = tx & (Ns - 1);
        float2 w1 = __ldg(&g_tw256[p * (64/Ns)]);
        float2 w2 = cmul(w1, w1);
        float2 w3 = cmul(w2, w1);
        float2 a0 = X[tx];
        float2 a1 = cmul(X[tx + 64],  w1);
        float2 a2 = cmul(X[tx + 128], w2);
        float2 a3 = cmul(X[tx + 192], w3);
        float2 pa = cadd(a0, a2), pb = csub(a0, a2);
        float2 pc = cadd(a1, a3), pd = csub(a1, a3);
        float2 dneg = make_float2(pd.y, -pd.x);
        float2 dpos = make_float2(-pd.y, pd.x);
        int idxD = ((tx >> (2*s)) << (2*s + 2)) + p;
        Y[idxD]          = cadd(pa, pc);
        Y[idxD + Ns]     = cadd(pb, dneg);
        Y[idxD + 2*Ns]   = csub(pa, pc);
        Y[idxD + 3*Ns]   = cadd(pb, dpos);
        __syncthreads();
        float2* tmp = X; X = Y; Y = tmp;
    }
    out[row*DH + tx]      = X[tx];
    out[row*DH + tx + 64] = X[tx + 64];
    if (tx == 0) out[row*DH + 128] = X[128];
}

__global__ void k_fft1024(const float2* __restrict__ in, float* __restrict__ outr){
    __shared__ float2 bufA[1024];
    __shared__ float2 bufB[1024];
    int t = threadIdx.x;                       // 256
    size_t row = blockIdx.x;
    const float2* src = in + row*1024;
    float2 a0 = src[t], a1 = src[t+256], a2 = src[t+512], a3 = src[t+768];
    {
        float2 pa = cadd(a0, a2), pb = csub(a0, a2);
        float2 pc = cadd(a1, a3), pd = csub(a1, a3);
        bufA[4*t]     = cadd(pa, pc);
        bufA[4*t + 1] = cadd(pb, make_float2(pd.y, -pd.x));
        bufA[4*t + 2] = csub(pa, pc);
        bufA[4*t + 3] = cadd(pb, make_float2(-pd.y, pd.x));
    }
    __syncthreads();
    float2* X = bufA;
    float2* Y = bufB;
    #pragma unroll
    for (int s = 1; s < 5; s++){
        int Ns = 1 << (2*s);
        int p = t & (Ns - 1);
        float2 w1 = __ldg(&g_tw1024[p * (256/Ns)]);
        float2 w2 = cmul(w1, w1);
        float2 w3 = cmul(w2, w1);
        float2 b0 = X[t];
        float2 b1 = cmul(X[t + 256], w1);
        float2 b2 = cmul(X[t + 512], w2);
        float2 b3 = cmul(X[t + 768], w3);
        float2 pa = cadd(b0, b2), pb = csub(b0, b2);
        float2 pc = cadd(b1, b3), pd = csub(b1, b3);
        float2 dneg = make_float2(pd.y, -pd.x);
        float2 dpos = make_float2(-pd.y, pd.x);
        int idxD = ((t >> (2*s)) << (2*s + 2)) + p;
        Y[idxD]        = cadd(pa, pc);
        Y[idxD + Ns]   = cadd(pb, dneg);
        Y[idxD + 2*Ns] = csub(pa, pc);
        Y[idxD + 3*Ns] = cadd(pb, dpos);
        __syncthreads();
        float2* tmp = X; X = Y; Y = tmp;
    }
    #pragma unroll
    for (int i = 0; i < 4; i++)
        outr[row*1024 + t + i*256] = X[t + i*256].x;
}

__global__ void k_transpose_ch(const float2* __restrict__ in, float2* __restrict__ out){
    __shared__ float2 tile[32][33];
    int b = blockIdx.z;
    int c0 = blockIdx.x*32, r0 = blockIdx.y*32;
    const float2* src = in + (size_t)b*NSQ*DH;
    for (int i = threadIdx.y; i < 32; i += 8){
        int d = c0 + threadIdx.x;
        tile[i][threadIdx.x] = (d < DH) ? src[(size_t)(r0+i)*DH + d]
                                        : make_float2(0.f, 0.f);
    }
    __syncthreads();
    float2* dst = out + (size_t)b*DH*NSQ;
    for (int i = threadIdx.y; i < 32; i += 8){
        int d = c0 + i;
        if (d < DH) dst[(size_t)d*NSQ + r0 + threadIdx.x] = tile[threadIdx.x][i];
    }
}
__global__ void k_transpose_fh(const float* __restrict__ in, float* __restrict__ out){
    __shared__ float tile[32][33];
    int b = blockIdx.z;
    int d0 = blockIdx.x*32, n0 = blockIdx.y*32;
    const float* src = in + (size_t)b*DH*NSQ;
    for (int i = threadIdx.y; i < 32; i += 8){
        int d = d0 + i;
        tile[i][threadIdx.x] = (d < DH) ? src[(size_t)d*NSQ + n0 + threadIdx.x] : 0.f;
    }
    __syncthreads();
    float* dst = out + (size_t)b*NSQ*DH;
    int d = d0 + threadIdx.x;
    if (d < DH)
        for (int i = threadIdx.y; i < 32; i += 8)
            dst[(size_t)(n0+i)*DH + d] = tile[threadIdx.x][i];
}

// fused Hermitian mirror + euclid_to_lorentz; fp32 (centroid) + bf16 (GEMM operands)
__global__ void k_e2l(const float* __restrict__ rl, float* __restrict__ Ls,
                      float* __restrict__ Lc, __nv_bfloat16* __restrict__ Lsh,
                      __nv_bfloat16* __restrict__ Lch){
    size_t row = blockIdx.x;                   // 0 .. 2*BB*NSQ-1
    int t = threadIdx.x;                       // 256
    size_t bb = row >> 10;
    int n = (int)(row & 1023);
    float v;
    if (t < DH){
        v = rl[(bb*NSQ + n)*DH + t];
    } else {
        int srcn = (1024 - n) & 1023;
        v = rl[(bb*NSQ + srcn)*DH + (256 - t)];
    }
    float ss = blockReduceSum(v*v);
    float xn = sqrtf(fmaxf(ss, 1e-15f)) + 1e-5f;
    float scl = fminf(1.f, 2.0f / xn);
    v *= scl;
    float vn = sqrtf(fmaxf(ss*scl*scl, 1e-15f));
    float f = sinhf(vn) / vn;
    bool isS = bb < BB;
    float* out = isS ? Ls : Lc;
    __nv_bfloat16* outh = isS ? Lsh : Lch;
    size_t orow = isS ? row : row - (size_t)BB*NSQ;
    float tv = coshf(vn), sv = f * v;
    if (t == 0){ out[orow*DPAD] = tv; outh[orow*DPAD] = __float2bfloat16_rn(tv); }
    out[orow*DPAD + 1 + t] = sv;
    outh[orow*DPAD + 1 + t] = __float2bfloat16_rn(sv);
    if (t < DPAD - DP1) out[orow*DPAD + DP1 + t] = 0.f;
}

// --------- bf16 GEMM (m16n8k16): A[m][k], B[n][k] --------------------------------
//  MODE 0: plain fp32 C            MODE 2: einsum epilogue
//  MODE 3: fp32 C + fused mscale (rss=xnc in, css=msc out)
//  MODE 4: bias + fused poincare -> fp32 C (requires gridDim.x==1, N==128)
//  MODE 5: bias + bf16 Cb store + global row-SSQ atomics into rss
template<int MODE, int SPLITB>
__global__ void k_bgemm(const __nv_bfloat16* __restrict__ A,
                        const __nv_bfloat16* __restrict__ Bm,
                        const __nv_bfloat16* __restrict__ Bl,
                        const float* __restrict__ bias,
                        float* __restrict__ C,
                        __nv_bfloat16* __restrict__ Cb, __nv_bfloat16* __restrict__ CbT,
                        int M, int N, int Klen, int lda, int ldb, int ldc, int ldt,
                        long sA, long sB, long sC, long sCb,
                        float* __restrict__ rss, float* __restrict__ css)
{
    __shared__ __align__(16) char smemraw[49152];
    __nv_bfloat16* AsBuf = reinterpret_cast<__nv_bfloat16*>(smemraw);
    __nv_bfloat16* BlBuf = reinterpret_cast<__nv_bfloat16*>(smemraw + 12288);
    __nv_bfloat16* BsBuf = reinterpret_cast<__nv_bfloat16*>(smemraw + 24576);

    int bz = blockIdx.z;
    A  += (size_t)bz * sA;
    Bm += (size_t)bz * sB;
    if (MODE != 2) C += (size_t)bz * sC;
    else { Cb += (size_t)bz * sCb; CbT += (size_t)bz * sCb; }
    int bm = blockIdx.y * 128, bn = blockIdx.x * 128;
    int tid = threadIdx.x;
    int wid = tid >> 5, lane = tid & 31;
    int wm = (wid >> 2) * 64;
    int wn = (wid & 3) * 32;
    int g = lane >> 2, tg = lane & 3;
    int KT = (Klen + 15) >> 4;

    uint32_t asBase = (uint32_t)__cvta_generic_to_shared(AsBuf);
    uint32_t blBase = (uint32_t)__cvta_generic_to_shared(BlBuf);
    uint32_t bsBase = (uint32_t)__cvta_generic_to_shared(BsBuf);

    auto issueA = [&](int st, int k0){
        int mm = tid >> 1, c = tid & 1;
        cpa16(asBase + (uint32_t)(st*6144) + (mm*24 + c*8)*2,
              A + (size_t)(bm+mm)*lda + k0 + c*8);
    };
    auto issueB = [&](int st, int k0){
        int nn = tid >> 1, c = tid & 1;
        cpa16(bsBase + (uint32_t)(st*6144) + (nn*24 + c*8)*2,
              Bm + (size_t)(bn+nn)*ldb + k0 + c*8);
        if (SPLITB)
            cpa16(blBase + (uint32_t)(st*6144) + (nn*24 + c*8)*2,
                  Bl + (size_t)(bn+nn)*ldb + k0 + c*8);
    };

    float acc[4][4][4];
    #pragma unroll
    for (int mi = 0; mi < 4; mi++)
        #pragma unroll
        for (int ni = 0; ni < 4; ni++)
            #pragma unroll
            for (int r = 0; r < 4; r++) acc[mi][ni][r] = 0.f;

    issueA(0, 0); issueB(0, 0);
    CP_COMMIT();

    for (int kt = 0; kt < KT; kt++){
        int st = kt & 1;
        if (kt + 1 < KT){
            issueA(st ^ 1, (kt+1)*16);
            issueB(st ^ 1, (kt+1)*16);
            CP_COMMIT();
            CP_WAIT1();
        } else {
            CP_WAIT0();
        }
        __syncthreads();

        const uint32_t* pA = reinterpret_cast<const uint32_t*>(AsBuf + st*3072);
        const uint32_t* pB = reinterpret_cast<const uint32_t*>(BsBuf + st*3072);
        uint32_t bhf[4][2];
        #pragma unroll
        for (int ni = 0; ni < 4; ni++){
            int n = wn + ni*8 + g;
            bhf[ni][0] = pB[n*12 + tg];
            bhf[ni][1] = pB[n*12 + tg + 4];
        }
        uint32_t blf[4][2];
        if (SPLITB){
            const uint32_t* pL = reinterpret_cast<const uint32_t*>(BlBuf + st*3072);
            #pragma unroll
            for (int ni = 0; ni < 4; ni++){
                int n = wn + ni*8 + g;
                blf[ni][0] = pL[n*12 + tg];
                blf[ni][1] = pL[n*12 + tg + 4];
            }
        }
        #pragma unroll
        for (int mi = 0; mi < 4; mi++){
            int m = wm + mi*16;
            uint32_t ahf[4];
            ahf[0] = pA[(m+g)*12   + tg];
            ahf[1] = pA[(m+g+8)*12 + tg];
            ahf[2] = pA[(m+g)*12   + tg + 4];
            ahf[3] = pA[(m+g+8)*12 + tg + 4];
            #pragma unroll
            for (int ni = 0; ni < 4; ni++){
                mma_bf16(acc[mi][ni], ahf, bhf[ni]);
                if (SPLITB) mma_bf16(acc[mi][ni], ahf, blf[ni]);
            }
        }
        __syncthreads();
    }

    if (MODE == 0 || MODE == 3){
        #pragma unroll
        for (int mi = 0; mi < 4; mi++)
            #pragma unroll
            for (int ni = 0; ni < 4; ni++){
                int col = bn + wn + ni*8 + 2*tg;
                #pragma unroll
                for (int r = 0; r < 4; r++){
                    int gm = bm + wm + mi*16 + g + (r >= 2 ? 8 : 0);
                    int gn = col + (r & 1);
                    if (gn >= N) continue;
                    C[(size_t)gm*ldc + gn] = acc[mi][ni][r];
                }
            }
        if (MODE == 3){
            __syncthreads();
            float* colss = reinterpret_cast<float*>(smemraw);
            if (tid < 128) colss[tid] = 0.f;
            __syncthreads();
            #pragma unroll
            for (int ni = 0; ni < 4; ni++){
                #pragma unroll
                for (int cb = 0; cb < 2; cb++){
                    float cp = 0.f;
                    #pragma unroll
                    for (int mi = 0; mi < 4; mi++){
                        float a0 = acc[mi][ni][cb], a1 = acc[mi][ni][2+cb];
                        cp += a0*a0 + a1*a1;
                    }
                    cp += __shfl_down_sync(0xffffffffu, cp, 4);
                    cp += __shfl_down_sync(0xffffffffu, cp, 8);
                    cp += __shfl_down_sync(0xffffffffu, cp, 16);
                    if (g == 0)
                        atomicAdd(&colss[wn + ni*8 + 2*tg + cb], cp);
                }
            }
            __syncthreads();
            if (tid < 128){
                float ssv = colss[tid];
                float mxn = sqrtf(fmaxf(ssv, 1e-15f));
                float xnv = rss[(size_t)bz*1024 + bn + tid];       // xnc
                css[(size_t)bz*1024 + bn + tid] =                  // msc
                    tanhf(mxn / xnv * atanhc(xnv)) / mxn;
            }
        }
    } else if (MODE == 4){
        #pragma unroll
        for (int mi = 0; mi < 4; mi++)
            #pragma unroll
            for (int ni = 0; ni < 4; ni++){
                int col = wn + ni*8 + 2*tg;
                #pragma unroll
                for (int r = 0; r < 4; r++)
                    acc[mi][ni][r] += bias[col + (r & 1)];
            }
        __syncthreads();
        float* rowss = reinterpret_cast<float*>(smemraw);
        if (tid < 128) rowss[tid] = 0.f;
        __syncthreads();
        #pragma unroll
        for (int mi = 0; mi < 4; mi++){
            #pragma unroll
            for (int half = 0; half < 2; half++){
                float rp = 0.f;
                #pragma unroll
                for (int ni = 0; ni < 4; ni++){
                    float a0 = acc[mi][ni][half*2], a1 = acc[mi][ni][half*2+1];
                    rp += a0*a0 + a1*a1;
                }
                rp += __shfl_down_sync(0xffffffffu, rp, 1);
                rp += __shfl_down_sync(0xffffffffu, rp, 2);
                if (tg == 0)
                    atomicAdd(&rowss[wm + mi*16 + g + half*8], rp);
            }
        }
        __syncthreads();
        #pragma unroll
        for (int mi = 0; mi < 4; mi++){
            float inv0 = 1.f / (sqrtf(rowss[wm + mi*16 + g]     + 1.f) + 1.f);
            float inv1 = 1.f / (sqrtf(rowss[wm + mi*16 + g + 8] + 1.f) + 1.f);
            #pragma unroll
            for (int ni = 0; ni < 4; ni++){
                int col = wn + ni*8 + 2*tg;
                #pragma unroll
                for (int r = 0; r < 4; r++){
                    int gm = bm + wm + mi*16 + g + (r >= 2 ? 8 : 0);
                    float inv = (r >= 2) ? inv1 : inv0;
                    C[(size_t)gm*ldc + col + (r & 1)] = acc[mi][ni][r] * inv;
                }
            }
        }
    } else if (MODE == 5){
        #pragma unroll
        for (int mi = 0; mi < 4; mi++)
            #pragma unroll
            for (int ni = 0; ni < 4; ni++){
                int col = bn + wn + ni*8 + 2*tg;
                #pragma unroll
                for (int r = 0; r < 4; r++){
                    float v = acc[mi][ni][r] + bias[col + (r & 1)];
                    acc[mi][ni][r] = v;
                    int gm = bm + wm + mi*16 + g + (r >= 2 ? 8 : 0);
                    Cb[(size_t)gm*ldc + col + (r & 1)] = __float2bfloat16_rn(v);
                }
            }
        #pragma unroll
        for (int mi = 0; mi < 4; mi++){
            #pragma unroll
            for (int half = 0; half < 2; half++){
                float rp = 0.f;
                #pragma unroll
                for (int ni = 0; ni < 4; ni++){
                    float a0 = acc[mi][ni][half*2], a1 = acc[mi][ni][half*2+1];
                    rp += a0*a0 + a1*a1;
                }
                rp += __shfl_down_sync(0xffffffffu, rp, 1);
                rp += __shfl_down_sync(0xffffffffu, rp, 2);
                if (tg == 0)
                    atomicAdd(&rss[bm + wm + mi*16 + g + half*8], rp);
            }
        }
    } else {
        // MODE 2
        #pragma unroll
        for (int mi = 0; mi < 4; mi++)
            #pragma unroll
            for (int ni = 0; ni < 4; ni++){
                int col = bn + wn + ni*8 + 2*tg;
                #pragma unroll
                for (int r = 0; r < 4; r++){
                    int gn = col + (r & 1);
                    acc[mi][ni][r] = (gn == 0) ? 0.f : gelu_exact(acc[mi][ni][r]);
                }
            }
        #pragma unroll
        for (int mi = 0; mi < 4; mi++){
            #pragma unroll
            for (int half = 0; half < 2; half++){
                float rp = 0.f;
                #pragma unroll
                for (int ni = 0; ni < 4; ni++){
                    float a0 = acc[mi][ni][half*2], a1 = acc[mi][ni][half*2+1];
                    rp += a0*a0 + a1*a1;
                }
                rp += __shfl_down_sync(0xffffffffu, rp, 1);
                rp += __shfl_down_sync(0xffffffffu, rp, 2);
                if (tg == 0)
                    atomicAdd(&rss[(size_t)bz*1024 + bm + wm + mi*16 + g + half*8], rp);
            }
        }
        #pragma unroll
        for (int ni = 0; ni < 4; ni++){
            #pragma unroll
            for (int cb = 0; cb < 2; cb++){
                float cp = 0.f;
                #pragma unroll
                for (int mi = 0; mi < 4; mi++){
                    float a0 = acc[mi][ni][cb], a1 = acc[mi][ni][2+cb];
                    cp += a0*a0 + a1*a1;
                }
                cp += __shfl_down_sync(0xffffffffu, cp, 4);
                cp += __shfl_down_sync(0xffffffffu, cp, 8);
                cp += __shfl_down_sync(0xffffffffu, cp, 16);
                if (g == 0)
                    atomicAdd(&css[(size_t)bz*1024 + bn + wn + ni*8 + 2*tg + cb], cp);
            }
        }
        __syncthreads();
        constexpr int TS = 136;
        __nv_bfloat16* tile = reinterpret_cast<__nv_bfloat16*>(smemraw);
        #pragma unroll
        for (int mi = 0; mi < 4; mi++)
            #pragma unroll
            for (int ni = 0; ni < 4; ni++){
                int ln = wn + ni*8 + 2*tg;
                #pragma unroll
                for (int r = 0; r < 4; r++){
                    int lm = wm + mi*16 + g + (r >= 2 ? 8 : 0);
                    tile[lm*TS + ln + (r & 1)] = __float2bfloat16_rn(acc[mi][ni][r]);
                }
            }
        __syncthreads();
        {
            int rw = tid >> 1, half = tid & 1;
            const uint4* srcv = reinterpret_cast<const uint4*>(tile + rw*TS + half*64);
            uint4* dstv = reinterpret_cast<uint4*>(Cb + (size_t)(bm+rw)*ldc + bn + half*64);
            #pragma unroll
            for (int i = 0; i < 8; i++) dstv[i] = srcv[i];
        }
        {
            int coln = tid >> 1, halfm = tid & 1;
            #pragma unroll
            for (int c8 = 0; c8 < 8; c8++){
                __nv_bfloat16 tmp[8];
                #pragma unroll
                for (int j = 0; j < 8; j++)
                    tmp[j] = tile[(halfm*64 + c8*8 + j)*TS + coln];
                *reinterpret_cast<uint4*>(CbT + (size_t)(bn+coln)*ldt + bm + halfm*64 + c8*8)
                    = *reinterpret_cast<const uint4*>(tmp);
            }
        }
    }
}

// ----------------------------- row-wise kernels ------------------------------------
__global__ void k_lltime(const float* __restrict__ acc, __nv_bfloat16* __restrict__ Llh){
    int i = blockIdx.x*1024 + threadIdx.x;
    Llh[(size_t)i*DPAD] = __float2bfloat16_rn(sqrtf(acc[i] + 1.f));
}
__global__ void k_nfin(const float* __restrict__ rss, const float* __restrict__ css,
                       __nv_bfloat16* __restrict__ Lbh, __nv_bfloat16* __restrict__ LbTh,
                       float* __restrict__ xnr, float* __restrict__ xnc){
    int b = blockIdx.x, n = threadIdx.x;                  // 1024
    float S = rss[b*1024 + n];
    float tv = sqrtf(S + 1.f);
    Lbh[((size_t)b*1024 + n)*1024] = __float2bfloat16_rn(tv);
    LbTh[(size_t)b*1024*1024 + n]  = __float2bfloat16_rn(tv);
    xnr[b*1024 + n] = sqrtf(fmaxf(2.f*S + 1.f, 1e-15f));
    float ts = blockReduceSum(S + 1.f);
    float c = css[b*1024 + n];
    xnc[b*1024 + n] = (n == 0) ? sqrtf(ts) : sqrtf(fmaxf(c, 1e-15f));
}
// warp-per-row fused Hs pipeline
__global__ void k_hs(const float* __restrict__ Hsa, const float* __restrict__ MxRaw,
                     const float* __restrict__ xnr,
                     const float* __restrict__ whs, float* __restrict__ lg){
    size_t row = (size_t)blockIdx.x*8 + (threadIdx.x >> 5);
    int lane = threadIdx.x & 31;
    const float* my = MxRaw + row*KKW;
    const float* hx = Hsa + row*KKW;
    float yr[4], x[4];
    float mm = 0.f;
    #pragma unroll
    for (int i = 0; i < 4; i++){
        yr[i] = my[lane + i*32];
        x[i]  = hx[lane + i*32];
        mm += yr[i]*yr[i];
    }
    mm = wsum(mm);
    float mxn = sqrtf(fmaxf(mm, 1e-15f));
    float xnb = xnr[row];
    float fac = tanhf(mxn / xnb * atanhc(xnb)) / mxn;

    float xy = 0.f, x2 = 0.f, y2 = 0.f;
    float y[4];
    #pragma unroll
    for (int i = 0; i < 4; i++){
        y[i] = yr[i] * fac;
        xy += x[i]*y[i]; x2 += x[i]*x[i]; y2 += y[i]*y[i];
    }
    xy = wsum(xy); x2 = wsum(x2); y2 = wsum(y2);
    float den = fmaxf(1.f + 2.f*xy + x2*y2, 1e-15f);
    float c1 = (1.f + 2.f*xy + y2) / den, c2 = (1.f - x2) / den;
    float h[4], hh = 0.f;
    #pragma unroll
    for (int i = 0; i < 4; i++){ h[i] = c1*x[i] + c2*y[i]; hh += h[i]*h[i]; }
    hh = wsum(hh);
    float hn = sqrtf(fmaxf(hh, 1e-15f));
    float fa = atanhc(hn) / hn;
    float gv[4], gg = 0.f;
    #pragma unroll
    for (int i = 0; i < 4; i++){ gv[i] = gelu_exact(fa*h[i]); gg += gv[i]*gv[i]; }
    gg = wsum(gg);
    float gn = sqrtf(fmaxf(gg, 1e-15f));
    float fb = tanhf(gn) / gn;
    float mx = 0.f, xn2 = 0.f;
    #pragma unroll
    for (int i = 0; i < 4; i++){
        float hs = fb * gv[i];
        mx += hs * __ldg(&whs[lane + i*32]);
        xn2 += hs*hs;
    }
    mx = wsum(mx); xn2 = wsum(xn2);
    if (lane == 0){
        float xn = sqrtf(fmaxf(xn2, 1e-15f));
        float mxn2 = sqrtf(fmaxf(mx*mx, 1e-15f));
        lg[row] = tanhf(mxn2 / xn * atanhc(xn)) * mx / mxn2;
    }
}
// dual transpose: z<BB: Hca -> HcaT fp32 + HcaTh bf16 ; z>=BB: Hsa -> HsahT bf16
__global__ void k_tbk2(const float* __restrict__ Hca, const float* __restrict__ Hsa,
                       float* __restrict__ HcaT, __nv_bfloat16* __restrict__ HcaTh,
                       __nv_bfloat16* __restrict__ HsahT){
    __shared__ float tile[32][33];
    int z = blockIdx.z;
    bool isHc = z < BB;
    int b = isHc ? z : z - BB;
    int j0 = blockIdx.x*32, m0 = blockIdx.y*32;
    const float* src = (isHc ? Hca : Hsa) + (size_t)b*NCQ*KKW;
    for (int i = threadIdx.y; i < 32; i += 8)
        tile[i][threadIdx.x] = src[(size_t)(m0+i)*KKW + j0 + threadIdx.x];
    __syncthreads();
    size_t base = (size_t)b*KKW*NCQ;
    for (int i = threadIdx.y; i < 32; i += 8){
        float v = tile[threadIdx.x][i];
        size_t idx = base + (size_t)(j0+i)*NCQ + m0 + threadIdx.x;
        if (isHc){ HcaT[idx] = v; HcaTh[idx] = __float2bfloat16_rn(v); }
        else     { HsahT[idx] = __float2bfloat16_rn(v); }
    }
}
// Hc pipeline: TWO warps per (b,j) row; 16 elems/lane; smem stage-combines
__global__ void k_hc(const float* __restrict__ HcaT, const float* __restrict__ MxcT,
                     const float* __restrict__ sc, const float* __restrict__ whc,
                     float* __restrict__ amx, float* __restrict__ ass){
    __shared__ float comb[4][2][3];
    int wid = threadIdx.x >> 5;                // 0..7
    int wrow = wid >> 1, half = wid & 1;
    int wg = blockIdx.x*4 + wrow;              // 0..BB*KKW-1
    int b = wg >> 7, j = wg & 127;
    int lane = threadIdx.x & 31;
    float wj = __ldg(&whc[j]);
    const float* xrow = HcaT + ((size_t)(b*KKW + j))*NCQ + half*512;
    const float* yrow = MxcT + ((size_t)(b*KKW + j))*NCQ + half*512;
    const float* srow = sc + (size_t)b*NCQ + half*512;
    float x[16], y[16];
    float sxy = 0.f, sx2 = 0.f, sy2 = 0.f;
    #pragma unroll
    for (int i = 0; i < 16; i++){
        int m = lane + i*32;
        x[i] = xrow[m];
        y[i] = yrow[m] * srow[m];
        sxy += x[i]*y[i]; sx2 += x[i]*x[i]; sy2 += y[i]*y[i];
    }
    sxy = wsum(sxy); sx2 = wsum(sx2); sy2 = wsum(sy2);
    if (lane == 0){ comb[wrow][half][0] = sxy; comb[wrow][half][1] = sx2; comb[wrow][half][2] = sy2; }
    __syncthreads();
    sxy = comb[wrow][0][0] + comb[wrow][1][0];
    sx2 = comb[wrow][0][1] + comb[wrow][1][1];
    sy2 = comb[wrow][0][2] + comb[wrow][1][2];
    float den = fmaxf(1.f + 2.f*sxy + sx2*sy2, 1e-15f);
    float c1 = (1.f + 2.f*sxy + sy2) / den, c2 = (1.f - sx2) / den;
    float hh = 0.f;
    #pragma unroll
    for (int i = 0; i < 16; i++){ y[i] = c1*x[i] + c2*y[i]; hh += y[i]*y[i]; }  // y := h
    hh = wsum(hh);
    __syncthreads();
    if (lane == 0) comb[wrow][half][0] = hh;
    __syncthreads();
    hh = comb[wrow][0][0] + comb[wrow][1][0];
    float hn = sqrtf(fmaxf(hh, 1e-15f));
    float fa = atanhc(hn) / hn;
    float gg = 0.f;
    #pragma unroll
    for (int i = 0; i < 16; i++){ x[i] = gelu_exact(fa*y[i]); gg += x[i]*x[i]; } // x := g
    gg = wsum(gg);
    __syncthreads();
    if (lane == 0) comb[wrow][half][1] = gg;
    __syncthreads();
    gg = comb[wrow][0][1] + comb[wrow][1][1];
    float gn = sqrtf(fmaxf(gg, 1e-15f));
    float fb = tanhf(gn) / gn;
    #pragma unroll
    for (int i = 0; i < 16; i++){
        int m = half*512 + lane + i*32;
        float hc = fb * x[i];
        atomicAdd(&amx[b*NCQ + m], hc * wj);
        atomicAdd(&ass[b*NCQ + m], hc * hc);
    }
}
// merged dual softmax: z<BB: As from lgs; z>=BB: Ac with fused logit from amx/ass
__global__ void k_softmax2(const float* __restrict__ lg, const float* __restrict__ amx,
                           const float* __restrict__ ass, float* __restrict__ out,
                           int asoff, int acoff){
    int z = blockIdx.x, t = threadIdx.x;                  // 256
    bool isS = z < BB;
    int b = isS ? z : z - BB;
    float l[4];
    float lm = -3.4e38f;
    #pragma unroll
    for (int i = 0; i < 4; i++){
        int m = t + i*256;
        if (isS){
            l[i] = lg[b*1024 + m];
        } else {
            float mx = amx[b*NCQ + m];
            float ssv = ass[b*NCQ + m];
            float xn = sqrtf(fmaxf(ssv, 1e-15f));
            float mxn = sqrtf(fmaxf(mx*mx, 1e-15f));
            l[i] = tanhf(mxn / xn * atanhc(xn)) * mx / mxn;
        }
        lm = fmaxf(lm, l[i]);
    }
    float M = blockReduceMax(lm);
    float es = 0.f, e[4];
    #pragma unroll
    for (int i = 0; i < 4; i++){ e[i] = expf(l[i] - M); es += e[i]; }
    float S = blockReduceSum(es);
    float* o = out + (isS ? asoff : acoff) + (size_t)b*1024;
    #pragma unroll
    for (int i = 0; i < 4; i++) o[t + i*256] = e[i] / S;
}
// dual-branch centroid partials
__global__ void k_centroid_part(const float* __restrict__ Ls, const float* __restrict__ Lc,
                                const float* __restrict__ outw, int asoff, int acoff,
                                float* __restrict__ part){
    __shared__ float wsh[128];
    int ch = blockIdx.x, z = blockIdx.y;
    bool isS = z < BB;
    int b = isS ? z : z - BB;
    const float* Lx = isS ? Ls : Lc;
    const float* w = outw + (isS ? asoff : acoff) + (size_t)b*NSQ;
    int t = threadIdx.x;                                  // 288, t<257 active
    for (int i = t; i < 128; i += blockDim.x) wsh[i] = w[ch*128 + i];
    __syncthreads();
    if (t < DP1){
        const float* base = Lx + ((size_t)b*NSQ + (size_t)ch*128)*DPAD + t;
        float acc = 0.f;
        for (int n = 0; n < 128; n++) acc += wsh[n] * base[(size_t)n*DPAD];
        part[(z*8 + ch)*DP1 + t] = acc;
    }
}
__global__ void k_centroid_fin(const float* __restrict__ part, float* __restrict__ cs,
                               float* __restrict__ cc){
    __shared__ float t0sh;
    int z = blockIdx.x, t = threadIdx.x;                  // 288
    float acc = 0.f;
    if (t < DP1){
        #pragma unroll
        for (int c = 0; c < 8; c++) acc += part[(z*8 + c)*DP1 + t];
    }
    float sp = (t >= 1 && t < DP1) ? acc*acc : 0.f;
    float ssp = blockReduceSum(sp);
    if (t == 0) t0sh = acc;
    __syncthreads();
    float inner = -t0sh*t0sh + ssp;
    float den = sqrtf(fmaxf(fabsf(inner), 1e-8f));
    float* co = (z < BB) ? cs : cc;
    int b = (z < BB) ? z : z - BB;
    if (t < DP1) co[(size_t)b*DP1 + t] = acc / den;
}
__global__ void k_concat(const float* __restrict__ cs, const float* __restrict__ cc,
                         float* __restrict__ out){
    int b = blockIdx.x, t = threadIdx.x;                  // 256
    float t0s = cs[(size_t)b*DP1];
    float t0c = cc[(size_t)b*DP1];
    float sps = cs[(size_t)b*DP1 + 1 + t];
    float spc = cc[(size_t)b*DP1 + 1 + t];
    float ns  = sqrtf(fmaxf(blockReduceSum(sps*sps), 1e-15f));
    float ncv = sqrtf(fmaxf(blockReduceSum(spc*spc), 1e-15f));
    float zs = acoshf(fmaxf(t0s, 1.f + 1e-7f)) * sps / ns;
    float zc = acoshf(fmaxf(t0c, 1.f + 1e-7f)) * spc / ncv;
    float vn = sqrtf(fmaxf(blockReduceSum(zs*zs + zc*zc), 1e-15f));
    float f = sinhf(vn) / vn;
    float* o = out + (size_t)b*513;
    if (t == 0) o[0] = coshf(vn);
    o[1 + t]       = f * zs;
    o[1 + DD + t]  = f * zc;
}

// ----------------------------- launch ----------------------------------------------
extern "C" void kernel_launch(void* const* d_in, const int* in_sizes, int n_in,
                              void* d_out, int out_size)
{
    const float* sent = (const float*)d_in[0];
    const float* comm = (const float*)d_in[1];
    const float* WlW  = (const float*)d_in[2];
    const float* Wlb  = (const float*)d_in[3];
    const float* WcW  = (const float*)d_in[4];
    const float* Wcb  = (const float*)d_in[5];
    const float* WsW  = (const float*)d_in[6];
    const float* Wsb  = (const float*)d_in[7];
    const float* whs  = (const float*)d_in[8];
    const float* whc  = (const float*)d_in[9];
    float* out = (float*)d_out;
    (void)in_sizes; (void)n_in; (void)out_size;

    float2 *c1, *c1T;
    float *sT, *rl, *Ls, *Lc, *rss, *css, *amx, *ass, *lacc, *xnr, *xnc,
          *msc, *Hsa, *Hca, *HcaT, *Mxs, *MxcT, *lgs, *cs, *cc, *part;
    __nv_bfloat16 *Lsh, *Lch, *Llh, *Lbh, *LbTh, *HcaTh, *HsahT, *Wth, *Wtl;
    cudaGetSymbolAddress((void**)&c1,  g_c1);
    cudaGetSymbolAddress((void**)&c1T, g_c1T);
    cudaGetSymbolAddress((void**)&sT,  g_sT);
    cudaGetSymbolAddress((void**)&rl,  g_real);
    cudaGetSymbolAddress((void**)&Ls,  g_Ls);
    cudaGetSymbolAddress((void**)&Lc,  g_Lc);
    cudaGetSymbolAddress((void**)&Wth, g_Wth);
    cudaGetSymbolAddress((void**)&Wtl, g_Wtl);
    cudaGetSymbolAddress((void**)&Lsh, g_Lsh);
    cudaGetSymbolAddress((void**)&Lch, g_Lch);
    cudaGetSymbolAddress((void**)&Llh, g_Llh);
    cudaGetSymbolAddress((void**)&Lbh, g_Lbh);
    cudaGetSymbolAddress((void**)&LbTh,g_LbTh);
    cudaGetSymbolAddress((void**)&HcaTh,g_HcaTh);
    cudaGetSymbolAddress((void**)&HsahT,g_HsahT);
    cudaGetSymbolAddress((void**)&rss, g_rss);
    cudaGetSymbolAddress((void**)&css, g_css);
    cudaGetSymbolAddress((void**)&amx, g_amx);
    cudaGetSymbolAddress((void**)&ass, g_ass);
    cudaGetSymbolAddress((void**)&lacc,g_lacc);
    cudaGetSymbolAddress((void**)&xnr, g_xnr);
    cudaGetSymbolAddress((void**)&xnc, g_xnc);
    cudaGetSymbolAddress((void**)&msc, g_msc);
    cudaGetSymbolAddress((void**)&Hsa, g_Hsa);
    cudaGetSymbolAddress((void**)&Hca, g_Hca);
    cudaGetSymbolAddress((void**)&HcaT,g_HcaT);
    cudaGetSymbolAddress((void**)&Mxs, g_Mxs);
    cudaGetSymbolAddress((void**)&MxcT,g_MxcT);
    cudaGetSymbolAddress((void**)&lgs, g_lgs);
    cudaGetSymbolAddress((void**)&cs,  g_cs);
    cudaGetSymbolAddress((void**)&cc,  g_cc);
    cudaGetSymbolAddress((void**)&part,g_part);

    const int AS_OFF = BB*513;             // 16416
    const int AC_OFF = AS_OFF + BB*NSQ;    // 49184

    k_setup<<<32 + DP1 + 2*KP1, 1024>>>(WlW, WsW, WcW, rss, css, amx, ass, lacc);

    // ---- dual-branch FFT2 (stage-0 fused, Hermitian-compact) + euclid_to_lorentz ----
    k_fft256<<<2*BB*NSQ/4, dim3(64,4)>>>(sent, comm, c1);
    k_transpose_ch<<<dim3(5, NSQ/32, 2*BB), dim3(32,8)>>>(c1, c1T);
    k_fft1024<<<2*BB*DH, 256>>>(c1T, sT);
    k_transpose_fh<<<dim3(5, NSQ/32, 2*BB), dim3(32,8)>>>(sT, rl);
    k_e2l<<<2*BB*NSQ, 256>>>(rl, Ls, Lc, Lsh, Lch);

    // ---- linear layers (bf16 split-B weights; fused epilogues) ----
    k_bgemm<5,1><<<dim3(2,256,1),256>>>(Lch, Wth + (size_t)1*DPAD, Wtl + (size_t)1*DPAD,
        Wlb + 1, nullptr, Llh + 1, nullptr,
        BB*NCQ, 256, DP1, DPAD, DPAD, DPAD, 0, 0, 0, 0, 0, lacc, nullptr);
    k_lltime<<<32, 1024>>>(lacc, Llh);

    k_bgemm<4,1><<<dim3(1,256,1),256>>>(Lsh, Wth + (size_t)385*DPAD, Wtl + (size_t)385*DPAD,
        Wsb + 1, Hsa, nullptr, nullptr,
        BB*NSQ, KKW, DP1, DPAD, DPAD, KKW, 0, 0, 0, 0, 0, nullptr, nullptr);
    k_bgemm<4,1><<<dim3(1,256,1),256>>>(Lch, Wth + (size_t)641*DPAD, Wtl + (size_t)641*DPAD,
        Wcb + 1, Hca, nullptr, nullptr,
        BB*NCQ, KKW, DP1, DPAD, DPAD, KKW, 0, 0, 0, 0, 0, nullptr, nullptr);

    // ---- big einsum (bf16) + lorentz_act + fused norms, coalesced dual bf16 out ----
    k_bgemm<2,0><<<dim3(8,8,BB),256>>>(Lsh, Llh, nullptr, nullptr, nullptr, Lbh, LbTh,
        NSQ, NCQ, DP1, DPAD, DPAD, NCQ, NSQ,
        (long)NSQ*DPAD, (long)NCQ*DPAD, 0, (long)NSQ*NCQ, rss, css);
    k_nfin<<<BB, 1024>>>(rss, css, Lbh, LbTh, xnr, xnc);

    // ---- transposes for mobius operands ----
    k_tbk2<<<dim3(4, 32, 2*BB), dim3(32,8)>>>(Hca, Hsa, HcaT, HcaTh, HsahT);

    // ---- mobius_matvec GEMMs (bf16); MxcT GEMM fuses mscale ----
    k_bgemm<0,0><<<dim3(1,8,BB),256>>>(Lbh, HcaTh, nullptr, nullptr, Mxs, nullptr, nullptr,
        NSQ, KKW, NCQ, NCQ, NCQ, KKW, 0,
        (long)NSQ*NCQ, (long)KKW*NCQ, (long)NSQ*KKW, 0, nullptr, nullptr);
    k_bgemm<3,0><<<dim3(8,1,BB),256>>>(HsahT, LbTh, nullptr, nullptr, MxcT, nullptr, nullptr,
        KKW, NCQ, NSQ, NSQ, NSQ, NCQ, 0,
        (long)KKW*NSQ, (long)NCQ*NSQ, (long)KKW*NCQ, 0, xnc, msc);

    // ---- mobius_add + gelu pipelines + attention logits ----
    k_hs<<<BB*NSQ/8, 256>>>(Hsa, Mxs, xnr, whs, lgs);
    k_hc<<<BB*KKW/4, 256>>>(HcaT, MxcT, msc, whc, amx, ass);

    // ---- merged dual softmax straight into output ----
    k_softmax2<<<2*BB, 256>>>(lgs, amx, ass, out, AS_OFF, AC_OFF);

    // ---- centroids (dual-branch) + concat ----
    k_centroid_part<<<dim3(8, 2*BB), 288>>>(Ls, Lc, out, AS_OFF, AC_OFF, part);
    k_centroid_fin<<<2*BB, 288>>>(part, cs, cc);
    k_concat<<<BB, 256>>>(cs, cc, out);
}